// round 4
// baseline (speedup 1.0000x reference)
#include <cuda_runtime.h>
#include <cuda_bf16.h>

#define BB   2
#define SS   256
#define INP  80
#define HH   128
#define GG   512      // 4*H
#define FF   256      // 2*H
#define NCC  40
#define WW   64       // WSEG
#define HID  100

typedef unsigned long long u64;

// ---------------- scratch (device globals; no allocation allowed) ----------------
__device__ float g_wihT [4][FF*GG];        // transposed input weights (layer0 uses first 80 rows)
__device__ u64   g_whhP [4][(HH/2)*GG];    // Whh pair-packed + transposed: [k2][g] -> (Whh[g][2k2],Whh[g][2k2+1])
__device__ u64   g_wsP  [3][128*128];      // w_s1 parts c/d/e pair-packed transposed: [k2][h]
__device__ float g_preF [SS*BB*GG];
__device__ float g_preB [SS*BB*GG];
__device__ float g_h0   [BB*SS*FF];
__device__ float g_rnn  [BB*SS*FF];
__device__ float g_cum  [BB*SS*FF];
__device__ float g_Pd   [BB*SS*HID];
__device__ float g_Pe   [BB*SS*HID];       // includes +b_s1
__device__ float g_sband[BB*SS*WW];        // sband[b][i][w], j = i-64+w

// ---------------- helpers ----------------
__device__ __forceinline__ void fma2(u64 &d, u64 a, u64 b) {
    asm("fma.rn.f32x2 %0, %1, %2, %0;" : "+l"(d) : "l"(a), "l"(b));
}
__device__ __forceinline__ float2 u2f(u64 v) {
    float2 f; asm("mov.b64 {%0,%1}, %2;" : "=f"(f.x), "=f"(f.y) : "l"(v)); return f;
}
__device__ __forceinline__ u64 f2u(float x, float y) {
    u64 v; asm("mov.b64 %0, {%1,%2};" : "=l"(v) : "f"(x), "f"(y)); return v;
}
__device__ __forceinline__ float sigm(float x) { return 1.f/(1.f + expf(-x)); }

// ---------------- prep: transposes / packing ----------------
__global__ void k_transpose(const float* __restrict__ w, float* __restrict__ wT, int cols) {
    int c = blockIdx.x, g = threadIdx.x;
    wT[c*GG + g] = w[g*cols + c];
}
__global__ void k_pack_whh(const float* __restrict__ w, u64* __restrict__ wp) {
    int k2 = blockIdx.x, g = threadIdx.x;
    wp[k2*GG + g] = f2u(w[g*HH + 2*k2], w[g*HH + 2*k2 + 1]);
}
__global__ void k_pack_ws1(const float* __restrict__ w) {
    int k2 = blockIdx.x, p = blockIdx.y, h = threadIdx.x;
    u64 v = 0ull;
    if (h < HID) v = f2u(w[h*768 + p*256 + 2*k2], w[h*768 + p*256 + 2*k2 + 1]);
    g_wsP[p][k2*128 + h] = v;
}

// ---------------- pre = x @ Wih^T + b  (S,B,512) ----------------
__global__ void k_pre(const float* __restrict__ xin, const float* __restrict__ wT,
                      const float* __restrict__ bias, float* __restrict__ pre, int Din) {
    __shared__ float xs[FF];
    int s = blockIdx.x, b = blockIdx.y, g = threadIdx.x;
    for (int i = g; i < Din; i += GG) xs[i] = xin[(b*SS + s)*Din + i];
    __syncthreads();
    float acc = bias[g];
    #pragma unroll 4
    for (int i = 0; i < Din; i++) acc += xs[i] * wT[i*GG + g];
    pre[(s*BB + b)*GG + g] = acc;
}

// ---------------- LSTM scan (one CTA per (b,dir)) ----------------
__global__ void k_scan(const float* __restrict__ preFp, const float* __restrict__ preBp,
                       const u64* __restrict__ wpF, const u64* __restrict__ wpB,
                       float* __restrict__ hout) {
    int b = blockIdx.x, dir = blockIdx.y, t = threadIdx.x;
    const float* pre = dir ? preBp : preFp;
    const u64*   wp  = (dir ? wpB : wpF) + t;
    __shared__ __align__(16) float hs[HH];
    __shared__ float cs[HH];
    __shared__ float gs[GG];
    if (t < HH) { hs[t] = 0.f; cs[t] = 0.f; }
    __syncthreads();
    const u64* h2 = (const u64*)hs;
    for (int step = 0; step < SS; ++step) {
        int s = dir ? (SS - 1 - step) : step;
        u64 a0 = 0ull, a1 = 0ull;
        #pragma unroll 8
        for (int k2 = 0; k2 < HH/2; k2 += 2) {
            fma2(a0, wp[(k2    )*GG], h2[k2    ]);
            fma2(a1, wp[(k2 + 1)*GG], h2[k2 + 1]);
        }
        float2 f0 = u2f(a0), f1 = u2f(a1);
        gs[t] = (f0.x + f0.y) + (f1.x + f1.y) + pre[(s*BB + b)*GG + t];
        __syncthreads();
        if (t < HH) {
            float ig = sigm(gs[t]);
            float fg = sigm(gs[t + HH]);
            float gg = tanhf(gs[t + 2*HH]);
            float og = sigm(gs[t + 3*HH]);
            float c  = fg*cs[t] + ig*gg;
            cs[t] = c;
            float h = og * tanhf(c);
            hs[t] = h;
            hout[(b*SS + s)*FF + dir*HH + t] = h;
        }
        __syncthreads();
    }
}

// ---------------- cls / bin MLPs ----------------
__global__ void k_clsbin(const float* __restrict__ rnn,
    const float* ac0, const float* __restrict__ wc1, const float* __restrict__ bc1,
    const float* ac1, const float* __restrict__ wc2, const float* __restrict__ bc2,
    const float* ab0, const float* __restrict__ wb1, const float* __restrict__ bb1,
    const float* ab1, const float* __restrict__ wb2, const float* __restrict__ bb2,
    float* __restrict__ out) {
    int s = blockIdx.x, b = blockIdx.y, t = threadIdx.x; // blockDim = 192
    __shared__ float xc[FF], xb[FF], hc[80], hb[80];
    float a0c = *ac0, a0b = *ab0;
    for (int k = t; k < FF; k += 192) {
        float v = rnn[(b*SS + s)*FF + k];
        xc[k] = v >= 0.f ? v : a0c*v;
        xb[k] = v >= 0.f ? v : a0b*v;
    }
    __syncthreads();
    if (t < 80) {
        float acc = bc1[t];
        const float* w = wc1 + t*FF;
        #pragma unroll 4
        for (int k = 0; k < FF; k++) acc += xc[k]*w[k];
        float a1 = *ac1;
        hc[t] = acc >= 0.f ? acc : a1*acc;
    } else if (t < 160) {
        int g = t - 80;
        float acc = bb1[g];
        const float* w = wb1 + g*FF;
        #pragma unroll 4
        for (int k = 0; k < FF; k++) acc += xb[k]*w[k];
        float a1 = *ab1;
        hb[g] = acc >= 0.f ? acc : a1*acc;
    }
    __syncthreads();
    if (t < NCC) {
        float acc = bc2[t];
        const float* w = wc2 + t*80;
        #pragma unroll 4
        for (int k = 0; k < 80; k++) acc += hc[k]*w[k];
        out[(b*SS + s)*NCC + t] = acc;
    } else if (t < NCC + 2) {
        int o = t - NCC;
        float acc = bb2[o];
        const float* w = wb2 + o*80;
        #pragma unroll 4
        for (int k = 0; k < 80; k++) acc += hb[k]*w[k];
        out[20480 + (b*SS + s)*2 + o] = acc;
    }
}

// ---------------- inclusive cumsum over s ----------------
__global__ void k_cum(const float* __restrict__ rnn) {
    int b = blockIdx.x, k = threadIdx.x; // blockDim = 256
    float run = 0.f;
    for (int t = 0; t < SS; t++) {
        run += rnn[(b*SS + t)*FF + k];
        g_cum[(b*SS + t)*FF + k] = run;
    }
}

// ---------------- Pd / Pe (rank-1 score-MLP terms) ----------------
__global__ void k_pdpe(const float* __restrict__ rnn, const float* as0, const float* __restrict__ bs1) {
    int s = blockIdx.x, b = blockIdx.y, t = threadIdx.x; // blockDim = 128
    __shared__ __align__(16) float xr[FF];
    float a0 = *as0;
    {
        float v0 = rnn[(b*SS + s)*FF + 2*t];
        float v1 = rnn[(b*SS + s)*FF + 2*t + 1];
        xr[2*t]     = v0 >= 0.f ? v0 : a0*v0;
        xr[2*t + 1] = v1 >= 0.f ? v1 : a0*v1;
    }
    __syncthreads();
    const u64* xp = (const u64*)xr;
    if (t < HID) {
        u64 d0 = 0ull, d1 = 0ull, e0 = 0ull, e1 = 0ull;
        #pragma unroll 8
        for (int k2 = 0; k2 < 128; k2 += 2) {
            fma2(d0, g_wsP[1][(k2    )*128 + t], xp[k2    ]);
            fma2(d1, g_wsP[1][(k2 + 1)*128 + t], xp[k2 + 1]);
            fma2(e0, g_wsP[2][(k2    )*128 + t], xp[k2    ]);
            fma2(e1, g_wsP[2][(k2 + 1)*128 + t], xp[k2 + 1]);
        }
        float2 fd0 = u2f(d0), fd1 = u2f(d1), fe0 = u2f(e0), fe1 = u2f(e1);
        g_Pd[(b*SS + s)*HID + t] = fd0.x + fd0.y + fd1.x + fd1.y;
        g_Pe[(b*SS + s)*HID + t] = fe0.x + fe0.y + fe1.x + fe1.y + bs1[t];
    }
}

// ---------------- banded score MLP ----------------
__global__ void k_scores(const float* as0, const float* as1,
                         const float* __restrict__ ws2, const float* bs2) {
    int i = blockIdx.x, b = blockIdx.y, jh = blockIdx.z, t = threadIdx.x; // blockDim = 128
    if (i == 0) return;
    __shared__ __align__(16) float cdf[FF];
    __shared__ float wsum[4];
    const u64* cd = (const u64*)cdf;
    float a0 = *as0, a1 = *as1, b2 = *bs2;
    const float* cumi = g_cum + (b*SS + i)*FF;
    float ci0 = cumi[2*t], ci1 = cumi[2*t + 1];
    float pei = (t < HID) ? g_Pe[(b*SS + i)*HID + t] : 0.f;
    float w2  = (t < HID) ? ws2[t] : 0.f;
    for (int wl = 0; wl < 32; ++wl) {
        int w = jh*32 + wl;
        int j = i - WW + w;
        if (j < 0) {                             // uniform across block
            if (t == 0) g_sband[(b*SS + i)*WW + w] = -1000000000.0f;
            continue;
        }
        const float* cumj = g_cum + (b*SS + j)*FF;
        float c0 = ci0 - cumj[2*t];
        float c1 = ci1 - cumj[2*t + 1];
        cdf[2*t]     = c0 >= 0.f ? c0 : a0*c0;
        cdf[2*t + 1] = c1 >= 0.f ? c1 : a0*c1;
        __syncthreads();
        float val = 0.f;
        if (t < HID) {
            u64 s0 = 0ull, s1 = 0ull;
            const u64* wrow = g_wsP[0] + t;
            #pragma unroll 8
            for (int k2 = 0; k2 < 128; k2 += 2) {
                fma2(s0, wrow[(k2    )*128], cd[k2    ]);
                fma2(s1, wrow[(k2 + 1)*128], cd[k2 + 1]);
            }
            float2 f0 = u2f(s0), f1 = u2f(s1);
            float hid = f0.x + f0.y + f1.x + f1.y + g_Pd[(b*SS + j)*HID + t] + pei;
            float ph  = hid >= 0.f ? hid : a1*hid;
            val = ph * w2;
        }
        for (int off = 16; off; off >>= 1) val += __shfl_down_sync(0xffffffffu, val, off);
        if ((t & 31) == 0) wsum[t >> 5] = val;
        __syncthreads();
        if (t == 0) g_sband[(b*SS + i)*WW + w] = wsum[0] + wsum[1] + wsum[2] + wsum[3] + b2;
        __syncthreads();
    }
}

// ---------------- DP + backtrack (one warp per batch row) ----------------
__global__ void k_dp(const int* __restrict__ lengths, float* __restrict__ out) {
    __shared__ float best[BB][SS];
    __shared__ int   bp[BB][SS];
    int t = threadIdx.x;          // blockDim = 64
    int b = t >> 5, lane = t & 31;
    for (int idx = t; idx < BB*SS; idx += 64) best[idx >> 8][idx & 255] = 0.f;
    for (int idx = t; idx < BB*SS; idx += 64) out[21504 + idx] = 0.f;   // zero bmask
    if (t < BB) bp[t][0] = 0;
    __syncthreads();
    for (int i = 1; i < SS; i++) {
        int w1 = lane, w2 = lane + 32;
        int j1 = i - WW + w1, j2 = i - WW + w2;
        float c1 = (j1 >= 0) ? best[b][j1] + g_sband[(b*SS + i)*WW + w1] : -1000000000.0f;
        float c2 = (j2 >= 0) ? best[b][j2] + g_sband[(b*SS + i)*WW + w2] : -1000000000.0f;
        float v; int jj;
        if (c2 > c1) { v = c2; jj = j2; } else { v = c1; jj = j1; }   // tie -> smaller j
        for (int off = 16; off; off >>= 1) {
            float ov = __shfl_down_sync(0xffffffffu, v,  off);
            int   oj = __shfl_down_sync(0xffffffffu, jj, off);
            if (ov > v || (ov == v && oj < jj)) { v = ov; jj = oj; }
        }
        if (lane == 0) { best[b][i] = v; bp[b][i] = jj; }
        __syncwarp();
    }
    __syncthreads();
    if (t < BB) {
        int cur = lengths[t] - 1;
        if (cur < 0) cur = 0;
        float acc = 0.f;
        while (true) {
            out[21504 + t*SS + cur] = 1.f;
            if (cur == 0) break;
            int prev = bp[t][cur];
            acc += g_sband[(t*SS + cur)*WW + (prev - (cur - WW))];
            cur = prev;
        }
        out[22016 + t] = acc;
    }
}

// ---------------- launch ----------------
extern "C" void kernel_launch(void* const* d_in, const int* in_sizes, int n_in,
                              void* d_out, int out_size) {
    (void)in_sizes; (void)n_in; (void)out_size;
    const float* x        = (const float*)d_in[0];
    const int*   lengths  = (const int*)  d_in[1];
    const float* wih[4]   = {(const float*)d_in[2], (const float*)d_in[5],
                             (const float*)d_in[8], (const float*)d_in[11]};
    const float* whh[4]   = {(const float*)d_in[3], (const float*)d_in[6],
                             (const float*)d_in[9], (const float*)d_in[12]};
    const float* bl[4]    = {(const float*)d_in[4], (const float*)d_in[7],
                             (const float*)d_in[10], (const float*)d_in[13]};
    const float* a_s0 = (const float*)d_in[14];
    const float* w_s1 = (const float*)d_in[15];
    const float* b_s1 = (const float*)d_in[16];
    const float* a_s1 = (const float*)d_in[17];
    const float* w_s2 = (const float*)d_in[18];
    const float* b_s2 = (const float*)d_in[19];
    const float* a_c0 = (const float*)d_in[20];
    const float* w_c1 = (const float*)d_in[21];
    const float* b_c1 = (const float*)d_in[22];
    const float* a_c1 = (const float*)d_in[23];
    const float* w_c2 = (const float*)d_in[24];
    const float* b_c2 = (const float*)d_in[25];
    const float* a_b0 = (const float*)d_in[26];
    const float* w_b1 = (const float*)d_in[27];
    const float* b_b1 = (const float*)d_in[28];
    const float* a_b1 = (const float*)d_in[29];
    const float* w_b2 = (const float*)d_in[30];
    const float* b_b2 = (const float*)d_in[31];
    float* out = (float*)d_out;

    float *wihT, *preF, *preB, *h0, *rnn;
    u64 *whhP;
    cudaGetSymbolAddress((void**)&wihT, g_wihT);
    cudaGetSymbolAddress((void**)&whhP, g_whhP);
    cudaGetSymbolAddress((void**)&preF, g_preF);
    cudaGetSymbolAddress((void**)&preB, g_preB);
    cudaGetSymbolAddress((void**)&h0,   g_h0);
    cudaGetSymbolAddress((void**)&rnn,  g_rnn);

    const int dins[2] = {INP, FF};
    for (int m = 0; m < 4; m++) {
        int Din = dins[m >> 1];
        k_transpose<<<Din, GG>>>(wih[m], wihT + m*FF*GG, Din);
        k_pack_whh<<<HH/2, GG>>>(whh[m], whhP + m*(HH/2)*GG);
    }
    k_pack_ws1<<<dim3(128, 3), 128>>>(w_s1);

    dim3 gpre(SS, BB);
    // layer 0
    k_pre<<<gpre, GG>>>(x, wihT + 0*FF*GG, bl[0], preF, INP);
    k_pre<<<gpre, GG>>>(x, wihT + 1*FF*GG, bl[1], preB, INP);
    k_scan<<<dim3(BB, 2), GG>>>(preF, preB, whhP + 0*(HH/2)*GG, whhP + 1*(HH/2)*GG, h0);
    // layer 1
    k_pre<<<gpre, GG>>>(h0, wihT + 2*FF*GG, bl[2], preF, FF);
    k_pre<<<gpre, GG>>>(h0, wihT + 3*FF*GG, bl[3], preB, FF);
    k_scan<<<dim3(BB, 2), GG>>>(preF, preB, whhP + 2*(HH/2)*GG, whhP + 3*(HH/2)*GG, rnn);

    k_clsbin<<<gpre, 192>>>(rnn, a_c0, w_c1, b_c1, a_c1, w_c2, b_c2,
                                 a_b0, w_b1, b_b1, a_b1, w_b2, b_b2, out);
    k_cum<<<BB, FF>>>(rnn);
    k_pdpe<<<gpre, 128>>>(rnn, a_s0, b_s1);
    k_scores<<<dim3(SS, BB, 2), 128>>>(a_s0, a_s1, w_s2, b_s2);
    k_dp<<<1, 64>>>(lengths, out);
}

// round 6
// speedup vs baseline: 2.3341x; 2.3341x over previous
#include <cuda_runtime.h>
#include <cuda_bf16.h>

#define BB   2
#define SS   256
#define INP  80
#define HH   128
#define GG   512
#define FF   256
#define NCC  40
#define WW   64
#define HID  100

typedef unsigned long long u64;

__device__ float g_wihT [4][FF*GG];
__device__ u64   g_wsP  [3][128*128];
__device__ float g_preF [SS*BB*GG];
__device__ float g_preB [SS*BB*GG];
__device__ float g_h0   [BB*SS*FF];
__device__ float g_rnn  [BB*SS*FF];
__device__ float g_cum  [BB*SS*FF];
__device__ float g_Pd   [BB*SS*HID];
__device__ float g_Pe   [BB*SS*HID];
__device__ float g_sband[BB*SS*WW];

__device__ __forceinline__ void fma2(u64 &d, u64 a, u64 b) {
    asm("fma.rn.f32x2 %0, %1, %2, %0;" : "+l"(d) : "l"(a), "l"(b));
}
__device__ __forceinline__ float2 u2f(u64 v) {
    float2 f; asm("mov.b64 {%0,%1}, %2;" : "=f"(f.x), "=f"(f.y) : "l"(v)); return f;
}
__device__ __forceinline__ u64 f2u(float x, float y) {
    u64 v; asm("mov.b64 %0, {%1,%2};" : "=l"(v) : "f"(x), "f"(y)); return v;
}
__device__ __forceinline__ unsigned smem_u32(const void* p) {
    unsigned a;
    asm("{ .reg .u64 t; cvta.to.shared.u64 t, %1; cvt.u32.u64 %0, t; }" : "=r"(a) : "l"(p));
    return a;
}
__device__ __forceinline__ float fsig(float x) { return __fdividef(1.f, 1.f + __expf(-x)); }
__device__ __forceinline__ float ftanh(float x) {
    float ax = fabsf(x);
    float e  = __expf(-2.f * ax);
    float r  = __fdividef(1.f - e, 1.f + e);
    return x < 0.f ? -r : r;
}
__device__ __forceinline__ void mbar_wait(unsigned mb, unsigned par) {
    unsigned done = 0;
    do {
        asm volatile("{\n\t.reg .pred p;\n\t"
            "mbarrier.try_wait.parity.acquire.cluster.shared::cta.b64 p, [%1], %2;\n\t"
            "selp.b32 %0,1,0,p;\n\t}" : "=r"(done) : "r"(mb), "r"(par) : "memory");
    } while (!done);
}

// ---------------- prep ----------------
__global__ void k_transpose(const float* __restrict__ w, float* __restrict__ wT, int cols) {
    int c = blockIdx.x, g = threadIdx.x;
    wT[c*GG + g] = w[g*cols + c];
}
__global__ void k_pack_ws1(const float* __restrict__ w) {
    int k2 = blockIdx.x, p = blockIdx.y, h = threadIdx.x;
    u64 v = 0ull;
    if (h < HID) v = f2u(w[h*768 + p*256 + 2*k2], w[h*768 + p*256 + 2*k2 + 1]);
    g_wsP[p][k2*128 + h] = v;
}

// ---------------- pre = x @ Wih^T + b, 8 timesteps per block ----------------
__global__ void k_pre8(const float* __restrict__ xin, const float* __restrict__ wT,
                       const float* __restrict__ bias, float* __restrict__ pre, int Din) {
    __shared__ float xs[8][FF];
    int sb = blockIdx.x * 8, b = blockIdx.y, g = threadIdx.x;
    for (int idx = g; idx < 8*Din; idx += GG) {
        int j = idx / Din, k = idx - j*Din;
        xs[j][k] = xin[(b*SS + sb + j)*Din + k];
    }
    __syncthreads();
    float bi = bias[g];
    float acc[8];
    #pragma unroll
    for (int j = 0; j < 8; j++) acc[j] = bi;
    for (int i = 0; i < Din; i++) {
        float wv = wT[i*GG + g];
        #pragma unroll
        for (int j = 0; j < 8; j++) acc[j] += xs[j][i] * wv;
    }
    #pragma unroll
    for (int j = 0; j < 8; j++) pre[((sb + j)*BB + b)*GG + g] = acc[j];
}

// ---------------- LSTM scan: 2-CTA cluster per dir, Whh in registers ----------------
__global__ void __launch_bounds__(256, 1) __cluster_dims__(2, 1, 1)
k_scan2(const float* __restrict__ preFp, const float* __restrict__ preBp,
        const float* __restrict__ whFp, const float* __restrict__ whBp,
        float* __restrict__ hout) {
    int dir  = blockIdx.x >> 1;
    int rank = blockIdx.x & 1;
    int peer = rank ^ 1;
    const float* pre = dir ? preBp : preFp;
    const u64*   W   = (const u64*)(dir ? whBp : whFp);   // [512 rows][64 u64]
    int t = threadIdx.x;
    int g = t >> 6, hl = t & 63;
    int hbase = rank * 64;
    int row = g * HH + hbase + hl;

    __shared__ __align__(16) float hsf[2][2][HH];  // [buf][batch][k]
    __shared__ float gs[2][4][64];                 // [batch][gate][local h]
    __shared__ __align__(8) u64 mbar;

    // weight row in regs: [0..31] local-half pairs, [32..63] remote-half pairs
    u64 w[64];
    #pragma unroll
    for (int q = 0; q < 32; q++) w[q]      = W[row*64 + rank*32 + q];
    #pragma unroll
    for (int q = 0; q < 32; q++) w[32 + q] = W[row*64 + peer*32 + q];

    for (int i = t; i < 2*2*HH; i += 256) ((float*)hsf)[i] = 0.f;
    unsigned mb = smem_u32(&mbar);
    if (t == 0) asm volatile("mbarrier.init.shared.b64 [%0], 128;" :: "r"(mb) : "memory");
    __syncthreads();
    asm volatile("barrier.cluster.arrive.aligned;" ::: "memory");
    asm volatile("barrier.cluster.wait.aligned;"   ::: "memory");

    unsigned rmb;
    asm("mapa.shared::cluster.u32 %0, %1, %2;" : "=r"(rmb) : "r"(mb), "r"(peer));

    int eb = t >> 6, eh = t & 63;                  // epilogue mapping (t < 128)
    unsigned la0 = smem_u32(&hsf[0][eb & 1][hbase + eh]);
    unsigned la1 = smem_u32(&hsf[1][eb & 1][hbase + eh]);
    unsigned ra0, ra1;
    asm("mapa.shared::cluster.u32 %0, %1, %2;" : "=r"(ra0) : "r"(la0), "r"(peer));
    asm("mapa.shared::cluster.u32 %0, %1, %2;" : "=r"(ra1) : "r"(la1), "r"(peer));
    float cst = 0.f;

    for (int s_ = 0; s_ < SS; s_++) {
        int s = dir ? (SS - 1 - s_) : s_;
        float p0 = __ldg(&pre[(s*BB + 0)*GG + row]);
        float p1 = __ldg(&pre[(s*BB + 1)*GG + row]);
        int rb = (s_ + 1) & 1;                     // buffer holding h(s_-1)
        int wb = s_ & 1;                           // buffer for h(s_)
        const u64* h0b = (const u64*)hsf[rb][0];
        const u64* h1b = (const u64*)hsf[rb][1];
        const u64* hl0 = h0b + rank*32;
        const u64* hl1 = h1b + rank*32;
        const u64* hr0 = h0b + peer*32;
        const u64* hr1 = h1b + peer*32;
        u64 a0 = 0ull, a1 = 0ull, b0 = 0ull, b1 = 0ull;
        #pragma unroll
        for (int q = 0; q < 32; q += 2) {          // local half (synced by __syncthreads)
            ulonglong2 x0 = *(const ulonglong2*)(hl0 + q);
            ulonglong2 x1 = *(const ulonglong2*)(hl1 + q);
            fma2(a0, w[q], x0.x);  fma2(a1, w[q + 1], x0.y);
            fma2(b0, w[q], x1.x);  fma2(b1, w[q + 1], x1.y);
        }
        if (s_ > 0) mbar_wait(mb, (s_ - 1) & 1);   // peer half of h(s_-1) arrived
        #pragma unroll
        for (int q = 0; q < 32; q += 2) {          // remote half
            ulonglong2 x0 = *(const ulonglong2*)(hr0 + q);
            ulonglong2 x1 = *(const ulonglong2*)(hr1 + q);
            fma2(a0, w[32 + q], x0.x);  fma2(a1, w[33 + q], x0.y);
            fma2(b0, w[32 + q], x1.x);  fma2(b1, w[33 + q], x1.y);
        }
        float2 fa = u2f(a0), fb = u2f(a1), fc = u2f(b0), fd = u2f(b1);
        gs[0][g][hl] = (fa.x + fa.y) + (fb.x + fb.y) + p0;
        gs[1][g][hl] = (fc.x + fc.y) + (fd.x + fd.y) + p1;
        __syncthreads();                           // all reads of buffer rb done
        if (t < 128) {
            float ig = fsig(gs[eb][0][eh]);
            float fg = fsig(gs[eb][1][eh]);
            float gg = ftanh(gs[eb][2][eh]);
            float og = fsig(gs[eb][3][eh]);
            cst = fg*cst + ig*gg;
            float hv = og * ftanh(cst);
            hsf[wb][eb][hbase + eh] = hv;
            unsigned radr = wb ? ra1 : ra0;
            asm volatile("st.shared::cluster.f32 [%0], %1;" :: "r"(radr), "f"(hv) : "memory");
            asm volatile("mbarrier.arrive.release.cluster.shared::cluster.b64 _, [%0];"
                         :: "r"(rmb) : "memory");
            hout[(eb*SS + s)*FF + dir*HH + hbase + eh] = hv;
        }
        __syncthreads();
    }
    asm volatile("barrier.cluster.arrive.aligned;" ::: "memory");
    asm volatile("barrier.cluster.wait.aligned;"   ::: "memory");
}

// ---------------- cls / bin MLPs ----------------
__global__ void k_clsbin(const float* __restrict__ rnn,
    const float* ac0, const float* __restrict__ wc1, const float* __restrict__ bc1,
    const float* ac1, const float* __restrict__ wc2, const float* __restrict__ bc2,
    const float* ab0, const float* __restrict__ wb1, const float* __restrict__ bb1,
    const float* ab1, const float* __restrict__ wb2, const float* __restrict__ bb2,
    float* __restrict__ out) {
    int s = blockIdx.x, b = blockIdx.y, t = threadIdx.x; // blockDim = 192
    __shared__ float xc[FF], xb[FF], hc[80], hb[80];
    float a0c = *ac0, a0b = *ab0;
    for (int k = t; k < FF; k += 192) {
        float v = rnn[(b*SS + s)*FF + k];
        xc[k] = v >= 0.f ? v : a0c*v;
        xb[k] = v >= 0.f ? v : a0b*v;
    }
    __syncthreads();
    if (t < 80) {
        float acc = bc1[t];
        const float* w = wc1 + t*FF;
        #pragma unroll 4
        for (int k = 0; k < FF; k++) acc += xc[k]*w[k];
        float a1 = *ac1;
        hc[t] = acc >= 0.f ? acc : a1*acc;
    } else if (t < 160) {
        int g = t - 80;
        float acc = bb1[g];
        const float* w = wb1 + g*FF;
        #pragma unroll 4
        for (int k = 0; k < FF; k++) acc += xb[k]*w[k];
        float a1 = *ab1;
        hb[g] = acc >= 0.f ? acc : a1*acc;
    }
    __syncthreads();
    if (t < NCC) {
        float acc = bc2[t];
        const float* w = wc2 + t*80;
        #pragma unroll 4
        for (int k = 0; k < 80; k++) acc += hc[k]*w[k];
        out[(b*SS + s)*NCC + t] = acc;
    } else if (t < NCC + 2) {
        int o = t - NCC;
        float acc = bb2[o];
        const float* w = wb2 + o*80;
        #pragma unroll 4
        for (int k = 0; k < 80; k++) acc += hb[k]*w[k];
        out[20480 + (b*SS + s)*2 + o] = acc;
    }
}

// ---------------- cumsum ----------------
__global__ void k_cum(const float* __restrict__ rnn) {
    int b = blockIdx.x, k = threadIdx.x;
    float run = 0.f;
    for (int t = 0; t < SS; t++) {
        run += rnn[(b*SS + t)*FF + k];
        g_cum[(b*SS + t)*FF + k] = run;
    }
}

// ---------------- Pd / Pe ----------------
__global__ void k_pdpe(const float* __restrict__ rnn, const float* as0, const float* __restrict__ bs1) {
    int s = blockIdx.x, b = blockIdx.y, t = threadIdx.x; // blockDim = 128
    __shared__ __align__(16) float xr[FF];
    float a0 = *as0;
    {
        float v0 = rnn[(b*SS + s)*FF + 2*t];
        float v1 = rnn[(b*SS + s)*FF + 2*t + 1];
        xr[2*t]     = v0 >= 0.f ? v0 : a0*v0;
        xr[2*t + 1] = v1 >= 0.f ? v1 : a0*v1;
    }
    __syncthreads();
    const u64* xp = (const u64*)xr;
    if (t < HID) {
        u64 d0 = 0ull, d1 = 0ull, e0 = 0ull, e1 = 0ull;
        #pragma unroll 8
        for (int k2 = 0; k2 < 128; k2 += 2) {
            fma2(d0, g_wsP[1][(k2    )*128 + t], xp[k2    ]);
            fma2(d1, g_wsP[1][(k2 + 1)*128 + t], xp[k2 + 1]);
            fma2(e0, g_wsP[2][(k2    )*128 + t], xp[k2    ]);
            fma2(e1, g_wsP[2][(k2 + 1)*128 + t], xp[k2 + 1]);
        }
        float2 fd0 = u2f(d0), fd1 = u2f(d1), fe0 = u2f(e0), fe1 = u2f(e1);
        g_Pd[(b*SS + s)*HID + t] = fd0.x + fd0.y + fd1.x + fd1.y;
        g_Pe[(b*SS + s)*HID + t] = fe0.x + fe0.y + fe1.x + fe1.y + bs1[t];
    }
}

// ---------------- banded score MLP ----------------
__global__ void k_scores(const float* as0, const float* as1,
                         const float* __restrict__ ws2, const float* bs2) {
    int i = blockIdx.x, b = blockIdx.y, jh = blockIdx.z, t = threadIdx.x; // blockDim = 128
    if (i == 0) return;
    __shared__ __align__(16) float cdf[FF];
    __shared__ float wsum[4];
    const u64* cd = (const u64*)cdf;
    float a0 = *as0, a1 = *as1, b2 = *bs2;
    const float* cumi = g_cum + (b*SS + i)*FF;
    float ci0 = cumi[2*t], ci1 = cumi[2*t + 1];
    float pei = (t < HID) ? g_Pe[(b*SS + i)*HID + t] : 0.f;
    float w2  = (t < HID) ? ws2[t] : 0.f;
    for (int wl = 0; wl < 32; ++wl) {
        int w = jh*32 + wl;
        int j = i - WW + w;
        if (j < 0) {
            if (t == 0) g_sband[(b*SS + i)*WW + w] = -1000000000.0f;
            continue;
        }
        const float* cumj = g_cum + (b*SS + j)*FF;
        float c0 = ci0 - cumj[2*t];
        float c1 = ci1 - cumj[2*t + 1];
        cdf[2*t]     = c0 >= 0.f ? c0 : a0*c0;
        cdf[2*t + 1] = c1 >= 0.f ? c1 : a0*c1;
        __syncthreads();
        float val = 0.f;
        if (t < HID) {
            u64 s0 = 0ull, s1 = 0ull;
            const u64* wrow = g_wsP[0] + t;
            #pragma unroll 8
            for (int k2 = 0; k2 < 128; k2 += 2) {
                fma2(s0, wrow[(k2    )*128], cd[k2    ]);
                fma2(s1, wrow[(k2 + 1)*128], cd[k2 + 1]);
            }
            float2 f0 = u2f(s0), f1 = u2f(s1);
            float hid = f0.x + f0.y + f1.x + f1.y + g_Pd[(b*SS + j)*HID + t] + pei;
            float ph  = hid >= 0.f ? hid : a1*hid;
            val = ph * w2;
        }
        for (int off = 16; off; off >>= 1) val += __shfl_down_sync(0xffffffffu, val, off);
        if ((t & 31) == 0) wsum[t >> 5] = val;
        __syncthreads();
        if (t == 0) g_sband[(b*SS + i)*WW + w] = wsum[0] + wsum[1] + wsum[2] + wsum[3] + b2;
        __syncthreads();
    }
}

// ---------------- DP + backtrack ----------------
__global__ void k_dp(const int* __restrict__ lengths, float* __restrict__ out) {
    __shared__ float best[BB][SS];
    __shared__ int   bp[BB][SS];
    int t = threadIdx.x;          // blockDim = 64
    int b = t >> 5, lane = t & 31;
    for (int idx = t; idx < BB*SS; idx += 64) best[idx >> 8][idx & 255] = 0.f;
    for (int idx = t; idx < BB*SS; idx += 64) out[21504 + idx] = 0.f;
    if (t < BB) bp[t][0] = 0;
    __syncthreads();
    for (int i = 1; i < SS; i++) {
        int w1 = lane, w2 = lane + 32;
        int j1 = i - WW + w1, j2 = i - WW + w2;
        float c1 = (j1 >= 0) ? best[b][j1] + g_sband[(b*SS + i)*WW + w1] : -1000000000.0f;
        float c2 = (j2 >= 0) ? best[b][j2] + g_sband[(b*SS + i)*WW + w2] : -1000000000.0f;
        float v; int jj;
        if (c2 > c1) { v = c2; jj = j2; } else { v = c1; jj = j1; }
        for (int off = 16; off; off >>= 1) {
            float ov = __shfl_down_sync(0xffffffffu, v,  off);
            int   oj = __shfl_down_sync(0xffffffffu, jj, off);
            if (ov > v || (ov == v && oj < jj)) { v = ov; jj = oj; }
        }
        if (lane == 0) { best[b][i] = v; bp[b][i] = jj; }
        __syncwarp();
    }
    __syncthreads();
    if (t < BB) {
        int cur = lengths[t] - 1;
        if (cur < 0) cur = 0;
        float acc = 0.f;
        while (true) {
            out[21504 + t*SS + cur] = 1.f;
            if (cur == 0) break;
            int prev = bp[t][cur];
            acc += g_sband[(t*SS + cur)*WW + (prev - (cur - WW))];
            cur = prev;
        }
        out[22016 + t] = acc;
    }
}

// ---------------- launch ----------------
extern "C" void kernel_launch(void* const* d_in, const int* in_sizes, int n_in,
                              void* d_out, int out_size) {
    (void)in_sizes; (void)n_in; (void)out_size;
    const float* x        = (const float*)d_in[0];
    const int*   lengths  = (const int*)  d_in[1];
    const float* wih[4]   = {(const float*)d_in[2], (const float*)d_in[5],
                             (const float*)d_in[8], (const float*)d_in[11]};
    const float* whh[4]   = {(const float*)d_in[3], (const float*)d_in[6],
                             (const float*)d_in[9], (const float*)d_in[12]};
    const float* bl[4]    = {(const float*)d_in[4], (const float*)d_in[7],
                             (const float*)d_in[10], (const float*)d_in[13]};
    const float* a_s0 = (const float*)d_in[14];
    const float* w_s1 = (const float*)d_in[15];
    const float* b_s1 = (const float*)d_in[16];
    const float* a_s1 = (const float*)d_in[17];
    const float* w_s2 = (const float*)d_in[18];
    const float* b_s2 = (const float*)d_in[19];
    const float* a_c0 = (const float*)d_in[20];
    const float* w_c1 = (const float*)d_in[21];
    const float* b_c1 = (const float*)d_in[22];
    const float* a_c1 = (const float*)d_in[23];
    const float* w_c2 = (const float*)d_in[24];
    const float* b_c2 = (const float*)d_in[25];
    const float* a_b0 = (const float*)d_in[26];
    const float* w_b1 = (const float*)d_in[27];
    const float* b_b1 = (const float*)d_in[28];
    const float* a_b1 = (const float*)d_in[29];
    const float* w_b2 = (const float*)d_in[30];
    const float* b_b2 = (const float*)d_in[31];
    float* out = (float*)d_out;

    float *wihT, *preF, *preB, *h0, *rnn;
    cudaGetSymbolAddress((void**)&wihT, g_wihT);
    cudaGetSymbolAddress((void**)&preF, g_preF);
    cudaGetSymbolAddress((void**)&preB, g_preB);
    cudaGetSymbolAddress((void**)&h0,   g_h0);
    cudaGetSymbolAddress((void**)&rnn,  g_rnn);

    const int dins[2] = {INP, FF};
    for (int m = 0; m < 4; m++)
        k_transpose<<<dins[m >> 1], GG>>>(wih[m], wihT + m*FF*GG, dins[m >> 1]);
    k_pack_ws1<<<dim3(128, 3), 128>>>(w_s1);

    dim3 gpre8(SS/8, BB);
    // layer 0
    k_pre8<<<gpre8, GG>>>(x, wihT + 0*FF*GG, bl[0], preF, INP);
    k_pre8<<<gpre8, GG>>>(x, wihT + 1*FF*GG, bl[1], preB, INP);
    k_scan2<<<4, 256>>>(preF, preB, whh[0], whh[1], h0);
    // layer 1
    k_pre8<<<gpre8, GG>>>(h0, wihT + 2*FF*GG, bl[2], preF, FF);
    k_pre8<<<gpre8, GG>>>(h0, wihT + 3*FF*GG, bl[3], preB, FF);
    k_scan2<<<4, 256>>>(preF, preB, whh[2], whh[3], rnn);

    k_clsbin<<<dim3(SS, BB), 192>>>(rnn, a_c0, w_c1, b_c1, a_c1, w_c2, b_c2,
                                         a_b0, w_b1, b_b1, a_b1, w_b2, b_b2, out);
    k_cum<<<BB, FF>>>(rnn);
    k_pdpe<<<dim3(SS, BB), 128>>>(rnn, a_s0, b_s1);
    k_scores<<<dim3(SS, BB, 2), 128>>>(a_s0, a_s1, w_s2, b_s2);
    k_dp<<<1, 64>>>(lengths, out);
}

// round 7
// speedup vs baseline: 2.4875x; 1.0657x over previous
#include <cuda_runtime.h>
#include <cuda_bf16.h>

#define BB   2
#define SS   256
#define INP  80
#define HH   128
#define GG   512
#define FF   256
#define NCC  40
#define WW   64
#define HID  100

typedef unsigned long long u64;

__device__ float g_wihT [4][FF*GG];
__device__ u64   g_wsP  [3][128*128];
__device__ float g_preF [SS*BB*GG];
__device__ float g_preB [SS*BB*GG];
__device__ float g_h0   [BB*SS*FF];
__device__ float g_rnn  [BB*SS*FF];
__device__ float g_cum  [BB*SS*FF];
__device__ float g_Pd   [BB*SS*HID];
__device__ float g_Pe   [BB*SS*HID];
__device__ float g_sband[BB*SS*WW];

__device__ __forceinline__ void fma2(u64 &d, u64 a, u64 b) {
    asm("fma.rn.f32x2 %0, %1, %2, %0;" : "+l"(d) : "l"(a), "l"(b));
}
__device__ __forceinline__ float2 u2f(u64 v) {
    float2 f; asm("mov.b64 {%0,%1}, %2;" : "=f"(f.x), "=f"(f.y) : "l"(v)); return f;
}
__device__ __forceinline__ u64 f2u(float x, float y) {
    u64 v; asm("mov.b64 %0, {%1,%2};" : "=l"(v) : "f"(x), "f"(y)); return v;
}
__device__ __forceinline__ unsigned smem_u32(const void* p) {
    unsigned a;
    asm("{ .reg .u64 t; cvta.to.shared.u64 t, %1; cvt.u32.u64 %0, t; }" : "=r"(a) : "l"(p));
    return a;
}
__device__ __forceinline__ float fsig(float x) { return __fdividef(1.f, 1.f + __expf(-x)); }
__device__ __forceinline__ float ftanh(float x) {
    float ax = fabsf(x);
    float e  = __expf(-2.f * ax);
    float r  = __fdividef(1.f - e, 1.f + e);
    return x < 0.f ? -r : r;
}
__device__ __forceinline__ void mbar_wait(unsigned mb, unsigned par) {
    unsigned done = 0;
    do {
        asm volatile("{\n\t.reg .pred p;\n\t"
            "mbarrier.try_wait.parity.acquire.cluster.shared::cta.b64 p, [%1], %2;\n\t"
            "selp.b32 %0,1,0,p;\n\t}" : "=r"(done) : "r"(mb), "r"(par) : "memory");
    } while (!done);
}

// ---------------- prep ----------------
__global__ void k_transpose_all(const float* __restrict__ w0, const float* __restrict__ w1,
                                const float* __restrict__ w2, const float* __restrict__ w3,
                                float* __restrict__ wT) {
    int m = blockIdx.y, c = blockIdx.x, g = threadIdx.x;
    const float* w = (m == 0) ? w0 : (m == 1) ? w1 : (m == 2) ? w2 : w3;
    int cols = (m < 2) ? INP : FF;
    if (c < cols) wT[m*FF*GG + c*GG + g] = w[g*cols + c];
}
__global__ void k_pack_ws1(const float* __restrict__ w) {
    int k2 = blockIdx.x, p = blockIdx.y, h = threadIdx.x;
    u64 v = 0ull;
    if (h < HID) v = f2u(w[h*768 + p*256 + 2*k2], w[h*768 + p*256 + 2*k2 + 1]);
    g_wsP[p][k2*128 + h] = v;
}

// ---------------- pre = x @ Wih^T + b, 8 timesteps per block ----------------
__global__ void k_pre8(const float* __restrict__ xin, const float* __restrict__ wT,
                       const float* __restrict__ bias, float* __restrict__ pre, int Din) {
    __shared__ float xs[8][FF];
    int sb = blockIdx.x * 8, b = blockIdx.y, g = threadIdx.x;
    for (int idx = g; idx < 8*Din; idx += GG) {
        int j = idx / Din, k = idx - j*Din;
        xs[j][k] = xin[(b*SS + sb + j)*Din + k];
    }
    __syncthreads();
    float bi = bias[g];
    float acc[8];
    #pragma unroll
    for (int j = 0; j < 8; j++) acc[j] = bi;
    for (int i = 0; i < Din; i++) {
        float wv = wT[i*GG + g];
        #pragma unroll
        for (int j = 0; j < 8; j++) acc[j] += xs[j][i] * wv;
    }
    #pragma unroll
    for (int j = 0; j < 8; j++) pre[((sb + j)*BB + b)*GG + g] = acc[j];
}

// ---------------- LSTM scan: 2-CTA cluster per dir, Whh in registers ----------------
// Exchange redesign: one warp pushes the CTA's 128 fresh h floats as 32x16B
// vectorized DSMEM stores + 32 release-arrives (was: 128 scattered 4B stores
// + 128 release-arrives from the epilogue threads).
__global__ void __launch_bounds__(256, 1) __cluster_dims__(2, 1, 1)
k_scan2(const float* __restrict__ preFp, const float* __restrict__ preBp,
        const float* __restrict__ whFp, const float* __restrict__ whBp,
        float* __restrict__ hout) {
    int dir  = blockIdx.x >> 1;
    int rank = blockIdx.x & 1;
    int peer = rank ^ 1;
    const float* pre = dir ? preBp : preFp;
    const u64*   W   = (const u64*)(dir ? whBp : whFp);   // [512 rows][64 u64]
    int t = threadIdx.x;
    int g = t >> 6, hl = t & 63;
    int hbase = rank * 64;
    int row = g * HH + hbase + hl;

    __shared__ __align__(16) float hsf[2][2][HH];  // [buf][batch][k]
    __shared__ float gs[2][4][64];                 // [batch][gate][local h]
    __shared__ __align__(8) u64 mbar;

    // weight row in regs: [0..31] local-half pairs, [32..63] remote-half pairs
    u64 w[64];
    #pragma unroll
    for (int q = 0; q < 32; q++) w[q]      = W[row*64 + rank*32 + q];
    #pragma unroll
    for (int q = 0; q < 32; q++) w[32 + q] = W[row*64 + peer*32 + q];

    for (int i = t; i < 2*2*HH; i += 256) ((float*)hsf)[i] = 0.f;
    unsigned mb = smem_u32(&mbar);
    if (t == 0) asm volatile("mbarrier.init.shared.b64 [%0], 32;" :: "r"(mb) : "memory");
    __syncthreads();
    asm volatile("barrier.cluster.arrive.aligned;" ::: "memory");
    asm volatile("barrier.cluster.wait.aligned;"   ::: "memory");

    unsigned rmb;
    asm("mapa.shared::cluster.u32 %0, %1, %2;" : "=r"(rmb) : "r"(mb), "r"(peer));

    int eb = t >> 6, eh = t & 63;                  // epilogue mapping (t < 128)
    // exchange warp precompute (t in [224,256))
    int xl  = t & 31;                              // lane in exchange warp
    int xb  = xl >> 4;                             // batch
    int xof = ((0*2 + xb)*HH + hbase + (xl & 15)*4);   // float offset in hsf for buf 0
    unsigned lbase = smem_u32(&hsf[0][0][0]);
    unsigned rbase;
    asm("mapa.shared::cluster.u32 %0, %1, %2;" : "=r"(rbase) : "r"(lbase), "r"(peer));
    float cst = 0.f;

    for (int s_ = 0; s_ < SS; s_++) {
        int s = dir ? (SS - 1 - s_) : s_;
        float p0 = __ldg(&pre[(s*BB + 0)*GG + row]);
        float p1 = __ldg(&pre[(s*BB + 1)*GG + row]);
        int rb = (s_ + 1) & 1;                     // buffer holding h(s_-1)
        int wb = s_ & 1;                           // buffer for h(s_)
        const u64* h0b = (const u64*)hsf[rb][0];
        const u64* h1b = (const u64*)hsf[rb][1];
        const u64* hl0 = h0b + rank*32;
        const u64* hl1 = h1b + rank*32;
        const u64* hr0 = h0b + peer*32;
        const u64* hr1 = h1b + peer*32;
        u64 a0 = 0ull, a1 = 0ull, b0 = 0ull, b1 = 0ull;
        #pragma unroll
        for (int q = 0; q < 32; q += 2) {          // local half (synced by __syncthreads)
            ulonglong2 x0 = *(const ulonglong2*)(hl0 + q);
            ulonglong2 x1 = *(const ulonglong2*)(hl1 + q);
            fma2(a0, w[q], x0.x);  fma2(a1, w[q + 1], x0.y);
            fma2(b0, w[q], x1.x);  fma2(b1, w[q + 1], x1.y);
        }
        if (s_ > 0) mbar_wait(mb, (s_ - 1) & 1);   // peer half of h(s_-1) arrived
        #pragma unroll
        for (int q = 0; q < 32; q += 2) {          // remote half
            ulonglong2 x0 = *(const ulonglong2*)(hr0 + q);
            ulonglong2 x1 = *(const ulonglong2*)(hr1 + q);
            fma2(a0, w[32 + q], x0.x);  fma2(a1, w[33 + q], x0.y);
            fma2(b0, w[32 + q], x1.x);  fma2(b1, w[33 + q], x1.y);
        }
        float2 fa = u2f(a0), fb = u2f(a1), fc = u2f(b0), fd = u2f(b1);
        gs[0][g][hl] = (fa.x + fa.y) + (fb.x + fb.y) + p0;
        gs[1][g][hl] = (fc.x + fc.y) + (fd.x + fd.y) + p1;
        __syncthreads();                           // all reads of buffer rb done
        if (t < 128) {
            float ig = fsig(gs[eb][0][eh]);
            float fg = fsig(gs[eb][1][eh]);
            float gg = ftanh(gs[eb][2][eh]);
            float og = fsig(gs[eb][3][eh]);
            cst = fg*cst + ig*gg;
            float hv = og * ftanh(cst);
            hsf[wb][eb][hbase + eh] = hv;
            hout[(eb*SS + s)*FF + dir*HH + hbase + eh] = hv;
        }
        __syncthreads();                           // hsf[wb] local half complete
        if (t >= 224) {                            // exchange warp: push our 128 floats
            unsigned off = (unsigned)(wb*2*HH + xof) * 4u;
            float4 v = *(const float4*)((const char*)hsf + off
                        - (u64)((const char*)hsf - (const char*)&hsf[0][0][0]));
            // (hsf base == &hsf[0][0][0]; simple load:)
            v = *(const float4*)(&hsf[wb][xb][hbase + (xl & 15)*4]);
            unsigned radr = rbase + off;
            asm volatile("st.shared::cluster.v4.f32 [%0], {%1,%2,%3,%4};"
                         :: "r"(radr), "f"(v.x), "f"(v.y), "f"(v.z), "f"(v.w) : "memory");
            asm volatile("mbarrier.arrive.release.cluster.shared::cluster.b64 _, [%0];"
                         :: "r"(rmb) : "memory");
        }
    }
    asm volatile("barrier.cluster.arrive.aligned;" ::: "memory");
    asm volatile("barrier.cluster.wait.aligned;"   ::: "memory");
}

// ---------------- cls / bin MLPs ----------------
__global__ void k_clsbin(const float* __restrict__ rnn,
    const float* ac0, const float* __restrict__ wc1, const float* __restrict__ bc1,
    const float* ac1, const float* __restrict__ wc2, const float* __restrict__ bc2,
    const float* ab0, const float* __restrict__ wb1, const float* __restrict__ bb1,
    const float* ab1, const float* __restrict__ wb2, const float* __restrict__ bb2,
    float* __restrict__ out) {
    int s = blockIdx.x, b = blockIdx.y, t = threadIdx.x; // blockDim = 192
    __shared__ float xc[FF], xb[FF], hc[80], hb[80];
    float a0c = *ac0, a0b = *ab0;
    for (int k = t; k < FF; k += 192) {
        float v = rnn[(b*SS + s)*FF + k];
        xc[k] = v >= 0.f ? v : a0c*v;
        xb[k] = v >= 0.f ? v : a0b*v;
    }
    __syncthreads();
    if (t < 80) {
        float acc = bc1[t];
        const float* w = wc1 + t*FF;
        #pragma unroll 4
        for (int k = 0; k < FF; k++) acc += xc[k]*w[k];
        float a1 = *ac1;
        hc[t] = acc >= 0.f ? acc : a1*acc;
    } else if (t < 160) {
        int g = t - 80;
        float acc = bb1[g];
        const float* w = wb1 + g*FF;
        #pragma unroll 4
        for (int k = 0; k < FF; k++) acc += xb[k]*w[k];
        float a1 = *ab1;
        hb[g] = acc >= 0.f ? acc : a1*acc;
    }
    __syncthreads();
    if (t < NCC) {
        float acc = bc2[t];
        const float* w = wc2 + t*80;
        #pragma unroll 4
        for (int k = 0; k < 80; k++) acc += hc[k]*w[k];
        out[(b*SS + s)*NCC + t] = acc;
    } else if (t < NCC + 2) {
        int o = t - NCC;
        float acc = bb2[o];
        const float* w = wb2 + o*80;
        #pragma unroll 4
        for (int k = 0; k < 80; k++) acc += hb[k]*w[k];
        out[20480 + (b*SS + s)*2 + o] = acc;
    }
}

// ---------------- cumsum ----------------
__global__ void k_cum(const float* __restrict__ rnn) {
    int b = blockIdx.x, k = threadIdx.x;
    float run = 0.f;
    for (int t0 = 0; t0 < SS; t0 += 8) {
        float v[8];
        #pragma unroll
        for (int j = 0; j < 8; j++) v[j] = rnn[(b*SS + t0 + j)*FF + k];
        #pragma unroll
        for (int j = 0; j < 8; j++) { run += v[j]; g_cum[(b*SS + t0 + j)*FF + k] = run; }
    }
}

// ---------------- Pd / Pe ----------------
__global__ void k_pdpe(const float* __restrict__ rnn, const float* as0, const float* __restrict__ bs1) {
    int s = blockIdx.x, b = blockIdx.y, t = threadIdx.x; // blockDim = 128
    __shared__ __align__(16) float xr[FF];
    float a0 = *as0;
    {
        float v0 = rnn[(b*SS + s)*FF + 2*t];
        float v1 = rnn[(b*SS + s)*FF + 2*t + 1];
        xr[2*t]     = v0 >= 0.f ? v0 : a0*v0;
        xr[2*t + 1] = v1 >= 0.f ? v1 : a0*v1;
    }
    __syncthreads();
    const u64* xp = (const u64*)xr;
    if (t < HID) {
        u64 d0 = 0ull, d1 = 0ull, e0 = 0ull, e1 = 0ull;
        #pragma unroll 8
        for (int k2 = 0; k2 < 128; k2 += 2) {
            fma2(d0, g_wsP[1][(k2    )*128 + t], xp[k2    ]);
            fma2(d1, g_wsP[1][(k2 + 1)*128 + t], xp[k2 + 1]);
            fma2(e0, g_wsP[2][(k2    )*128 + t], xp[k2    ]);
            fma2(e1, g_wsP[2][(k2 + 1)*128 + t], xp[k2 + 1]);
        }
        float2 fd0 = u2f(d0), fd1 = u2f(d1), fe0 = u2f(e0), fe1 = u2f(e1);
        g_Pd[(b*SS + s)*HID + t] = fd0.x + fd0.y + fd1.x + fd1.y;
        g_Pe[(b*SS + s)*HID + t] = fe0.x + fe0.y + fe1.x + fe1.y + bs1[t];
    }
}

// ---------------- banded score MLP ----------------
__global__ void k_scores(const float* as0, const float* as1,
                         const float* __restrict__ ws2, const float* bs2) {
    int i = blockIdx.x, b = blockIdx.y, jh = blockIdx.z, t = threadIdx.x; // blockDim = 128
    if (i == 0) return;
    __shared__ __align__(16) float cdf[FF];
    __shared__ float wsum[4];
    const u64* cd = (const u64*)cdf;
    float a0 = *as0, a1 = *as1, b2 = *bs2;
    const float* cumi = g_cum + (b*SS + i)*FF;
    float ci0 = cumi[2*t], ci1 = cumi[2*t + 1];
    float pei = (t < HID) ? g_Pe[(b*SS + i)*HID + t] : 0.f;
    float w2  = (t < HID) ? ws2[t] : 0.f;
    for (int wl = 0; wl < 32; ++wl) {
        int w = jh*32 + wl;
        int j = i - WW + w;
        if (j < 0) {
            if (t == 0) g_sband[(b*SS + i)*WW + w] = -1000000000.0f;
            continue;
        }
        const float* cumj = g_cum + (b*SS + j)*FF;
        float c0 = ci0 - cumj[2*t];
        float c1 = ci1 - cumj[2*t + 1];
        cdf[2*t]     = c0 >= 0.f ? c0 : a0*c0;
        cdf[2*t + 1] = c1 >= 0.f ? c1 : a0*c1;
        __syncthreads();
        float val = 0.f;
        if (t < HID) {
            u64 s0 = 0ull, s1 = 0ull;
            const u64* wrow = g_wsP[0] + t;
            #pragma unroll 8
            for (int k2 = 0; k2 < 128; k2 += 2) {
                fma2(s0, wrow[(k2    )*128], cd[k2    ]);
                fma2(s1, wrow[(k2 + 1)*128], cd[k2 + 1]);
            }
            float2 f0 = u2f(s0), f1 = u2f(s1);
            float hid = f0.x + f0.y + f1.x + f1.y + g_Pd[(b*SS + j)*HID + t] + pei;
            float ph  = hid >= 0.f ? hid : a1*hid;
            val = ph * w2;
        }
        for (int off = 16; off; off >>= 1) val += __shfl_down_sync(0xffffffffu, val, off);
        if ((t & 31) == 0) wsum[t >> 5] = val;
        __syncthreads();
        if (t == 0) g_sband[(b*SS + i)*WW + w] = wsum[0] + wsum[1] + wsum[2] + wsum[3] + b2;
        __syncthreads();
    }
}

// ---------------- DP + backtrack ----------------
__global__ void k_dp(const int* __restrict__ lengths, float* __restrict__ out) {
    __shared__ float best[BB][SS];
    __shared__ int   bp[BB][SS];
    int t = threadIdx.x;          // blockDim = 64
    int b = t >> 5, lane = t & 31;
    for (int idx = t; idx < BB*SS; idx += 64) best[idx >> 8][idx & 255] = 0.f;
    for (int idx = t; idx < BB*SS; idx += 64) out[21504 + idx] = 0.f;
    if (t < BB) bp[t][0] = 0;
    __syncthreads();
    for (int i = 1; i < SS; i++) {
        int w1 = lane, w2 = lane + 32;
        int j1 = i - WW + w1, j2 = i - WW + w2;
        float c1 = (j1 >= 0) ? best[b][j1] + g_sband[(b*SS + i)*WW + w1] : -1000000000.0f;
        float c2 = (j2 >= 0) ? best[b][j2] + g_sband[(b*SS + i)*WW + w2] : -1000000000.0f;
        float v; int jj;
        if (c2 > c1) { v = c2; jj = j2; } else { v = c1; jj = j1; }
        for (int off = 16; off; off >>= 1) {
            float ov = __shfl_down_sync(0xffffffffu, v,  off);
            int   oj = __shfl_down_sync(0xffffffffu, jj, off);
            if (ov > v || (ov == v && oj < jj)) { v = ov; jj = oj; }
        }
        if (lane == 0) { best[b][i] = v; bp[b][i] = jj; }
        __syncwarp();
    }
    __syncthreads();
    if (t < BB) {
        int cur = lengths[t] - 1;
        if (cur < 0) cur = 0;
        float acc = 0.f;
        while (true) {
            out[21504 + t*SS + cur] = 1.f;
            if (cur == 0) break;
            int prev = bp[t][cur];
            acc += g_sband[(t*SS + cur)*WW + (prev - (cur - WW))];
            cur = prev;
        }
        out[22016 + t] = acc;
    }
}

// ---------------- launch ----------------
extern "C" void kernel_launch(void* const* d_in, const int* in_sizes, int n_in,
                              void* d_out, int out_size) {
    (void)in_sizes; (void)n_in; (void)out_size;
    const float* x        = (const float*)d_in[0];
    const int*   lengths  = (const int*)  d_in[1];
    const float* wih[4]   = {(const float*)d_in[2], (const float*)d_in[5],
                             (const float*)d_in[8], (const float*)d_in[11]};
    const float* whh[4]   = {(const float*)d_in[3], (const float*)d_in[6],
                             (const float*)d_in[9], (const float*)d_in[12]};
    const float* bl[4]    = {(const float*)d_in[4], (const float*)d_in[7],
                             (const float*)d_in[10], (const float*)d_in[13]};
    const float* a_s0 = (const float*)d_in[14];
    const float* w_s1 = (const float*)d_in[15];
    const float* b_s1 = (const float*)d_in[16];
    const float* a_s1 = (const float*)d_in[17];
    const float* w_s2 = (const float*)d_in[18];
    const float* b_s2 = (const float*)d_in[19];
    const float* a_c0 = (const float*)d_in[20];
    const float* w_c1 = (const float*)d_in[21];
    const float* b_c1 = (const float*)d_in[22];
    const float* a_c1 = (const float*)d_in[23];
    const float* w_c2 = (const float*)d_in[24];
    const float* b_c2 = (const float*)d_in[25];
    const float* a_b0 = (const float*)d_in[26];
    const float* w_b1 = (const float*)d_in[27];
    const float* b_b1 = (const float*)d_in[28];
    const float* a_b1 = (const float*)d_in[29];
    const float* w_b2 = (const float*)d_in[30];
    const float* b_b2 = (const float*)d_in[31];
    float* out = (float*)d_out;

    float *wihT, *preF, *preB, *h0, *rnn;
    cudaGetSymbolAddress((void**)&wihT, g_wihT);
    cudaGetSymbolAddress((void**)&preF, g_preF);
    cudaGetSymbolAddress((void**)&preB, g_preB);
    cudaGetSymbolAddress((void**)&h0,   g_h0);
    cudaGetSymbolAddress((void**)&rnn,  g_rnn);

    k_transpose_all<<<dim3(FF, 4), GG>>>(wih[0], wih[1], wih[2], wih[3], wihT);
    k_pack_ws1<<<dim3(128, 3), 128>>>(w_s1);

    dim3 gpre8(SS/8, BB);
    // layer 0
    k_pre8<<<gpre8, GG>>>(x, wihT + 0*FF*GG, bl[0], preF, INP);
    k_pre8<<<gpre8, GG>>>(x, wihT + 1*FF*GG, bl[1], preB, INP);
    k_scan2<<<4, 256>>>(preF, preB, whh[0], whh[1], h0);
    // layer 1
    k_pre8<<<gpre8, GG>>>(h0, wihT + 2*FF*GG, bl[2], preF, FF);
    k_pre8<<<gpre8, GG>>>(h0, wihT + 3*FF*GG, bl[3], preB, FF);
    k_scan2<<<4, 256>>>(preF, preB, whh[2], whh[3], rnn);

    k_clsbin<<<dim3(SS, BB), 192>>>(rnn, a_c0, w_c1, b_c1, a_c1, w_c2, b_c2,
                                         a_b0, w_b1, b_b1, a_b1, w_b2, b_b2, out);
    k_cum<<<BB, FF>>>(rnn);
    k_pdpe<<<dim3(SS, BB), 128>>>(rnn, a_s0, b_s1);
    k_scores<<<dim3(SS, BB, 2), 128>>>(a_s0, a_s1, w_s2, b_s2);
    k_dp<<<1, 64>>>(lengths, out);
}

// round 8
// speedup vs baseline: 2.7501x; 1.1056x over previous
#include <cuda_runtime.h>
#include <cuda_bf16.h>

#define BB   2
#define SS   256
#define INP  80
#define HH   128
#define GG   512
#define FF   256
#define NCC  40
#define WW   64
#define HID  100

typedef unsigned long long u64;

__device__ float g_wihT [4][FF*GG];
__device__ u64   g_wsP  [3][128*128];
__device__ float g_preF [SS*BB*GG];
__device__ float g_preB [SS*BB*GG];
__device__ float g_h0   [BB*SS*FF];
__device__ float g_rnn  [BB*SS*FF];
__device__ float g_cum  [BB*SS*FF];
__device__ float g_Pd   [BB*SS*HID];
__device__ float g_Pe   [BB*SS*HID];
__device__ float g_sband[BB*SS*WW];

__device__ __forceinline__ void fma2(u64 &d, u64 a, u64 b) {
    asm("fma.rn.f32x2 %0, %1, %2, %0;" : "+l"(d) : "l"(a), "l"(b));
}
__device__ __forceinline__ float2 u2f(u64 v) {
    float2 f; asm("mov.b64 {%0,%1}, %2;" : "=f"(f.x), "=f"(f.y) : "l"(v)); return f;
}
__device__ __forceinline__ u64 f2u(float x, float y) {
    u64 v; asm("mov.b64 %0, {%1,%2};" : "=l"(v) : "f"(x), "f"(y)); return v;
}
__device__ __forceinline__ unsigned smem_u32(const void* p) {
    unsigned a;
    asm("{ .reg .u64 t; cvta.to.shared.u64 t, %1; cvt.u32.u64 %0, t; }" : "=r"(a) : "l"(p));
    return a;
}
__device__ __forceinline__ float fsig(float x) { return __fdividef(1.f, 1.f + __expf(-x)); }
__device__ __forceinline__ float ftanh(float x) {
    float ax = fabsf(x);
    float e  = __expf(-2.f * ax);
    float r  = __fdividef(1.f - e, 1.f + e);
    return x < 0.f ? -r : r;
}
__device__ __forceinline__ void mbar_wait(unsigned mb, unsigned par) {
    unsigned done = 0;
    do {
        asm volatile("{\n\t.reg .pred p;\n\t"
            "mbarrier.try_wait.parity.acquire.cluster.shared::cta.b64 p, [%1], %2;\n\t"
            "selp.b32 %0,1,0,p;\n\t}" : "=r"(done) : "r"(mb), "r"(par) : "memory");
    } while (!done);
}

// ---------------- prep ----------------
__global__ void k_transpose_all(const float* __restrict__ w0, const float* __restrict__ w1,
                                const float* __restrict__ w2, const float* __restrict__ w3,
                                float* __restrict__ wT) {
    int m = blockIdx.y, c = blockIdx.x, g = threadIdx.x;
    const float* w = (m == 0) ? w0 : (m == 1) ? w1 : (m == 2) ? w2 : w3;
    int cols = (m < 2) ? INP : FF;
    if (c < cols) wT[m*FF*GG + c*GG + g] = w[g*cols + c];
}
__global__ void k_pack_ws1(const float* __restrict__ w) {
    int k2 = blockIdx.x, p = blockIdx.y, h = threadIdx.x;
    u64 v = 0ull;
    if (h < HID) v = f2u(w[h*768 + p*256 + 2*k2], w[h*768 + p*256 + 2*k2 + 1]);
    g_wsP[p][k2*128 + h] = v;
}

// ---------------- pre = x @ Wih^T + b, 8 timesteps per block, F+B merged ----------------
__global__ void k_pre8m(const float* __restrict__ xin, const float* __restrict__ wTbase,
                        const float* __restrict__ bF, const float* __restrict__ bB,
                        float* __restrict__ preFo, float* __restrict__ preBo, int Din) {
    __shared__ float xs[8][FF];
    int z = blockIdx.z;
    const float* wT   = wTbase + z*FF*GG;
    const float* bias = z ? bB : bF;
    float* pre        = z ? preBo : preFo;
    int sb = blockIdx.x * 8, b = blockIdx.y, g = threadIdx.x;
    for (int idx = g; idx < 8*Din; idx += GG) {
        int j = idx / Din, k = idx - j*Din;
        xs[j][k] = xin[(b*SS + sb + j)*Din + k];
    }
    __syncthreads();
    float bi = bias[g];
    float acc[8];
    #pragma unroll
    for (int j = 0; j < 8; j++) acc[j] = bi;
    for (int i = 0; i < Din; i += 4) {
        float w0 = wT[(i    )*GG + g];
        float w1 = wT[(i + 1)*GG + g];
        float w2 = wT[(i + 2)*GG + g];
        float w3 = wT[(i + 3)*GG + g];
        #pragma unroll
        for (int j = 0; j < 8; j++)
            acc[j] += xs[j][i]*w0 + xs[j][i+1]*w1 + xs[j][i+2]*w2 + xs[j][i+3]*w3;
    }
    #pragma unroll
    for (int j = 0; j < 8; j++) pre[((sb + j)*BB + b)*GG + g] = acc[j];
}

// ---------------- LSTM scan: 4-CTA cluster per dir, Whh in registers ----------------
// CTA rank owns h-units [32r, 32r+32). Thread t: batch tb=t>>7, gate g=(t>>5)&3,
// unit hl=t&31 -> one 128-long dot per thread (64 FFMA2).
// Exchange: warps 6-7 push the CTA's 64 fresh h floats (16 float4) to each of
// 3 peers; mbar counts 48 arrivals (16 per peer).
__global__ void __launch_bounds__(256, 1) __cluster_dims__(4, 1, 1)
k_scan4(const float* __restrict__ preFp, const float* __restrict__ preBp,
        const float* __restrict__ whFp, const float* __restrict__ whBp,
        float* __restrict__ hout) {
    int dir  = blockIdx.x >> 2;
    int rank = blockIdx.x & 3;
    const float* pre = dir ? preBp : preFp;
    const u64*   W   = (const u64*)(dir ? whBp : whFp);   // [512 rows][64 u64]
    int t  = threadIdx.x;
    int tb = t >> 7;
    int g  = (t >> 5) & 3;
    int hl = t & 31;
    int row = g*HH + rank*32 + hl;

    __shared__ __align__(16) float hsf[2][2][HH];  // [buf][batch][k]
    __shared__ float gs[2][4][32];                 // [batch][gate][local unit]
    __shared__ __align__(8) u64 mbar;

    // 64 weight pairs, chunked so chunk 0 = this CTA's local quarter of k
    u64 w[64];
    #pragma unroll
    for (int c = 0; c < 4; c++) {
        int qb = 16 * ((rank + c) & 3);
        #pragma unroll
        for (int j = 0; j < 16; j++) w[c*16 + j] = W[row*64 + qb + j];
    }

    for (int i = t; i < 2*2*HH; i += 256) ((float*)hsf)[i] = 0.f;
    unsigned mb = smem_u32(&mbar);
    if (t == 0) asm volatile("mbarrier.init.shared.b64 [%0], 48;" :: "r"(mb) : "memory");
    __syncthreads();
    asm volatile("barrier.cluster.arrive.aligned;" ::: "memory");
    asm volatile("barrier.cluster.wait.aligned;"   ::: "memory");

    // exchange-lane precompute (t in [192,256), active xl<48)
    int xl  = t - 192;
    int pi  = xl >> 4;                 // peer index 0..2
    int vv  = xl & 15;                 // vec id 0..15
    int vtb = vv >> 3;                 // batch
    int vof = (vv & 7) * 4;            // float offset within 32-unit quarter
    int pr  = (rank + 1 + pi) & 3;     // peer rank
    unsigned lbase = smem_u32(&hsf[0][0][0]);
    unsigned rmb = 0, rbase = 0;
    asm("mapa.shared::cluster.u32 %0, %1, %2;" : "=r"(rmb)   : "r"(mb),    "r"(pr));
    asm("mapa.shared::cluster.u32 %0, %1, %2;" : "=r"(rbase) : "r"(lbase), "r"(pr));

    int etb = t >> 5, eh = t & 31;     // epilogue mapping (t < 64)
    float cst = 0.f;

    for (int s_ = 0; s_ < SS; s_++) {
        int s = dir ? (SS - 1 - s_) : s_;
        float p = __ldg(&pre[(s*BB + tb)*GG + row]);
        int rb = (s_ + 1) & 1;
        int wb = s_ & 1;
        const u64* h2 = (const u64*)hsf[rb][tb];
        u64 a0 = 0ull, a1 = 0ull;
        {   // local quarter (chunk 0) — ordered by __syncthreads
            const u64* hq = h2 + 16*rank;
            #pragma unroll
            for (int j = 0; j < 16; j += 2) {
                ulonglong2 x = *(const ulonglong2*)(hq + j);
                fma2(a0, w[j], x.x);  fma2(a1, w[j + 1], x.y);
            }
        }
        if (s_ > 0) mbar_wait(mb, (s_ - 1) & 1);   // all peers' quarters arrived
        #pragma unroll
        for (int c = 1; c < 4; c++) {
            const u64* hq = h2 + 16*((rank + c) & 3);
            #pragma unroll
            for (int j = 0; j < 16; j += 2) {
                ulonglong2 x = *(const ulonglong2*)(hq + j);
                fma2(a0, w[c*16 + j], x.x);  fma2(a1, w[c*16 + j + 1], x.y);
            }
        }
        float2 fa = u2f(a0), fb = u2f(a1);
        gs[tb][g][hl] = (fa.x + fa.y) + (fb.x + fb.y) + p;
        __syncthreads();                           // gates ready; reads of rb done
        if (t < 64) {
            float ig = fsig(gs[etb][0][eh]);
            float fg = fsig(gs[etb][1][eh]);
            float gg = ftanh(gs[etb][2][eh]);
            float og = fsig(gs[etb][3][eh]);
            cst = fg*cst + ig*gg;
            float hv = og * ftanh(cst);
            hsf[wb][etb][rank*32 + eh] = hv;
            hout[(etb*SS + s)*FF + dir*HH + rank*32 + eh] = hv;
        }
        __syncthreads();                           // local quarter of wb complete
        if (xl >= 0 && xl < 48) {                  // push our quarter to 3 peers
            float4 v = *(const float4*)(&hsf[wb][vtb][rank*32 + vof]);
            unsigned off = (unsigned)(((wb*2 + vtb)*HH + rank*32 + vof) * 4);
            asm volatile("st.shared::cluster.v4.f32 [%0], {%1,%2,%3,%4};"
                         :: "r"(rbase + off), "f"(v.x), "f"(v.y), "f"(v.z), "f"(v.w) : "memory");
            asm volatile("mbarrier.arrive.release.cluster.shared::cluster.b64 _, [%0];"
                         :: "r"(rmb) : "memory");
        }
    }
    asm volatile("barrier.cluster.arrive.aligned;" ::: "memory");
    asm volatile("barrier.cluster.wait.aligned;"   ::: "memory");
}

// ---------------- cls / bin MLPs ----------------
__global__ void k_clsbin(const float* __restrict__ rnn,
    const float* ac0, const float* __restrict__ wc1, const float* __restrict__ bc1,
    const float* ac1, const float* __restrict__ wc2, const float* __restrict__ bc2,
    const float* ab0, const float* __restrict__ wb1, const float* __restrict__ bb1,
    const float* ab1, const float* __restrict__ wb2, const float* __restrict__ bb2,
    float* __restrict__ out) {
    int s = blockIdx.x, b = blockIdx.y, t = threadIdx.x; // blockDim = 192
    __shared__ float xc[FF], xb[FF], hc[80], hb[80];
    float a0c = *ac0, a0b = *ab0;
    for (int k = t; k < FF; k += 192) {
        float v = rnn[(b*SS + s)*FF + k];
        xc[k] = v >= 0.f ? v : a0c*v;
        xb[k] = v >= 0.f ? v : a0b*v;
    }
    __syncthreads();
    if (t < 80) {
        float acc = bc1[t];
        const float* w = wc1 + t*FF;
        #pragma unroll 4
        for (int k = 0; k < FF; k++) acc += xc[k]*w[k];
        float a1 = *ac1;
        hc[t] = acc >= 0.f ? acc : a1*acc;
    } else if (t < 160) {
        int g = t - 80;
        float acc = bb1[g];
        const float* w = wb1 + g*FF;
        #pragma unroll 4
        for (int k = 0; k < FF; k++) acc += xb[k]*w[k];
        float a1 = *ab1;
        hb[g] = acc >= 0.f ? acc : a1*acc;
    }
    __syncthreads();
    if (t < NCC) {
        float acc = bc2[t];
        const float* w = wc2 + t*80;
        #pragma unroll 4
        for (int k = 0; k < 80; k++) acc += hc[k]*w[k];
        out[(b*SS + s)*NCC + t] = acc;
    } else if (t < NCC + 2) {
        int o = t - NCC;
        float acc = bb2[o];
        const float* w = wb2 + o*80;
        #pragma unroll 4
        for (int k = 0; k < 80; k++) acc += hb[k]*w[k];
        out[20480 + (b*SS + s)*2 + o] = acc;
    }
}

// ---------------- cumsum ----------------
__global__ void k_cum(const float* __restrict__ rnn) {
    int b = blockIdx.x, k = threadIdx.x;
    float run = 0.f;
    for (int t0 = 0; t0 < SS; t0 += 8) {
        float v[8];
        #pragma unroll
        for (int j = 0; j < 8; j++) v[j] = rnn[(b*SS + t0 + j)*FF + k];
        #pragma unroll
        for (int j = 0; j < 8; j++) { run += v[j]; g_cum[(b*SS + t0 + j)*FF + k] = run; }
    }
}

// ---------------- Pd / Pe ----------------
__global__ void k_pdpe(const float* __restrict__ rnn, const float* as0, const float* __restrict__ bs1) {
    int s = blockIdx.x, b = blockIdx.y, t = threadIdx.x; // blockDim = 128
    __shared__ __align__(16) float xr[FF];
    float a0 = *as0;
    {
        float v0 = rnn[(b*SS + s)*FF + 2*t];
        float v1 = rnn[(b*SS + s)*FF + 2*t + 1];
        xr[2*t]     = v0 >= 0.f ? v0 : a0*v0;
        xr[2*t + 1] = v1 >= 0.f ? v1 : a0*v1;
    }
    __syncthreads();
    const u64* xp = (const u64*)xr;
    if (t < HID) {
        u64 d0 = 0ull, d1 = 0ull, e0 = 0ull, e1 = 0ull;
        #pragma unroll 8
        for (int k2 = 0; k2 < 128; k2 += 2) {
            fma2(d0, g_wsP[1][(k2    )*128 + t], xp[k2    ]);
            fma2(d1, g_wsP[1][(k2 + 1)*128 + t], xp[k2 + 1]);
            fma2(e0, g_wsP[2][(k2    )*128 + t], xp[k2    ]);
            fma2(e1, g_wsP[2][(k2 + 1)*128 + t], xp[k2 + 1]);
        }
        float2 fd0 = u2f(d0), fd1 = u2f(d1), fe0 = u2f(e0), fe1 = u2f(e1);
        g_Pd[(b*SS + s)*HID + t] = fd0.x + fd0.y + fd1.x + fd1.y;
        g_Pe[(b*SS + s)*HID + t] = fe0.x + fe0.y + fe1.x + fe1.y + bs1[t];
    }
}

// ---------------- banded score MLP ----------------
__global__ void k_scores(const float* as0, const float* as1,
                         const float* __restrict__ ws2, const float* bs2) {
    int i = blockIdx.x, b = blockIdx.y, jh = blockIdx.z, t = threadIdx.x; // blockDim = 128
    if (i == 0) return;
    __shared__ __align__(16) float cdf[FF];
    __shared__ float wsum[4];
    const u64* cd = (const u64*)cdf;
    float a0 = *as0, a1 = *as1, b2 = *bs2;
    const float* cumi = g_cum + (b*SS + i)*FF;
    float ci0 = cumi[2*t], ci1 = cumi[2*t + 1];
    float pei = (t < HID) ? g_Pe[(b*SS + i)*HID + t] : 0.f;
    float w2  = (t < HID) ? ws2[t] : 0.f;
    for (int wl = 0; wl < 32; ++wl) {
        int w = jh*32 + wl;
        int j = i - WW + w;
        if (j < 0) {
            if (t == 0) g_sband[(b*SS + i)*WW + w] = -1000000000.0f;
            continue;
        }
        const float* cumj = g_cum + (b*SS + j)*FF;
        float c0 = ci0 - cumj[2*t];
        float c1 = ci1 - cumj[2*t + 1];
        cdf[2*t]     = c0 >= 0.f ? c0 : a0*c0;
        cdf[2*t + 1] = c1 >= 0.f ? c1 : a0*c1;
        __syncthreads();
        float val = 0.f;
        if (t < HID) {
            u64 s0 = 0ull, s1 = 0ull;
            const u64* wrow = g_wsP[0] + t;
            #pragma unroll 8
            for (int k2 = 0; k2 < 128; k2 += 2) {
                fma2(s0, wrow[(k2    )*128], cd[k2    ]);
                fma2(s1, wrow[(k2 + 1)*128], cd[k2 + 1]);
            }
            float2 f0 = u2f(s0), f1 = u2f(s1);
            float hid = f0.x + f0.y + f1.x + f1.y + g_Pd[(b*SS + j)*HID + t] + pei;
            float ph  = hid >= 0.f ? hid : a1*hid;
            val = ph * w2;
        }
        for (int off = 16; off; off >>= 1) val += __shfl_down_sync(0xffffffffu, val, off);
        if ((t & 31) == 0) wsum[t >> 5] = val;
        __syncthreads();
        if (t == 0) g_sband[(b*SS + i)*WW + w] = wsum[0] + wsum[1] + wsum[2] + wsum[3] + b2;
        __syncthreads();
    }
}

// ---------------- DP + backtrack ----------------
__global__ void k_dp(const int* __restrict__ lengths, float* __restrict__ out) {
    __shared__ float best[BB][SS];
    __shared__ int   bp[BB][SS];
    int t = threadIdx.x;          // blockDim = 64
    int b = t >> 5, lane = t & 31;
    for (int idx = t; idx < BB*SS; idx += 64) best[idx >> 8][idx & 255] = 0.f;
    for (int idx = t; idx < BB*SS; idx += 64) out[21504 + idx] = 0.f;
    if (t < BB) bp[t][0] = 0;
    __syncthreads();
    for (int i = 1; i < SS; i++) {
        int w1 = lane, w2 = lane + 32;
        int j1 = i - WW + w1, j2 = i - WW + w2;
        float c1 = (j1 >= 0) ? best[b][j1] + g_sband[(b*SS + i)*WW + w1] : -1000000000.0f;
        float c2 = (j2 >= 0) ? best[b][j2] + g_sband[(b*SS + i)*WW + w2] : -1000000000.0f;
        float v; int jj;
        if (c2 > c1) { v = c2; jj = j2; } else { v = c1; jj = j1; }
        for (int off = 16; off; off >>= 1) {
            float ov = __shfl_down_sync(0xffffffffu, v,  off);
            int   oj = __shfl_down_sync(0xffffffffu, jj, off);
            if (ov > v || (ov == v && oj < jj)) { v = ov; jj = oj; }
        }
        if (lane == 0) { best[b][i] = v; bp[b][i] = jj; }
        __syncwarp();
    }
    __syncthreads();
    if (t < BB) {
        int cur = lengths[t] - 1;
        if (cur < 0) cur = 0;
        float acc = 0.f;
        while (true) {
            out[21504 + t*SS + cur] = 1.f;
            if (cur == 0) break;
            int prev = bp[t][cur];
            acc += g_sband[(t*SS + cur)*WW + (prev - (cur - WW))];
            cur = prev;
        }
        out[22016 + t] = acc;
    }
}

// ---------------- launch ----------------
extern "C" void kernel_launch(void* const* d_in, const int* in_sizes, int n_in,
                              void* d_out, int out_size) {
    (void)in_sizes; (void)n_in; (void)out_size;
    const float* x        = (const float*)d_in[0];
    const int*   lengths  = (const int*)  d_in[1];
    const float* wih[4]   = {(const float*)d_in[2], (const float*)d_in[5],
                             (const float*)d_in[8], (const float*)d_in[11]};
    const float* whh[4]   = {(const float*)d_in[3], (const float*)d_in[6],
                             (const float*)d_in[9], (const float*)d_in[12]};
    const float* bl[4]    = {(const float*)d_in[4], (const float*)d_in[7],
                             (const float*)d_in[10], (const float*)d_in[13]};
    const float* a_s0 = (const float*)d_in[14];
    const float* w_s1 = (const float*)d_in[15];
    const float* b_s1 = (const float*)d_in[16];
    const float* a_s1 = (const float*)d_in[17];
    const float* w_s2 = (const float*)d_in[18];
    const float* b_s2 = (const float*)d_in[19];
    const float* a_c0 = (const float*)d_in[20];
    const float* w_c1 = (const float*)d_in[21];
    const float* b_c1 = (const float*)d_in[22];
    const float* a_c1 = (const float*)d_in[23];
    const float* w_c2 = (const float*)d_in[24];
    const float* b_c2 = (const float*)d_in[25];
    const float* a_b0 = (const float*)d_in[26];
    const float* w_b1 = (const float*)d_in[27];
    const float* b_b1 = (const float*)d_in[28];
    const float* a_b1 = (const float*)d_in[29];
    const float* w_b2 = (const float*)d_in[30];
    const float* b_b2 = (const float*)d_in[31];
    float* out = (float*)d_out;

    float *wihT, *preF, *preB, *h0, *rnn;
    cudaGetSymbolAddress((void**)&wihT, g_wihT);
    cudaGetSymbolAddress((void**)&preF, g_preF);
    cudaGetSymbolAddress((void**)&preB, g_preB);
    cudaGetSymbolAddress((void**)&h0,   g_h0);
    cudaGetSymbolAddress((void**)&rnn,  g_rnn);

    k_transpose_all<<<dim3(FF, 4), GG>>>(wih[0], wih[1], wih[2], wih[3], wihT);
    k_pack_ws1<<<dim3(128, 3), 128>>>(w_s1);

    dim3 gpre8(SS/8, BB, 2);
    // layer 0
    k_pre8m<<<gpre8, GG>>>(x, wihT, bl[0], bl[1], preF, preB, INP);
    k_scan4<<<8, 256>>>(preF, preB, whh[0], whh[1], h0);
    // layer 1
    k_pre8m<<<gpre8, GG>>>(h0, wihT + 2*FF*GG, bl[2], bl[3], preF, preB, FF);
    k_scan4<<<8, 256>>>(preF, preB, whh[2], whh[3], rnn);

    k_clsbin<<<dim3(SS, BB), 192>>>(rnn, a_c0, w_c1, b_c1, a_c1, w_c2, b_c2,
                                         a_b0, w_b1, b_b1, a_b1, w_b2, b_b2, out);
    k_cum<<<BB, FF>>>(rnn);
    k_pdpe<<<dim3(SS, BB), 128>>>(rnn, a_s0, b_s1);
    k_scores<<<dim3(SS, BB, 2), 128>>>(a_s0, a_s1, w_s2, b_s2);
    k_dp<<<1, 64>>>(lengths, out);
}

// round 9
// speedup vs baseline: 3.0126x; 1.0954x over previous
#include <cuda_runtime.h>
#include <cuda_bf16.h>

#define BB   2
#define SS   256
#define INP  80
#define HH   128
#define GG   512
#define FF   256
#define NCC  40
#define WW   64
#define HID  100

typedef unsigned long long u64;

__device__ float g_wihT [4][FF*GG];
__device__ u64   g_wsP  [3][128*128];
__device__ float g_preF [SS*BB*GG];
__device__ float g_preB [SS*BB*GG];
__device__ float g_h0   [BB*SS*FF];
__device__ float g_rnn  [BB*SS*FF];
__device__ float g_cum  [BB*SS*FF];
__device__ float g_Pd   [BB*SS*HID];
__device__ float g_Pe   [BB*SS*HID];
__device__ float g_sband[BB*SS*WW];

__device__ __forceinline__ void fma2(u64 &d, u64 a, u64 b) {
    asm("fma.rn.f32x2 %0, %1, %2, %0;" : "+l"(d) : "l"(a), "l"(b));
}
__device__ __forceinline__ float2 u2f(u64 v) {
    float2 f; asm("mov.b64 {%0,%1}, %2;" : "=f"(f.x), "=f"(f.y) : "l"(v)); return f;
}
__device__ __forceinline__ u64 f2u(float x, float y) {
    u64 v; asm("mov.b64 %0, {%1,%2};" : "=l"(v) : "f"(x), "f"(y)); return v;
}
__device__ __forceinline__ unsigned smem_u32(const void* p) {
    unsigned a;
    asm("{ .reg .u64 t; cvta.to.shared.u64 t, %1; cvt.u32.u64 %0, t; }" : "=r"(a) : "l"(p));
    return a;
}
__device__ __forceinline__ float fsig(float x) { return __fdividef(1.f, 1.f + __expf(-x)); }
__device__ __forceinline__ float ftanh(float x) {
    float ax = fabsf(x);
    float e  = __expf(-2.f * ax);
    float r  = __fdividef(1.f - e, 1.f + e);
    return x < 0.f ? -r : r;
}
__device__ __forceinline__ void mbar_wait(unsigned mb, unsigned par) {
    unsigned done = 0;
    do {
        asm volatile("{\n\t.reg .pred p;\n\t"
            "mbarrier.try_wait.parity.acquire.cluster.shared::cta.b64 p, [%1], %2, 0x989680;\n\t"
            "selp.b32 %0,1,0,p;\n\t}" : "=r"(done) : "r"(mb), "r"(par) : "memory");
    } while (!done);
}

// ---------------- prep ----------------
__global__ void k_transpose_all(const float* __restrict__ w0, const float* __restrict__ w1,
                                const float* __restrict__ w2, const float* __restrict__ w3,
                                float* __restrict__ wT) {
    int m = blockIdx.y, c = blockIdx.x, g = threadIdx.x;
    const float* w = (m == 0) ? w0 : (m == 1) ? w1 : (m == 2) ? w2 : w3;
    int cols = (m < 2) ? INP : FF;
    if (c < cols) wT[m*FF*GG + c*GG + g] = w[g*cols + c];
}
__global__ void k_pack_ws1(const float* __restrict__ w) {
    int k2 = blockIdx.x, p = blockIdx.y, h = threadIdx.x;
    u64 v = 0ull;
    if (h < HID) v = f2u(w[h*768 + p*256 + 2*k2], w[h*768 + p*256 + 2*k2 + 1]);
    g_wsP[p][k2*128 + h] = v;
}

// ---------------- pre = x @ Wih^T + b, 8 timesteps per block, F+B merged ----------------
__global__ void k_pre8m(const float* __restrict__ xin, const float* __restrict__ wTbase,
                        const float* __restrict__ bF, const float* __restrict__ bB,
                        float* __restrict__ preFo, float* __restrict__ preBo, int Din) {
    __shared__ float xs[8][FF];
    int z = blockIdx.z;
    const float* wT   = wTbase + z*FF*GG;
    const float* bias = z ? bB : bF;
    float* pre        = z ? preBo : preFo;
    int sb = blockIdx.x * 8, b = blockIdx.y, g = threadIdx.x;
    for (int idx = g; idx < 8*Din; idx += GG) {
        int j = idx / Din, k = idx - j*Din;
        xs[j][k] = xin[(b*SS + sb + j)*Din + k];
    }
    __syncthreads();
    float bi = bias[g];
    float acc[8];
    #pragma unroll
    for (int j = 0; j < 8; j++) acc[j] = bi;
    for (int i = 0; i < Din; i += 4) {
        float w0 = wT[(i    )*GG + g];
        float w1 = wT[(i + 1)*GG + g];
        float w2 = wT[(i + 2)*GG + g];
        float w3 = wT[(i + 3)*GG + g];
        #pragma unroll
        for (int j = 0; j < 8; j++)
            acc[j] += xs[j][i]*w0 + xs[j][i+1]*w1 + xs[j][i+2]*w2 + xs[j][i+3]*w3;
    }
    #pragma unroll
    for (int j = 0; j < 8; j++) pre[((sb + j)*BB + b)*GG + g] = acc[j];
}

// ---------------- LSTM scan: 4-CTA cluster per dir, Whh in registers ----------------
// Epilogue threads push their own h float to all 3 peers immediately (contiguous
// per-warp stores), then one counted arrive per warp per peer (mbar count 6).
// pre is prefetched one step ahead.
__global__ void __launch_bounds__(256, 1) __cluster_dims__(4, 1, 1)
k_scan4(const float* __restrict__ preFp, const float* __restrict__ preBp,
        const float* __restrict__ whFp, const float* __restrict__ whBp,
        float* __restrict__ hout) {
    int dir  = blockIdx.x >> 2;
    int rank = blockIdx.x & 3;
    const float* pre = dir ? preBp : preFp;
    const u64*   W   = (const u64*)(dir ? whBp : whFp);   // [512 rows][64 u64]
    int t  = threadIdx.x;
    int tb = t >> 7;
    int g  = (t >> 5) & 3;
    int hl = t & 31;
    int row = g*HH + rank*32 + hl;

    __shared__ __align__(16) float hsf[2][2][HH];  // [buf][batch][k]
    __shared__ float gs[2][4][32];                 // [batch][gate][local unit]
    __shared__ __align__(8) u64 mbar;

    // 64 weight pairs, chunked so chunk 0 = this CTA's local quarter of k
    u64 w[64];
    #pragma unroll
    for (int c = 0; c < 4; c++) {
        int qb = 16 * ((rank + c) & 3);
        #pragma unroll
        for (int j = 0; j < 16; j++) w[c*16 + j] = W[row*64 + qb + j];
    }

    for (int i = t; i < 2*2*HH; i += 256) ((float*)hsf)[i] = 0.f;
    unsigned mb = smem_u32(&mbar);
    if (t == 0) asm volatile("mbarrier.init.shared.b64 [%0], 6;" :: "r"(mb) : "memory");
    __syncthreads();
    asm volatile("barrier.cluster.arrive.aligned;" ::: "memory");
    asm volatile("barrier.cluster.wait.aligned;"   ::: "memory");

    // peer addresses (all threads compute; used by epilogue warps)
    unsigned lbase = smem_u32(&hsf[0][0][0]);
    unsigned rmbp[3], rbp[3];
    #pragma unroll
    for (int pi = 0; pi < 3; pi++) {
        int pr = (rank + 1 + pi) & 3;
        asm("mapa.shared::cluster.u32 %0, %1, %2;" : "=r"(rmbp[pi]) : "r"(mb),    "r"(pr));
        asm("mapa.shared::cluster.u32 %0, %1, %2;" : "=r"(rbp[pi])  : "r"(lbase), "r"(pr));
    }

    int etb = t >> 5, eh = t & 31;     // epilogue mapping (t < 64)
    float cst = 0.f;
    int s0 = dir ? (SS - 1) : 0;
    float pcur = __ldg(&pre[(s0*BB + tb)*GG + row]);

    for (int s_ = 0; s_ < SS; s_++) {
        int s = dir ? (SS - 1 - s_) : s_;
        // prefetch next step's pre
        float pnext = 0.f;
        if (s_ + 1 < SS) {
            int sn = dir ? (SS - 2 - s_) : (s_ + 1);
            pnext = __ldg(&pre[(sn*BB + tb)*GG + row]);
        }
        int rb = (s_ + 1) & 1;
        int wb = s_ & 1;
        const u64* h2 = (const u64*)hsf[rb][tb];
        u64 a0 = 0ull, a1 = 0ull, a2 = 0ull, a3 = 0ull;
        {   // local quarter (chunk 0) — ordered by __syncthreads
            const u64* hq = h2 + 16*rank;
            #pragma unroll
            for (int j = 0; j < 16; j += 2) {
                ulonglong2 x = *(const ulonglong2*)(hq + j);
                fma2(a0, w[j], x.x);  fma2(a1, w[j + 1], x.y);
            }
        }
        if (s_ > 0) mbar_wait(mb, (s_ - 1) & 1);   // all peers' quarters arrived
        #pragma unroll
        for (int c = 1; c < 4; c++) {
            const u64* hq = h2 + 16*((rank + c) & 3);
            #pragma unroll
            for (int j = 0; j < 16; j += 4) {
                ulonglong2 x0 = *(const ulonglong2*)(hq + j);
                ulonglong2 x1 = *(const ulonglong2*)(hq + j + 2);
                fma2(a0, w[c*16 + j],     x0.x);  fma2(a1, w[c*16 + j + 1], x0.y);
                fma2(a2, w[c*16 + j + 2], x1.x);  fma2(a3, w[c*16 + j + 3], x1.y);
            }
        }
        float2 fa = u2f(a0), fb = u2f(a1), fc = u2f(a2), fd = u2f(a3);
        gs[tb][g][hl] = ((fa.x + fa.y) + (fb.x + fb.y)) + ((fc.x + fc.y) + (fd.x + fd.y)) + pcur;
        pcur = pnext;
        __syncthreads();                           // gates ready; reads of rb done
        if (t < 64) {
            float ig = fsig(gs[etb][0][eh]);
            float fg = fsig(gs[etb][1][eh]);
            float gg = ftanh(gs[etb][2][eh]);
            float og = fsig(gs[etb][3][eh]);
            cst = fg*cst + ig*gg;
            float hv = og * ftanh(cst);
            hsf[wb][etb][rank*32 + eh] = hv;
            unsigned off = (unsigned)(((wb*2 + etb)*HH + rank*32 + eh) * 4);
            asm volatile("st.shared::cluster.f32 [%0], %1;" :: "r"(rbp[0] + off), "f"(hv) : "memory");
            asm volatile("st.shared::cluster.f32 [%0], %1;" :: "r"(rbp[1] + off), "f"(hv) : "memory");
            asm volatile("st.shared::cluster.f32 [%0], %1;" :: "r"(rbp[2] + off), "f"(hv) : "memory");
            __syncwarp();
            if (eh < 3) {   // one arrive per warp per peer; syncwarp gives HB for warp's stores
                asm volatile("mbarrier.arrive.release.cluster.shared::cluster.b64 _, [%0];"
                             :: "r"(rmbp[eh]) : "memory");
            }
            hout[(etb*SS + s)*FF + dir*HH + rank*32 + eh] = hv;
        }
        __syncthreads();                           // local quarter of wb visible to CTA
    }
    asm volatile("barrier.cluster.arrive.aligned;" ::: "memory");
    asm volatile("barrier.cluster.wait.aligned;"   ::: "memory");
}

// ---------------- cls / bin MLPs ----------------
__global__ void k_clsbin(const float* __restrict__ rnn,
    const float* ac0, const float* __restrict__ wc1, const float* __restrict__ bc1,
    const float* ac1, const float* __restrict__ wc2, const float* __restrict__ bc2,
    const float* ab0, const float* __restrict__ wb1, const float* __restrict__ bb1,
    const float* ab1, const float* __restrict__ wb2, const float* __restrict__ bb2,
    float* __restrict__ out) {
    int s = blockIdx.x, b = blockIdx.y, t = threadIdx.x; // blockDim = 192
    __shared__ float xc[FF], xb[FF], hc[80], hb[80];
    float a0c = *ac0, a0b = *ab0;
    for (int k = t; k < FF; k += 192) {
        float v = rnn[(b*SS + s)*FF + k];
        xc[k] = v >= 0.f ? v : a0c*v;
        xb[k] = v >= 0.f ? v : a0b*v;
    }
    __syncthreads();
    if (t < 80) {
        float acc = bc1[t];
        const float* w = wc1 + t*FF;
        #pragma unroll 4
        for (int k = 0; k < FF; k++) acc += xc[k]*w[k];
        float a1 = *ac1;
        hc[t] = acc >= 0.f ? acc : a1*acc;
    } else if (t < 160) {
        int g = t - 80;
        float acc = bb1[g];
        const float* w = wb1 + g*FF;
        #pragma unroll 4
        for (int k = 0; k < FF; k++) acc += xb[k]*w[k];
        float a1 = *ab1;
        hb[g] = acc >= 0.f ? acc : a1*acc;
    }
    __syncthreads();
    if (t < NCC) {
        float acc = bc2[t];
        const float* w = wc2 + t*80;
        #pragma unroll 4
        for (int k = 0; k < 80; k++) acc += hc[k]*w[k];
        out[(b*SS + s)*NCC + t] = acc;
    } else if (t < NCC + 2) {
        int o = t - NCC;
        float acc = bb2[o];
        const float* w = wb2 + o*80;
        #pragma unroll 4
        for (int k = 0; k < 80; k++) acc += hb[k]*w[k];
        out[20480 + (b*SS + s)*2 + o] = acc;
    }
}

// ---------------- cumsum ----------------
__global__ void k_cum(const float* __restrict__ rnn) {
    int b = blockIdx.x, k = threadIdx.x;
    float run = 0.f;
    for (int t0 = 0; t0 < SS; t0 += 8) {
        float v[8];
        #pragma unroll
        for (int j = 0; j < 8; j++) v[j] = rnn[(b*SS + t0 + j)*FF + k];
        #pragma unroll
        for (int j = 0; j < 8; j++) { run += v[j]; g_cum[(b*SS + t0 + j)*FF + k] = run; }
    }
}

// ---------------- Pd / Pe ----------------
__global__ void k_pdpe(const float* __restrict__ rnn, const float* as0, const float* __restrict__ bs1) {
    int s = blockIdx.x, b = blockIdx.y, t = threadIdx.x; // blockDim = 128
    __shared__ __align__(16) float xr[FF];
    float a0 = *as0;
    {
        float v0 = rnn[(b*SS + s)*FF + 2*t];
        float v1 = rnn[(b*SS + s)*FF + 2*t + 1];
        xr[2*t]     = v0 >= 0.f ? v0 : a0*v0;
        xr[2*t + 1] = v1 >= 0.f ? v1 : a0*v1;
    }
    __syncthreads();
    const u64* xp = (const u64*)xr;
    if (t < HID) {
        u64 d0 = 0ull, d1 = 0ull, e0 = 0ull, e1 = 0ull;
        #pragma unroll 8
        for (int k2 = 0; k2 < 128; k2 += 2) {
            fma2(d0, g_wsP[1][(k2    )*128 + t], xp[k2    ]);
            fma2(d1, g_wsP[1][(k2 + 1)*128 + t], xp[k2 + 1]);
            fma2(e0, g_wsP[2][(k2    )*128 + t], xp[k2    ]);
            fma2(e1, g_wsP[2][(k2 + 1)*128 + t], xp[k2 + 1]);
        }
        float2 fd0 = u2f(d0), fd1 = u2f(d1), fe0 = u2f(e0), fe1 = u2f(e1);
        g_Pd[(b*SS + s)*HID + t] = fd0.x + fd0.y + fd1.x + fd1.y;
        g_Pe[(b*SS + s)*HID + t] = fe0.x + fe0.y + fe1.x + fe1.y + bs1[t];
    }
}

// ---------------- banded score MLP, register-blocked 16 windows ----------------
__global__ void k_scores(const float* as0, const float* as1,
                         const float* __restrict__ ws2, const float* bs2) {
    int i = blockIdx.x, b = blockIdx.y, t = threadIdx.x; // blockDim = 128
    if (i == 0) return;
    __shared__ __align__(16) float cdf[16][FF];
    __shared__ float sv[16][104];
    const u64 (*cd)[128] = (const u64 (*)[128])cdf;
    float a0 = *as0, a1 = *as1, b2 = *bs2;
    u64 civ = ((const u64*)(g_cum + (b*SS + i)*FF))[t];
    float2 ci = u2f(civ);
    float pei = (t < HID) ? g_Pe[(b*SS + i)*HID + t] : 0.f;
    float w2  = (t < HID) ? ws2[t] : 0.f;
    int wid = t >> 5, lane = t & 31;

    for (int gq = 0; gq < 4; gq++) {
        // build 16 cdiff columns
        #pragma unroll 4
        for (int p = 0; p < 16; p++) {
            int j = i - WW + gq*16 + p;
            float c0 = 0.f, c1 = 0.f;
            if (j >= 0) {
                float2 cj = u2f(((const u64*)(g_cum + (b*SS + j)*FF))[t]);
                c0 = ci.x - cj.x;  c1 = ci.y - cj.y;
                c0 = c0 >= 0.f ? c0 : a0*c0;
                c1 = c1 >= 0.f ? c1 : a0*c1;
            }
            ((u64*)cdf[p])[t] = f2u(c0, c1);
        }
        __syncthreads();
        if (t < HID) {
            u64 acc[16];
            #pragma unroll
            for (int p = 0; p < 16; p++) acc[p] = 0ull;
            const u64* wrow = g_wsP[0] + t;
            #pragma unroll 2
            for (int k2 = 0; k2 < 128; k2++) {
                u64 wv = __ldg(wrow + k2*128);
                #pragma unroll
                for (int p = 0; p < 16; p++) fma2(acc[p], wv, cd[p][k2]);
            }
            #pragma unroll
            for (int p = 0; p < 16; p++) {
                int j = i - WW + gq*16 + p;
                float2 f = u2f(acc[p]);
                float pd = (j >= 0) ? g_Pd[(b*SS + j)*HID + t] : 0.f;
                float hid = f.x + f.y + pd + pei;
                float ph  = hid >= 0.f ? hid : a1*hid;
                sv[p][t] = ph * w2;
            }
        }
        __syncthreads();
        // reduce: warp wid handles p = wid + 4q
        #pragma unroll
        for (int q = 0; q < 4; q++) {
            int p = wid + q*4;
            float v = sv[p][lane] + sv[p][lane + 32] + sv[p][lane + 64]
                    + (lane < 4 ? sv[p][lane + 96] : 0.f);
            for (int off = 16; off; off >>= 1) v += __shfl_down_sync(0xffffffffu, v, off);
            if (lane == 0) {
                int w = gq*16 + p;
                int j = i - WW + w;
                g_sband[(b*SS + i)*WW + w] = (j >= 0) ? v + b2 : -1000000000.0f;
            }
        }
        __syncthreads();
    }
}

// ---------------- DP + backtrack ----------------
__global__ void k_dp(const int* __restrict__ lengths, float* __restrict__ out) {
    __shared__ float best[BB][SS];
    __shared__ int   bp[BB][SS];
    int t = threadIdx.x;          // blockDim = 64
    int b = t >> 5, lane = t & 31;
    for (int idx = t; idx < BB*SS; idx += 64) best[idx >> 8][idx & 255] = 0.f;
    for (int idx = t; idx < BB*SS; idx += 64) out[21504 + idx] = 0.f;
    if (t < BB) bp[t][0] = 0;
    __syncthreads();
    for (int i = 1; i < SS; i++) {
        int w1 = lane, w2 = lane + 32;
        int j1 = i - WW + w1, j2 = i - WW + w2;
        float c1 = (j1 >= 0) ? best[b][j1] + g_sband[(b*SS + i)*WW + w1] : -1000000000.0f;
        float c2 = (j2 >= 0) ? best[b][j2] + g_sband[(b*SS + i)*WW + w2] : -1000000000.0f;
        float v; int jj;
        if (c2 > c1) { v = c2; jj = j2; } else { v = c1; jj = j1; }
        for (int off = 16; off; off >>= 1) {
            float ov = __shfl_down_sync(0xffffffffu, v,  off);
            int   oj = __shfl_down_sync(0xffffffffu, jj, off);
            if (ov > v || (ov == v && oj < jj)) { v = ov; jj = oj; }
        }
        if (lane == 0) { best[b][i] = v; bp[b][i] = jj; }
        __syncwarp();
    }
    __syncthreads();
    if (t < BB) {
        int cur = lengths[t] - 1;
        if (cur < 0) cur = 0;
        float acc = 0.f;
        while (true) {
            out[21504 + t*SS + cur] = 1.f;
            if (cur == 0) break;
            int prev = bp[t][cur];
            acc += g_sband[(t*SS + cur)*WW + (prev - (cur - WW))];
            cur = prev;
        }
        out[22016 + t] = acc;
    }
}

// ---------------- launch ----------------
extern "C" void kernel_launch(void* const* d_in, const int* in_sizes, int n_in,
                              void* d_out, int out_size) {
    (void)in_sizes; (void)n_in; (void)out_size;
    const float* x        = (const float*)d_in[0];
    const int*   lengths  = (const int*)  d_in[1];
    const float* wih[4]   = {(const float*)d_in[2], (const float*)d_in[5],
                             (const float*)d_in[8], (const float*)d_in[11]};
    const float* whh[4]   = {(const float*)d_in[3], (const float*)d_in[6],
                             (const float*)d_in[9], (const float*)d_in[12]};
    const float* bl[4]    = {(const float*)d_in[4], (const float*)d_in[7],
                             (const float*)d_in[10], (const float*)d_in[13]};
    const float* a_s0 = (const float*)d_in[14];
    const float* w_s1 = (const float*)d_in[15];
    const float* b_s1 = (const float*)d_in[16];
    const float* a_s1 = (const float*)d_in[17];
    const float* w_s2 = (const float*)d_in[18];
    const float* b_s2 = (const float*)d_in[19];
    const float* a_c0 = (const float*)d_in[20];
    const float* w_c1 = (const float*)d_in[21];
    const float* b_c1 = (const float*)d_in[22];
    const float* a_c1 = (const float*)d_in[23];
    const float* w_c2 = (const float*)d_in[24];
    const float* b_c2 = (const float*)d_in[25];
    const float* a_b0 = (const float*)d_in[26];
    const float* w_b1 = (const float*)d_in[27];
    const float* b_b1 = (const float*)d_in[28];
    const float* a_b1 = (const float*)d_in[29];
    const float* w_b2 = (const float*)d_in[30];
    const float* b_b2 = (const float*)d_in[31];
    float* out = (float*)d_out;

    float *wihT, *preF, *preB, *h0, *rnn;
    cudaGetSymbolAddress((void**)&wihT, g_wihT);
    cudaGetSymbolAddress((void**)&preF, g_preF);
    cudaGetSymbolAddress((void**)&preB, g_preB);
    cudaGetSymbolAddress((void**)&h0,   g_h0);
    cudaGetSymbolAddress((void**)&rnn,  g_rnn);

    k_transpose_all<<<dim3(FF, 4), GG>>>(wih[0], wih[1], wih[2], wih[3], wihT);
    k_pack_ws1<<<dim3(128, 3), 128>>>(w_s1);

    dim3 gpre8(SS/8, BB, 2);
    // layer 0
    k_pre8m<<<gpre8, GG>>>(x, wihT, bl[0], bl[1], preF, preB, INP);
    k_scan4<<<8, 256>>>(preF, preB, whh[0], whh[1], h0);
    // layer 1
    k_pre8m<<<gpre8, GG>>>(h0, wihT + 2*FF*GG, bl[2], bl[3], preF, preB, FF);
    k_scan4<<<8, 256>>>(preF, preB, whh[2], whh[3], rnn);

    k_clsbin<<<dim3(SS, BB), 192>>>(rnn, a_c0, w_c1, b_c1, a_c1, w_c2, b_c2,
                                         a_b0, w_b1, b_b1, a_b1, w_b2, b_b2, out);
    k_cum<<<BB, FF>>>(rnn);
    k_pdpe<<<dim3(SS, BB), 128>>>(rnn, a_s0, b_s1);
    k_scores<<<dim3(SS, BB), 128>>>(a_s0, a_s1, w_s2, b_s2);
    k_dp<<<1, 64>>>(lengths, out);
}

// round 11
// speedup vs baseline: 3.4432x; 1.1429x over previous
#include <cuda_runtime.h>
#include <cuda_bf16.h>

#define BB   2
#define SS   256
#define INP  80
#define HH   128
#define GG   512
#define FF   256
#define NCC  40
#define WW   64
#define HID  100

typedef unsigned long long u64;

__device__ float g_wihT [4][FF*GG];
__device__ u64   g_wsP  [3][128*128];
__device__ float g_preF [SS*BB*GG];
__device__ float g_preB [SS*BB*GG];
__device__ float g_h0   [BB*SS*FF];
__device__ float g_rnn  [BB*SS*FF];
__device__ float g_cum  [BB*SS*FF];
__device__ float g_Pd   [BB*SS*HID];
__device__ float g_Pe   [BB*SS*HID];
__device__ float g_sband[BB*SS*WW];

__device__ __forceinline__ void fma2(u64 &d, u64 a, u64 b) {
    asm("fma.rn.f32x2 %0, %1, %2, %0;" : "+l"(d) : "l"(a), "l"(b));
}
__device__ __forceinline__ float2 u2f(u64 v) {
    float2 f; asm("mov.b64 {%0,%1}, %2;" : "=f"(f.x), "=f"(f.y) : "l"(v)); return f;
}
__device__ __forceinline__ u64 f2u(float x, float y) {
    u64 v; asm("mov.b64 %0, {%1,%2};" : "=l"(v) : "f"(x), "f"(y)); return v;
}
__device__ __forceinline__ unsigned smem_u32(const void* p) {
    unsigned a;
    asm("{ .reg .u64 t; cvta.to.shared.u64 t, %1; cvt.u32.u64 %0, t; }" : "=r"(a) : "l"(p));
    return a;
}
__device__ __forceinline__ float fsig(float x) { return __fdividef(1.f, 1.f + __expf(-x)); }
__device__ __forceinline__ float ftanh(float x) {
    float ax = fabsf(x);
    float e  = __expf(-2.f * ax);
    float r  = __fdividef(1.f - e, 1.f + e);
    return x < 0.f ? -r : r;
}
__device__ __forceinline__ float tanha(float x) {
    float r; asm("tanh.approx.f32 %0, %1;" : "=f"(r) : "f"(x)); return r;
}
__device__ __forceinline__ void mbar_wait(unsigned mb, unsigned par) {
    unsigned done = 0;
    do {
        asm volatile("{\n\t.reg .pred p;\n\t"
            "mbarrier.try_wait.parity.acquire.cluster.shared::cta.b64 p, [%1], %2, 0x989680;\n\t"
            "selp.b32 %0,1,0,p;\n\t}" : "=r"(done) : "r"(mb), "r"(par) : "memory");
    } while (!done);
}

// ---------------- prep ----------------
__global__ void k_transpose_all(const float* __restrict__ w0, const float* __restrict__ w1,
                                const float* __restrict__ w2, const float* __restrict__ w3,
                                float* __restrict__ wT) {
    int m = blockIdx.y, c = blockIdx.x, g = threadIdx.x;
    const float* w = (m == 0) ? w0 : (m == 1) ? w1 : (m == 2) ? w2 : w3;
    int cols = (m < 2) ? INP : FF;
    if (c < cols) wT[m*FF*GG + c*GG + g] = w[g*cols + c];
}
__global__ void k_pack_ws1(const float* __restrict__ w) {
    int k2 = blockIdx.x, p = blockIdx.y, h = threadIdx.x;
    u64 v = 0ull;
    if (h < HID) v = f2u(w[h*768 + p*256 + 2*k2], w[h*768 + p*256 + 2*k2 + 1]);
    g_wsP[p][k2*128 + h] = v;
}

// ---------------- pre = x @ Wih^T + b, 8 timesteps per block, F+B merged ----------------
__global__ void k_pre8m(const float* __restrict__ xin, const float* __restrict__ wTbase,
                        const float* __restrict__ bF, const float* __restrict__ bB,
                        float* __restrict__ preFo, float* __restrict__ preBo, int Din) {
    __shared__ float xs[8][FF];
    int z = blockIdx.z;
    const float* wT   = wTbase + z*FF*GG;
    const float* bias = z ? bB : bF;
    float* pre        = z ? preBo : preFo;
    int sb = blockIdx.x * 8, b = blockIdx.y, g = threadIdx.x;
    for (int idx = g; idx < 8*Din; idx += GG) {
        int j = idx / Din, k = idx - j*Din;
        xs[j][k] = xin[(b*SS + sb + j)*Din + k];
    }
    __syncthreads();
    float bi = bias[g];
    float acc[8];
    #pragma unroll
    for (int j = 0; j < 8; j++) acc[j] = bi;
    for (int i = 0; i < Din; i += 4) {
        float w0 = wT[(i    )*GG + g];
        float w1 = wT[(i + 1)*GG + g];
        float w2 = wT[(i + 2)*GG + g];
        float w3 = wT[(i + 3)*GG + g];
        #pragma unroll
        for (int j = 0; j < 8; j++)
            acc[j] += xs[j][i]*w0 + xs[j][i+1]*w1 + xs[j][i+2]*w2 + xs[j][i+3]*w3;
    }
    #pragma unroll
    for (int j = 0; j < 8; j++) pre[((sb + j)*BB + b)*GG + g] = acc[j];
}

// ---------------- LSTM scan: 8-CTA cluster per dir ----------------
// Cluster rank r: q = r&3 (h-quarter), bt = r>>2 (batch). 128 threads/CTA,
// one 128-long dot per thread (64 FFMA2). Exchange ring is the 4 same-batch
// CTAs: epilogue warp stores its 32 fresh h floats to 3 peers, lanes 0-2 do
// one counted release-arrive each (mbar count 3). Gates use HW tanh.approx.
__global__ void __launch_bounds__(128, 1) __cluster_dims__(8, 1, 1)
k_scan8(const float* __restrict__ preFp, const float* __restrict__ preBp,
        const float* __restrict__ whFp, const float* __restrict__ whBp,
        float* __restrict__ hout) {
    int dir  = blockIdx.x >> 3;
    int r    = blockIdx.x & 7;
    int q    = r & 3;
    int bt   = r >> 2;
    const float* pre = dir ? preBp : preFp;
    const u64*   W   = (const u64*)(dir ? whBp : whFp);   // [512 rows][64 u64]
    int t  = threadIdx.x;          // 128
    int g  = t >> 5;
    int hl = t & 31;
    int row = g*HH + q*32 + hl;

    __shared__ __align__(16) float hsf[2][HH];     // [buf][k] for this batch
    __shared__ float gs[4][32];                    // [gate][local unit]
    __shared__ __align__(8) u64 mbar;

    // 64 weight pairs, chunk 0 = this CTA's local quarter of k
    u64 w[64];
    #pragma unroll
    for (int c = 0; c < 4; c++) {
        int qb = 16 * ((q + c) & 3);
        #pragma unroll
        for (int j = 0; j < 16; j++) w[c*16 + j] = W[row*64 + qb + j];
    }

    for (int i = t; i < 2*HH; i += 128) ((float*)hsf)[i] = 0.f;
    unsigned mb = smem_u32(&mbar);
    if (t == 0) asm volatile("mbarrier.init.shared.b64 [%0], 3;" :: "r"(mb) : "memory");
    __syncthreads();
    asm volatile("barrier.cluster.arrive.aligned;" ::: "memory");
    asm volatile("barrier.cluster.wait.aligned;"   ::: "memory");

    unsigned lbase = smem_u32(&hsf[0][0]);
    unsigned rmbp[3], rbp[3];
    #pragma unroll
    for (int pi = 0; pi < 3; pi++) {
        int pr = (bt << 2) | ((q + 1 + pi) & 3);   // same-batch peer
        asm("mapa.shared::cluster.u32 %0, %1, %2;" : "=r"(rmbp[pi]) : "r"(mb),    "r"(pr));
        asm("mapa.shared::cluster.u32 %0, %1, %2;" : "=r"(rbp[pi])  : "r"(lbase), "r"(pr));
    }

    int eh = t & 31;               // epilogue lane (t < 32)
    float cst = 0.f;
    int s0 = dir ? (SS - 1) : 0;
    float pcur = __ldg(&pre[(s0*BB + bt)*GG + row]);

    for (int s_ = 0; s_ < SS; s_++) {
        int s  = dir ? (SS - 1 - s_) : s_;
        int sn = dir ? (s - 1 < 0 ? 0 : s - 1) : (s + 1 > SS - 1 ? SS - 1 : s + 1);
        float pnext = __ldg(&pre[(sn*BB + bt)*GG + row]);
        int rb = (s_ + 1) & 1;
        int wb = s_ & 1;
        const u64* h2 = (const u64*)hsf[rb];
        u64 a0 = 0ull, a1 = 0ull, a2 = 0ull, a3 = 0ull;
        {   // local quarter — ordered by __syncthreads
            const u64* hq = h2 + 16*q;
            #pragma unroll
            for (int j = 0; j < 16; j += 2) {
                ulonglong2 x = *(const ulonglong2*)(hq + j);
                fma2(a0, w[j], x.x);  fma2(a1, w[j + 1], x.y);
            }
        }
        if (s_ > 0) mbar_wait(mb, (s_ - 1) & 1);   // peers' quarters arrived
        #pragma unroll
        for (int c = 1; c < 4; c++) {
            const u64* hq = h2 + 16*((q + c) & 3);
            #pragma unroll
            for (int j = 0; j < 16; j += 4) {
                ulonglong2 x0 = *(const ulonglong2*)(hq + j);
                ulonglong2 x1 = *(const ulonglong2*)(hq + j + 2);
                fma2(a0, w[c*16 + j],     x0.x);  fma2(a1, w[c*16 + j + 1], x0.y);
                fma2(a2, w[c*16 + j + 2], x1.x);  fma2(a3, w[c*16 + j + 3], x1.y);
            }
        }
        float2 fa = u2f(a0), fb = u2f(a1), fc = u2f(a2), fd = u2f(a3);
        gs[g][hl] = ((fa.x + fa.y) + (fb.x + fb.y)) + ((fc.x + fc.y) + (fd.x + fd.y)) + pcur;
        pcur = pnext;
        __syncthreads();                           // gates ready; reads of rb done
        if (t < 32) {
            float ig = 0.5f*tanha(0.5f*gs[0][eh]) + 0.5f;
            float fg = 0.5f*tanha(0.5f*gs[1][eh]) + 0.5f;
            float gg = tanha(gs[2][eh]);
            float og = 0.5f*tanha(0.5f*gs[3][eh]) + 0.5f;
            cst = fg*cst + ig*gg;
            float hv = og * tanha(cst);
            hsf[wb][q*32 + eh] = hv;
            unsigned off = (unsigned)((wb*HH + q*32 + eh) * 4);
            asm volatile("st.shared::cluster.f32 [%0], %1;" :: "r"(rbp[0] + off), "f"(hv) : "memory");
            asm volatile("st.shared::cluster.f32 [%0], %1;" :: "r"(rbp[1] + off), "f"(hv) : "memory");
            asm volatile("st.shared::cluster.f32 [%0], %1;" :: "r"(rbp[2] + off), "f"(hv) : "memory");
            __syncwarp();
            if (eh < 3) {
                asm volatile("mbarrier.arrive.release.cluster.shared::cluster.b64 _, [%0];"
                             :: "r"(rmbp[eh]) : "memory");
            }
            hout[(bt*SS + s)*FF + dir*HH + q*32 + eh] = hv;
        }
        __syncthreads();                           // local quarter of wb visible to CTA
    }
    asm volatile("barrier.cluster.arrive.aligned;" ::: "memory");
    asm volatile("barrier.cluster.wait.aligned;"   ::: "memory");
}

// ---------------- cls / bin MLPs ----------------
__global__ void k_clsbin(const float* __restrict__ rnn,
    const float* ac0, const float* __restrict__ wc1, const float* __restrict__ bc1,
    const float* ac1, const float* __restrict__ wc2, const float* __restrict__ bc2,
    const float* ab0, const float* __restrict__ wb1, const float* __restrict__ bb1,
    const float* ab1, const float* __restrict__ wb2, const float* __restrict__ bb2,
    float* __restrict__ out) {
    int s = blockIdx.x, b = blockIdx.y, t = threadIdx.x; // blockDim = 192
    __shared__ float xc[FF], xb[FF], hc[80], hb[80];
    float a0c = *ac0, a0b = *ab0;
    for (int k = t; k < FF; k += 192) {
        float v = rnn[(b*SS + s)*FF + k];
        xc[k] = v >= 0.f ? v : a0c*v;
        xb[k] = v >= 0.f ? v : a0b*v;
    }
    __syncthreads();
    if (t < 80) {
        float acc = bc1[t];
        const float* w = wc1 + t*FF;
        #pragma unroll 4
        for (int k = 0; k < FF; k++) acc += xc[k]*w[k];
        float a1 = *ac1;
        hc[t] = acc >= 0.f ? acc : a1*acc;
    } else if (t < 160) {
        int g = t - 80;
        float acc = bb1[g];
        const float* w = wb1 + g*FF;
        #pragma unroll 4
        for (int k = 0; k < FF; k++) acc += xb[k]*w[k];
        float a1 = *ab1;
        hb[g] = acc >= 0.f ? acc : a1*acc;
    }
    __syncthreads();
    if (t < NCC) {
        float acc = bc2[t];
        const float* w = wc2 + t*80;
        #pragma unroll 4
        for (int k = 0; k < 80; k++) acc += hc[k]*w[k];
        out[(b*SS + s)*NCC + t] = acc;
    } else if (t < NCC + 2) {
        int o = t - NCC;
        float acc = bb2[o];
        const float* w = wb2 + o*80;
        #pragma unroll 4
        for (int k = 0; k < 80; k++) acc += hb[k]*w[k];
        out[20480 + (b*SS + s)*2 + o] = acc;
    }
}

// ---------------- cumsum ----------------
__global__ void k_cum(const float* __restrict__ rnn) {
    int b = blockIdx.x, k = threadIdx.x;
    float run = 0.f;
    for (int t0 = 0; t0 < SS; t0 += 8) {
        float v[8];
        #pragma unroll
        for (int j = 0; j < 8; j++) v[j] = rnn[(b*SS + t0 + j)*FF + k];
        #pragma unroll
        for (int j = 0; j < 8; j++) { run += v[j]; g_cum[(b*SS + t0 + j)*FF + k] = run; }
    }
}

// ---------------- Pd / Pe ----------------
__global__ void k_pdpe(const float* __restrict__ rnn, const float* as0, const float* __restrict__ bs1) {
    int s = blockIdx.x, b = blockIdx.y, t = threadIdx.x; // blockDim = 128
    __shared__ __align__(16) float xr[FF];
    float a0 = *as0;
    {
        float v0 = rnn[(b*SS + s)*FF + 2*t];
        float v1 = rnn[(b*SS + s)*FF + 2*t + 1];
        xr[2*t]     = v0 >= 0.f ? v0 : a0*v0;
        xr[2*t + 1] = v1 >= 0.f ? v1 : a0*v1;
    }
    __syncthreads();
    const u64* xp = (const u64*)xr;
    if (t < HID) {
        u64 d0 = 0ull, d1 = 0ull, e0 = 0ull, e1 = 0ull;
        #pragma unroll 8
        for (int k2 = 0; k2 < 128; k2 += 2) {
            fma2(d0, g_wsP[1][(k2    )*128 + t], xp[k2    ]);
            fma2(d1, g_wsP[1][(k2 + 1)*128 + t], xp[k2 + 1]);
            fma2(e0, g_wsP[2][(k2    )*128 + t], xp[k2    ]);
            fma2(e1, g_wsP[2][(k2 + 1)*128 + t], xp[k2 + 1]);
        }
        float2 fd0 = u2f(d0), fd1 = u2f(d1), fe0 = u2f(e0), fe1 = u2f(e1);
        g_Pd[(b*SS + s)*HID + t] = fd0.x + fd0.y + fd1.x + fd1.y;
        g_Pe[(b*SS + s)*HID + t] = fe0.x + fe0.y + fe1.x + fe1.y + bs1[t];
    }
}

// ---------------- banded score MLP, register-blocked 16 windows ----------------
__global__ void k_scores(const float* as0, const float* as1,
                         const float* __restrict__ ws2, const float* bs2) {
    int i = blockIdx.x, b = blockIdx.y, t = threadIdx.x; // blockDim = 128
    if (i == 0) return;
    __shared__ __align__(16) float cdf[16][FF];
    __shared__ float sv[16][104];
    const u64 (*cd)[128] = (const u64 (*)[128])cdf;
    float a0 = *as0, a1 = *as1, b2 = *bs2;
    u64 civ = ((const u64*)(g_cum + (b*SS + i)*FF))[t];
    float2 ci = u2f(civ);
    float pei = (t < HID) ? g_Pe[(b*SS + i)*HID + t] : 0.f;
    float w2  = (t < HID) ? ws2[t] : 0.f;
    int wid = t >> 5, lane = t & 31;

    for (int gq = 0; gq < 4; gq++) {
        #pragma unroll 4
        for (int p = 0; p < 16; p++) {
            int j = i - WW + gq*16 + p;
            float c0 = 0.f, c1 = 0.f;
            if (j >= 0) {
                float2 cj = u2f(((const u64*)(g_cum + (b*SS + j)*FF))[t]);
                c0 = ci.x - cj.x;  c1 = ci.y - cj.y;
                c0 = c0 >= 0.f ? c0 : a0*c0;
                c1 = c1 >= 0.f ? c1 : a0*c1;
            }
            ((u64*)cdf[p])[t] = f2u(c0, c1);
        }
        __syncthreads();
        if (t < HID) {
            u64 acc[16];
            #pragma unroll
            for (int p = 0; p < 16; p++) acc[p] = 0ull;
            const u64* wrow = g_wsP[0] + t;
            #pragma unroll 2
            for (int k2 = 0; k2 < 128; k2++) {
                u64 wv = __ldg(wrow + k2*128);
                #pragma unroll
                for (int p = 0; p < 16; p++) fma2(acc[p], wv, cd[p][k2]);
            }
            #pragma unroll
            for (int p = 0; p < 16; p++) {
                int j = i - WW + gq*16 + p;
                float2 f = u2f(acc[p]);
                float pd = (j >= 0) ? g_Pd[(b*SS + j)*HID + t] : 0.f;
                float hid = f.x + f.y + pd + pei;
                float ph  = hid >= 0.f ? hid : a1*hid;
                sv[p][t] = ph * w2;
            }
        }
        __syncthreads();
        #pragma unroll
        for (int q = 0; q < 4; q++) {
            int p = wid + q*4;
            float v = sv[p][lane] + sv[p][lane + 32] + sv[p][lane + 64]
                    + (lane < 4 ? sv[p][lane + 96] : 0.f);
            for (int off = 16; off; off >>= 1) v += __shfl_down_sync(0xffffffffu, v, off);
            if (lane == 0) {
                int w = gq*16 + p;
                int j = i - WW + w;
                g_sband[(b*SS + i)*WW + w] = (j >= 0) ? v + b2 : -1000000000.0f;
            }
        }
        __syncthreads();
    }
}

// ---------------- DP + backtrack ----------------
__global__ void k_dp(const int* __restrict__ lengths, float* __restrict__ out) {
    __shared__ float best[BB][SS];
    __shared__ int   bp[BB][SS];
    int t = threadIdx.x;          // blockDim = 64
    int b = t >> 5, lane = t & 31;
    for (int idx = t; idx < BB*SS; idx += 64) best[idx >> 8][idx & 255] = 0.f;
    for (int idx = t; idx < BB*SS; idx += 64) out[21504 + idx] = 0.f;
    if (t < BB) bp[t][0] = 0;
    __syncthreads();
    for (int i = 1; i < SS; i++) {
        int w1 = lane, w2 = lane + 32;
        int j1 = i - WW + w1, j2 = i - WW + w2;
        float c1 = (j1 >= 0) ? best[b][j1] + g_sband[(b*SS + i)*WW + w1] : -1000000000.0f;
        float c2 = (j2 >= 0) ? best[b][j2] + g_sband[(b*SS + i)*WW + w2] : -1000000000.0f;
        float v; int jj;
        if (c2 > c1) { v = c2; jj = j2; } else { v = c1; jj = j1; }
        for (int off = 16; off; off >>= 1) {
            float ov = __shfl_down_sync(0xffffffffu, v,  off);
            int   oj = __shfl_down_sync(0xffffffffu, jj, off);
            if (ov > v || (ov == v && oj < jj)) { v = ov; jj = oj; }
        }
        if (lane == 0) { best[b][i] = v; bp[b][i] = jj; }
        __syncwarp();
    }
    __syncthreads();
    if (t < BB) {
        int cur = lengths[t] - 1;
        if (cur < 0) cur = 0;
        float acc = 0.f;
        while (true) {
            out[21504 + t*SS + cur] = 1.f;
            if (cur == 0) break;
            int prev = bp[t][cur];
            acc += g_sband[(t*SS + cur)*WW + (prev - (cur - WW))];
            cur = prev;
        }
        out[22016 + t] = acc;
    }
}

// ---------------- launch ----------------
extern "C" void kernel_launch(void* const* d_in, const int* in_sizes, int n_in,
                              void* d_out, int out_size) {
    (void)in_sizes; (void)n_in; (void)out_size;
    const float* x        = (const float*)d_in[0];
    const int*   lengths  = (const int*)  d_in[1];
    const float* wih[4]   = {(const float*)d_in[2], (const float*)d_in[5],
                             (const float*)d_in[8], (const float*)d_in[11]};
    const float* whh[4]   = {(const float*)d_in[3], (const float*)d_in[6],
                             (const float*)d_in[9], (const float*)d_in[12]};
    const float* bl[4]    = {(const float*)d_in[4], (const float*)d_in[7],
                             (const float*)d_in[10], (const float*)d_in[13]};
    const float* a_s0 = (const float*)d_in[14];
    const float* w_s1 = (const float*)d_in[15];
    const float* b_s1 = (const float*)d_in[16];
    const float* a_s1 = (const float*)d_in[17];
    const float* w_s2 = (const float*)d_in[18];
    const float* b_s2 = (const float*)d_in[19];
    const float* a_c0 = (const float*)d_in[20];
    const float* w_c1 = (const float*)d_in[21];
    const float* b_c1 = (const float*)d_in[22];
    const float* a_c1 = (const float*)d_in[23];
    const float* w_c2 = (const float*)d_in[24];
    const float* b_c2 = (const float*)d_in[25];
    const float* a_b0 = (const float*)d_in[26];
    const float* w_b1 = (const float*)d_in[27];
    const float* b_b1 = (const float*)d_in[28];
    const float* a_b1 = (const float*)d_in[29];
    const float* w_b2 = (const float*)d_in[30];
    const float* b_b2 = (const float*)d_in[31];
    float* out = (float*)d_out;

    float *wihT, *preF, *preB, *h0, *rnn;
    cudaGetSymbolAddress((void**)&wihT, g_wihT);
    cudaGetSymbolAddress((void**)&preF, g_preF);
    cudaGetSymbolAddress((void**)&preB, g_preB);
    cudaGetSymbolAddress((void**)&h0,   g_h0);
    cudaGetSymbolAddress((void**)&rnn,  g_rnn);

    k_transpose_all<<<dim3(FF, 4), GG>>>(wih[0], wih[1], wih[2], wih[3], wihT);
    k_pack_ws1<<<dim3(128, 3), 128>>>(w_s1);

    dim3 gpre8(SS/8, BB, 2);
    // layer 0
    k_pre8m<<<gpre8, GG>>>(x, wihT, bl[0], bl[1], preF, preB, INP);
    k_scan8<<<16, 128>>>(preF, preB, whh[0], whh[1], h0);
    // layer 1
    k_pre8m<<<gpre8, GG>>>(h0, wihT + 2*FF*GG, bl[2], bl[3], preF, preB, FF);
    k_scan8<<<16, 128>>>(preF, preB, whh[2], whh[3], rnn);

    k_clsbin<<<dim3(SS, BB), 192>>>(rnn, a_c0, w_c1, b_c1, a_c1, w_c2, b_c2,
                                         a_b0, w_b1, b_b1, a_b1, w_b2, b_b2, out);
    k_cum<<<BB, FF>>>(rnn);
    k_pdpe<<<dim3(SS, BB), 128>>>(rnn, a_s0, b_s1);
    k_scores<<<dim3(SS, BB), 128>>>(a_s0, a_s1, w_s2, b_s2);
    k_dp<<<1, 64>>>(lengths, out);
}

// round 12
// speedup vs baseline: 3.7600x; 1.0920x over previous
#include <cuda_runtime.h>
#include <cuda_bf16.h>

#define BB   2
#define SS   256
#define INP  80
#define HH   128
#define GG   512
#define FF   256
#define NCC  40
#define WW   64
#define HID  100

typedef unsigned long long u64;

__device__ float g_wihT [4][FF*GG];
__device__ u64   g_wsP  [3][128*128];
__device__ __align__(16) u64 g_wsPc[128*128];   // w_s1 c-part, [h][k2] contiguous
__device__ float g_preF [SS*BB*GG];
__device__ float g_preB [SS*BB*GG];
__device__ float g_h0   [BB*SS*FF];
__device__ float g_rnn  [BB*SS*FF];
__device__ float g_cum  [BB*SS*FF];
__device__ float g_Pd   [BB*SS*HID];
__device__ float g_Pe   [BB*SS*HID];
__device__ float g_sband[BB*SS*WW];

__device__ __forceinline__ void fma2(u64 &d, u64 a, u64 b) {
    asm("fma.rn.f32x2 %0, %1, %2, %0;" : "+l"(d) : "l"(a), "l"(b));
}
__device__ __forceinline__ float2 u2f(u64 v) {
    float2 f; asm("mov.b64 {%0,%1}, %2;" : "=f"(f.x), "=f"(f.y) : "l"(v)); return f;
}
__device__ __forceinline__ u64 f2u(float x, float y) {
    u64 v; asm("mov.b64 %0, {%1,%2};" : "=l"(v) : "f"(x), "f"(y)); return v;
}
__device__ __forceinline__ unsigned smem_u32(const void* p) {
    unsigned a;
    asm("{ .reg .u64 t; cvta.to.shared.u64 t, %1; cvt.u32.u64 %0, t; }" : "=r"(a) : "l"(p));
    return a;
}
__device__ __forceinline__ float tanha(float x) {
    float r; asm("tanh.approx.f32 %0, %1;" : "=f"(r) : "f"(x)); return r;
}
__device__ __forceinline__ unsigned orderable(float v) {
    unsigned u = __float_as_uint(v);
    return (u & 0x80000000u) ? ~u : (u | 0x80000000u);
}
__device__ __forceinline__ float unorder(unsigned u) {
    return (u & 0x80000000u) ? __uint_as_float(u & 0x7FFFFFFFu)
                             : __uint_as_float(~u);
}

// ---------------- prep ----------------
__global__ void k_transpose_all(const float* __restrict__ w0, const float* __restrict__ w1,
                                const float* __restrict__ w2, const float* __restrict__ w3,
                                float* __restrict__ wT) {
    int m = blockIdx.y, c = blockIdx.x, g = threadIdx.x;
    const float* w = (m == 0) ? w0 : (m == 1) ? w1 : (m == 2) ? w2 : w3;
    int cols = (m < 2) ? INP : FF;
    if (c < cols) wT[m*FF*GG + c*GG + g] = w[g*cols + c];
}
__global__ void k_pack_ws1(const float* __restrict__ w) {
    int k2 = blockIdx.x, p = blockIdx.y, h = threadIdx.x;
    u64 v = 0ull;
    if (h < HID) v = f2u(w[h*768 + p*256 + 2*k2], w[h*768 + p*256 + 2*k2 + 1]);
    g_wsP[p][k2*128 + h] = v;
    if (p == 0) g_wsPc[h*128 + k2] = v;
}

// ---------------- pre = x @ Wih^T + b, 8 timesteps per block, F+B merged ----------------
__global__ void k_pre8m(const float* __restrict__ xin, const float* __restrict__ wTbase,
                        const float* __restrict__ bF, const float* __restrict__ bB,
                        float* __restrict__ preFo, float* __restrict__ preBo, int Din) {
    __shared__ float xs[8][FF];
    int z = blockIdx.z;
    const float* wT   = wTbase + z*FF*GG;
    const float* bias = z ? bB : bF;
    float* pre        = z ? preBo : preFo;
    int sb = blockIdx.x * 8, b = blockIdx.y, g = threadIdx.x;
    for (int idx = g; idx < 8*Din; idx += GG) {
        int j = idx / Din, k = idx - j*Din;
        xs[j][k] = xin[(b*SS + sb + j)*Din + k];
    }
    __syncthreads();
    float bi = bias[g];
    float acc[8];
    #pragma unroll
    for (int j = 0; j < 8; j++) acc[j] = bi;
    for (int i = 0; i < Din; i += 4) {
        float w0 = wT[(i    )*GG + g];
        float w1 = wT[(i + 1)*GG + g];
        float w2 = wT[(i + 2)*GG + g];
        float w3 = wT[(i + 3)*GG + g];
        #pragma unroll
        for (int j = 0; j < 8; j++)
            acc[j] += xs[j][i]*w0 + xs[j][i+1]*w1 + xs[j][i+2]*w2 + xs[j][i+3]*w3;
    }
    #pragma unroll
    for (int j = 0; j < 8; j++) pre[((sb + j)*BB + b)*GG + g] = acc[j];
}

// ---------------- LSTM scan: 8-CTA cluster per dir, flag-based signaling ----------------
// Cluster rank r: q = r&3 (h-quarter), bt = r>>2 (batch). 128 threads/CTA.
// Producers push 32 h-floats + a monotonic step flag via st.release.cluster;
// consumers spin on local smem flags with ld.acquire.cluster (no mbarrier,
// no remote arrive, no TRYWAIT wake on the critical path).
__global__ void __launch_bounds__(128, 1) __cluster_dims__(8, 1, 1)
k_scan8(const float* __restrict__ preFp, const float* __restrict__ preBp,
        const float* __restrict__ whFp, const float* __restrict__ whBp,
        float* __restrict__ hout) {
    int dir  = blockIdx.x >> 3;
    int r    = blockIdx.x & 7;
    int q    = r & 3;
    int bt   = r >> 2;
    const float* pre = dir ? preBp : preFp;
    const u64*   W   = (const u64*)(dir ? whBp : whFp);   // [512 rows][64 u64]
    int t  = threadIdx.x;          // 128
    int g  = t >> 5;
    int hl = t & 31;
    int row = g*HH + q*32 + hl;

    __shared__ __align__(16) float hsf[2][HH];     // [buf][k] for this batch
    __shared__ float gs[4][32];                    // [gate][local unit]
    __shared__ unsigned flg[4];                    // per-producer step counters

    u64 w[64];
    #pragma unroll
    for (int c = 0; c < 4; c++) {
        int qb = 16 * ((q + c) & 3);
        #pragma unroll
        for (int j = 0; j < 16; j++) w[c*16 + j] = W[row*64 + qb + j];
    }

    for (int i = t; i < 2*HH; i += 128) ((float*)hsf)[i] = 0.f;
    if (t < 4) flg[t] = 0;
    __syncthreads();
    asm volatile("barrier.cluster.arrive.aligned;" ::: "memory");
    asm volatile("barrier.cluster.wait.aligned;"   ::: "memory");

    unsigned fbase = smem_u32(&flg[0]);
    unsigned lbase = smem_u32(&hsf[0][0]);
    unsigned rbp[3], rfl[3], lfl[3];
    #pragma unroll
    for (int pi = 0; pi < 3; pi++) {
        int pq = (q + 1 + pi) & 3;
        int pr = (bt << 2) | pq;                   // same-batch peer
        asm("mapa.shared::cluster.u32 %0, %1, %2;" : "=r"(rfl[pi]) : "r"(fbase), "r"(pr));
        asm("mapa.shared::cluster.u32 %0, %1, %2;" : "=r"(rbp[pi]) : "r"(lbase), "r"(pr));
        rfl[pi] += q * 4;                          // my slot at peer
        lfl[pi] = fbase + pq * 4;                  // peer's slot here
    }

    int eh = t & 31;               // epilogue lane (t < 32)
    float cst = 0.f;
    int s0 = dir ? (SS - 1) : 0;
    float pcur = __ldg(&pre[(s0*BB + bt)*GG + row]);

    for (int s_ = 0; s_ < SS; s_++) {
        int s  = dir ? (SS - 1 - s_) : s_;
        int sn = dir ? (s - 1 < 0 ? 0 : s - 1) : (s + 1 > SS - 1 ? SS - 1 : s + 1);
        float pnext = __ldg(&pre[(sn*BB + bt)*GG + row]);
        int rb = (s_ + 1) & 1;
        int wb = s_ & 1;
        const u64* h2 = (const u64*)hsf[rb];
        u64 a0 = 0ull, a1 = 0ull, a2 = 0ull, a3 = 0ull;
        {   // local quarter — ordered by __syncthreads
            const u64* hq = h2 + 16*q;
            #pragma unroll
            for (int j = 0; j < 16; j += 2) {
                ulonglong2 x = *(const ulonglong2*)(hq + j);
                fma2(a0, w[j], x.x);  fma2(a1, w[j + 1], x.y);
            }
        }
        if (s_ > 0) {                              // wait peers' h(s_-1)
            #pragma unroll
            for (int pi = 0; pi < 3; pi++) {
                unsigned v;
                do {
                    asm volatile("ld.acquire.cluster.shared::cta.u32 %0, [%1];"
                                 : "=r"(v) : "r"(lfl[pi]) : "memory");
                } while ((int)v < s_);
            }
        }
        #pragma unroll
        for (int c = 1; c < 4; c++) {
            const u64* hq = h2 + 16*((q + c) & 3);
            #pragma unroll
            for (int j = 0; j < 16; j += 4) {
                ulonglong2 x0 = *(const ulonglong2*)(hq + j);
                ulonglong2 x1 = *(const ulonglong2*)(hq + j + 2);
                fma2(a0, w[c*16 + j],     x0.x);  fma2(a1, w[c*16 + j + 1], x0.y);
                fma2(a2, w[c*16 + j + 2], x1.x);  fma2(a3, w[c*16 + j + 3], x1.y);
            }
        }
        float2 fa = u2f(a0), fb = u2f(a1), fc = u2f(a2), fd = u2f(a3);
        gs[g][hl] = ((fa.x + fa.y) + (fb.x + fb.y)) + ((fc.x + fc.y) + (fd.x + fd.y)) + pcur;
        pcur = pnext;
        __syncthreads();                           // gates ready; reads of rb done
        if (t < 32) {
            float ig = 0.5f*tanha(0.5f*gs[0][eh]) + 0.5f;
            float fg = 0.5f*tanha(0.5f*gs[1][eh]) + 0.5f;
            float gg = tanha(gs[2][eh]);
            float og = 0.5f*tanha(0.5f*gs[3][eh]) + 0.5f;
            cst = fg*cst + ig*gg;
            float hv = og * tanha(cst);
            hsf[wb][q*32 + eh] = hv;
            unsigned off = (unsigned)((wb*HH + q*32 + eh) * 4);
            asm volatile("st.shared::cluster.f32 [%0], %1;" :: "r"(rbp[0] + off), "f"(hv) : "memory");
            asm volatile("st.shared::cluster.f32 [%0], %1;" :: "r"(rbp[1] + off), "f"(hv) : "memory");
            asm volatile("st.shared::cluster.f32 [%0], %1;" :: "r"(rbp[2] + off), "f"(hv) : "memory");
            __syncwarp();
            if (eh < 3) {                          // publish "h(s_) ready" = s_+1
                asm volatile("st.release.cluster.shared::cluster.u32 [%0], %1;"
                             :: "r"(rfl[eh]), "r"(s_ + 1) : "memory");
            }
            hout[(bt*SS + s)*FF + dir*HH + q*32 + eh] = hv;
        }
        __syncthreads();                           // local quarter of wb visible to CTA
    }
    asm volatile("barrier.cluster.arrive.aligned;" ::: "memory");
    asm volatile("barrier.cluster.wait.aligned;"   ::: "memory");
}

// ---------------- cls / bin MLPs ----------------
__global__ void k_clsbin(const float* __restrict__ rnn,
    const float* ac0, const float* __restrict__ wc1, const float* __restrict__ bc1,
    const float* ac1, const float* __restrict__ wc2, const float* __restrict__ bc2,
    const float* ab0, const float* __restrict__ wb1, const float* __restrict__ bb1,
    const float* ab1, const float* __restrict__ wb2, const float* __restrict__ bb2,
    float* __restrict__ out) {
    int s = blockIdx.x, b = blockIdx.y, t = threadIdx.x; // blockDim = 192
    __shared__ float xc[FF], xb[FF], hc[80], hb[80];
    float a0c = *ac0, a0b = *ab0;
    for (int k = t; k < FF; k += 192) {
        float v = rnn[(b*SS + s)*FF + k];
        xc[k] = v >= 0.f ? v : a0c*v;
        xb[k] = v >= 0.f ? v : a0b*v;
    }
    __syncthreads();
    if (t < 80) {
        float acc = bc1[t];
        const float* w = wc1 + t*FF;
        #pragma unroll 4
        for (int k = 0; k < FF; k++) acc += xc[k]*w[k];
        float a1 = *ac1;
        hc[t] = acc >= 0.f ? acc : a1*acc;
    } else if (t < 160) {
        int g = t - 80;
        float acc = bb1[g];
        const float* w = wb1 + g*FF;
        #pragma unroll 4
        for (int k = 0; k < FF; k++) acc += xb[k]*w[k];
        float a1 = *ab1;
        hb[g] = acc >= 0.f ? acc : a1*acc;
    }
    __syncthreads();
    if (t < NCC) {
        float acc = bc2[t];
        const float* w = wc2 + t*80;
        #pragma unroll 4
        for (int k = 0; k < 80; k++) acc += hc[k]*w[k];
        out[(b*SS + s)*NCC + t] = acc;
    } else if (t < NCC + 2) {
        int o = t - NCC;
        float acc = bb2[o];
        const float* w = wb2 + o*80;
        #pragma unroll 4
        for (int k = 0; k < 80; k++) acc += hb[k]*w[k];
        out[20480 + (b*SS + s)*2 + o] = acc;
    }
}

// ---------------- cumsum ----------------
__global__ void k_cum(const float* __restrict__ rnn) {
    int b = blockIdx.x, k = threadIdx.x;
    float run = 0.f;
    for (int t0 = 0; t0 < SS; t0 += 8) {
        float v[8];
        #pragma unroll
        for (int j = 0; j < 8; j++) v[j] = rnn[(b*SS + t0 + j)*FF + k];
        #pragma unroll
        for (int j = 0; j < 8; j++) { run += v[j]; g_cum[(b*SS + t0 + j)*FF + k] = run; }
    }
}

// ---------------- Pd / Pe ----------------
__global__ void k_pdpe(const float* __restrict__ rnn, const float* as0, const float* __restrict__ bs1) {
    int s = blockIdx.x, b = blockIdx.y, t = threadIdx.x; // blockDim = 128
    __shared__ __align__(16) float xr[FF];
    float a0 = *as0;
    {
        float v0 = rnn[(b*SS + s)*FF + 2*t];
        float v1 = rnn[(b*SS + s)*FF + 2*t + 1];
        xr[2*t]     = v0 >= 0.f ? v0 : a0*v0;
        xr[2*t + 1] = v1 >= 0.f ? v1 : a0*v1;
    }
    __syncthreads();
    const u64* xp = (const u64*)xr;
    if (t < HID) {
        u64 d0 = 0ull, d1 = 0ull, e0 = 0ull, e1 = 0ull;
        #pragma unroll 8
        for (int k2 = 0; k2 < 128; k2 += 2) {
            fma2(d0, g_wsP[1][(k2    )*128 + t], xp[k2    ]);
            fma2(d1, g_wsP[1][(k2 + 1)*128 + t], xp[k2 + 1]);
            fma2(e0, g_wsP[2][(k2    )*128 + t], xp[k2    ]);
            fma2(e1, g_wsP[2][(k2 + 1)*128 + t], xp[k2 + 1]);
        }
        float2 fd0 = u2f(d0), fd1 = u2f(d1), fe0 = u2f(e0), fe1 = u2f(e1);
        g_Pd[(b*SS + s)*HID + t] = fd0.x + fd0.y + fd1.x + fd1.y;
        g_Pe[(b*SS + s)*HID + t] = fe0.x + fe0.y + fe1.x + fe1.y + bs1[t];
    }
}

// ---------------- banded score MLP, register-blocked 16 windows, vectorized ----------------
__global__ void k_scores(const float* as0, const float* as1,
                         const float* __restrict__ ws2, const float* bs2) {
    int i = blockIdx.x, b = blockIdx.y, t = threadIdx.x; // blockDim = 128
    if (i == 0) return;
    __shared__ __align__(16) float cdf[16][FF];
    __shared__ float sv[16][104];
    const ulonglong2 (*cd2)[64] = (const ulonglong2 (*)[64])cdf;
    float a0 = *as0, a1 = *as1, b2 = *bs2;
    u64 civ = ((const u64*)(g_cum + (b*SS + i)*FF))[t];
    float2 ci = u2f(civ);
    float pei = (t < HID) ? g_Pe[(b*SS + i)*HID + t] : 0.f;
    float w2  = (t < HID) ? ws2[t] : 0.f;
    int wid = t >> 5, lane = t & 31;

    for (int gq = 0; gq < 4; gq++) {
        #pragma unroll 4
        for (int p = 0; p < 16; p++) {
            int j = i - WW + gq*16 + p;
            float c0 = 0.f, c1 = 0.f;
            if (j >= 0) {
                float2 cj = u2f(((const u64*)(g_cum + (b*SS + j)*FF))[t]);
                c0 = ci.x - cj.x;  c1 = ci.y - cj.y;
                c0 = c0 >= 0.f ? c0 : a0*c0;
                c1 = c1 >= 0.f ? c1 : a0*c1;
            }
            ((u64*)cdf[p])[t] = f2u(c0, c1);
        }
        __syncthreads();
        if (t < HID) {
            u64 acc[16];
            #pragma unroll
            for (int p = 0; p < 16; p++) acc[p] = 0ull;
            const ulonglong2* wr = (const ulonglong2*)(g_wsPc + (size_t)t*128);
            #pragma unroll 2
            for (int k4 = 0; k4 < 64; k4++) {
                ulonglong2 wv = __ldg(&wr[k4]);
                #pragma unroll
                for (int p = 0; p < 16; p++) {
                    ulonglong2 x = cd2[p][k4];
                    fma2(acc[p], wv.x, x.x);
                    fma2(acc[p], wv.y, x.y);
                }
            }
            #pragma unroll
            for (int p = 0; p < 16; p++) {
                int j = i - WW + gq*16 + p;
                float2 f = u2f(acc[p]);
                float pd = (j >= 0) ? g_Pd[(b*SS + j)*HID + t] : 0.f;
                float hid = f.x + f.y + pd + pei;
                float ph  = hid >= 0.f ? hid : a1*hid;
                sv[p][t] = ph * w2;
            }
        }
        __syncthreads();
        #pragma unroll
        for (int q = 0; q < 4; q++) {
            int p = wid + q*4;
            float v = sv[p][lane] + sv[p][lane + 32] + sv[p][lane + 64]
                    + (lane < 4 ? sv[p][lane + 96] : 0.f);
            for (int off = 16; off; off >>= 1) v += __shfl_down_sync(0xffffffffu, v, off);
            if (lane == 0) {
                int w = gq*16 + p;
                int j = i - WW + w;
                g_sband[(b*SS + i)*WW + w] = (j >= 0) ? v + b2 : -1000000000.0f;
            }
        }
        __syncthreads();
    }
}

// ---------------- DP + backtrack (sband preloaded to smem, redux argmax) ----------------
__global__ void k_dp(const int* __restrict__ lengths, float* __restrict__ out) {
    extern __shared__ __align__(16) float sbf[];   // 2*256*64 floats = 128 KB
    __shared__ float best[BB][SS];
    __shared__ int   bp[BB][SS];
    int t = threadIdx.x;          // blockDim = 256
    // preload sband + zero output mask region
    {
        float4* dst = (float4*)sbf;
        const float4* src = (const float4*)g_sband;
        #pragma unroll 4
        for (int idx = t; idx < BB*SS*WW/4; idx += 256) dst[idx] = __ldg(src + idx);
    }
    for (int idx = t; idx < BB*SS; idx += 256) { out[21504 + idx] = 0.f; best[idx >> 8][idx & 255] = 0.f; }
    if (t < BB) bp[t][0] = 0;
    __syncthreads();
    if (t < 64) {
        int b = t >> 5, lane = t & 31;
        for (int i = 1; i < SS; i++) {
            int w1 = lane, w2 = lane + 32;
            int j1 = i - WW + w1, j2 = i - WW + w2;
            const float* sr = sbf + (b*SS + i)*WW;
            float c1 = (j1 >= 0) ? best[b][j1] + sr[w1] : -1000000000.0f;
            float c2 = (j2 >= 0) ? best[b][j2] + sr[w2] : -1000000000.0f;
            float v; int jj;
            if (c2 > c1) { v = c2; jj = j2; } else { v = c1; jj = j1; }   // tie -> smaller j
            unsigned key = orderable(v), kmax;
            asm("redux.sync.max.u32 %0, %1, 0xffffffff;" : "=r"(kmax) : "r"(key));
            unsigned jc = (key == kmax) ? (unsigned)jj : 0xFFFFFFFFu;
            unsigned jmin;
            asm("redux.sync.min.u32 %0, %1, 0xffffffff;" : "=r"(jmin) : "r"(jc));
            if (lane == 0) { best[b][i] = unorder(kmax); bp[b][i] = (int)jmin; }
            __syncwarp();
        }
    }
    __syncthreads();
    if (t < BB) {
        int cur = lengths[t] - 1;
        if (cur < 0) cur = 0;
        float acc = 0.f;
        while (true) {
            out[21504 + t*SS + cur] = 1.f;
            if (cur == 0) break;
            int prev = bp[t][cur];
            acc += sbf[(t*SS + cur)*WW + (prev - (cur - WW))];
            cur = prev;
        }
        out[22016 + t] = acc;
    }
}

// ---------------- launch ----------------
extern "C" void kernel_launch(void* const* d_in, const int* in_sizes, int n_in,
                              void* d_out, int out_size) {
    (void)in_sizes; (void)n_in; (void)out_size;
    const float* x        = (const float*)d_in[0];
    const int*   lengths  = (const int*)  d_in[1];
    const float* wih[4]   = {(const float*)d_in[2], (const float*)d_in[5],
                             (const float*)d_in[8], (const float*)d_in[11]};
    const float* whh[4]   = {(const float*)d_in[3], (const float*)d_in[6],
                             (const float*)d_in[9], (const float*)d_in[12]};
    const float* bl[4]    = {(const float*)d_in[4], (const float*)d_in[7],
                             (const float*)d_in[10], (const float*)d_in[13]};
    const float* a_s0 = (const float*)d_in[14];
    const float* w_s1 = (const float*)d_in[15];
    const float* b_s1 = (const float*)d_in[16];
    const float* a_s1 = (const float*)d_in[17];
    const float* w_s2 = (const float*)d_in[18];
    const float* b_s2 = (const float*)d_in[19];
    const float* a_c0 = (const float*)d_in[20];
    const float* w_c1 = (const float*)d_in[21];
    const float* b_c1 = (const float*)d_in[22];
    const float* a_c1 = (const float*)d_in[23];
    const float* w_c2 = (const float*)d_in[24];
    const float* b_c2 = (const float*)d_in[25];
    const float* a_b0 = (const float*)d_in[26];
    const float* w_b1 = (const float*)d_in[27];
    const float* b_b1 = (const float*)d_in[28];
    const float* a_b1 = (const float*)d_in[29];
    const float* w_b2 = (const float*)d_in[30];
    const float* b_b2 = (const float*)d_in[31];
    float* out = (float*)d_out;

    float *wihT, *preF, *preB, *h0, *rnn;
    cudaGetSymbolAddress((void**)&wihT, g_wihT);
    cudaGetSymbolAddress((void**)&preF, g_preF);
    cudaGetSymbolAddress((void**)&preB, g_preB);
    cudaGetSymbolAddress((void**)&h0,   g_h0);
    cudaGetSymbolAddress((void**)&rnn,  g_rnn);

    static int dp_attr_set = 0;
    if (!dp_attr_set) {
        cudaFuncSetAttribute(k_dp, cudaFuncAttributeMaxDynamicSharedMemorySize, BB*SS*WW*4);
        dp_attr_set = 1;
    }

    k_transpose_all<<<dim3(FF, 4), GG>>>(wih[0], wih[1], wih[2], wih[3], wihT);
    k_pack_ws1<<<dim3(128, 3), 128>>>(w_s1);

    dim3 gpre8(SS/8, BB, 2);
    // layer 0
    k_pre8m<<<gpre8, GG>>>(x, wihT, bl[0], bl[1], preF, preB, INP);
    k_scan8<<<16, 128>>>(preF, preB, whh[0], whh[1], h0);
    // layer 1
    k_pre8m<<<gpre8, GG>>>(h0, wihT + 2*FF*GG, bl[2], bl[3], preF, preB, FF);
    k_scan8<<<16, 128>>>(preF, preB, whh[2], whh[3], rnn);

    k_clsbin<<<dim3(SS, BB), 192>>>(rnn, a_c0, w_c1, b_c1, a_c1, w_c2, b_c2,
                                         a_b0, w_b1, b_b1, a_b1, w_b2, b_b2, out);
    k_cum<<<BB, FF>>>(rnn);
    k_pdpe<<<dim3(SS, BB), 128>>>(rnn, a_s0, b_s1);
    k_scores<<<dim3(SS, BB), 128>>>(a_s0, a_s1, w_s2, b_s2);
    k_dp<<<1, 256, BB*SS*WW*4>>>(lengths, out);
}

// round 13
// speedup vs baseline: 4.7668x; 1.2678x over previous
#include <cuda_runtime.h>
#include <cuda_bf16.h>

#define BB   2
#define SS   256
#define INP  80
#define HH   128
#define GG   512
#define FF   256
#define NCC  40
#define WW   64
#define HID  100

typedef unsigned long long u64;

__device__ float g_wihT [4][FF*GG];
__device__ u64   g_wsP  [3][128*128];
__device__ __align__(16) u64 g_wsPc[128*128];   // w_s1 c-part, [h][k2] contiguous
__device__ float g_preF [SS*BB*GG];
__device__ float g_preB [SS*BB*GG];
__device__ float g_h0   [BB*SS*FF];
__device__ float g_rnn  [BB*SS*FF];
__device__ float g_cum  [BB*SS*FF];
__device__ float g_Pd   [BB*SS*HID];
__device__ float g_Pe   [BB*SS*HID];
__device__ float g_sband[BB*SS*WW];

__device__ __forceinline__ void fma2(u64 &d, u64 a, u64 b) {
    asm("fma.rn.f32x2 %0, %1, %2, %0;" : "+l"(d) : "l"(a), "l"(b));
}
__device__ __forceinline__ float2 u2f(u64 v) {
    float2 f; asm("mov.b64 {%0,%1}, %2;" : "=f"(f.x), "=f"(f.y) : "l"(v)); return f;
}
__device__ __forceinline__ u64 f2u(float x, float y) {
    u64 v; asm("mov.b64 %0, {%1,%2};" : "=l"(v) : "f"(x), "f"(y)); return v;
}
__device__ __forceinline__ unsigned smem_u32(const void* p) {
    unsigned a;
    asm("{ .reg .u64 t; cvta.to.shared.u64 t, %1; cvt.u32.u64 %0, t; }" : "=r"(a) : "l"(p));
    return a;
}
__device__ __forceinline__ float tanha(float x) {
    float r; asm("tanh.approx.f32 %0, %1;" : "=f"(r) : "f"(x)); return r;
}
__device__ __forceinline__ unsigned orderable(float v) {
    unsigned u = __float_as_uint(v);
    return (u & 0x80000000u) ? ~u : (u | 0x80000000u);
}
__device__ __forceinline__ float unorder(unsigned u) {
    return (u & 0x80000000u) ? __uint_as_float(u & 0x7FFFFFFFu)
                             : __uint_as_float(~u);
}
__device__ __forceinline__ void mbar_init(unsigned mb, unsigned cnt) {
    asm volatile("mbarrier.init.shared.b64 [%0], %1;" :: "r"(mb), "r"(cnt) : "memory");
}
__device__ __forceinline__ void mbar_expect(unsigned mb, unsigned bytes) {
    asm volatile("mbarrier.arrive.expect_tx.shared.b64 _, [%0], %1;"
                 :: "r"(mb), "r"(bytes) : "memory");
}
__device__ __forceinline__ void mbar_wait_par(unsigned mb, unsigned par) {
    unsigned done = 0;
    do {
        asm volatile("{\n\t.reg .pred p;\n\t"
            "mbarrier.try_wait.parity.acquire.cta.shared::cta.b64 p, [%1], %2, 0x989680;\n\t"
            "selp.b32 %0,1,0,p;\n\t}" : "=r"(done) : "r"(mb), "r"(par) : "memory");
    } while (!done);
}
__device__ __forceinline__ void bulk_copy_peer(unsigned dst, unsigned src, unsigned mbar_remote) {
    asm volatile("cp.async.bulk.shared::cluster.shared::cta.mbarrier::complete_tx::bytes "
                 "[%0], [%1], 128, [%2];"
                 :: "r"(dst), "r"(src), "r"(mbar_remote) : "memory");
}
__device__ __forceinline__ void fence_async() {
    asm volatile("fence.proxy.async.shared::cta;" ::: "memory");
}

// ---------------- prep: transpose + ws1 pack, one kernel ----------------
__global__ void k_prep(const float* __restrict__ w0, const float* __restrict__ w1,
                       const float* __restrict__ w2, const float* __restrict__ w3,
                       const float* __restrict__ ws1, float* __restrict__ wT) {
    int m = blockIdx.y, c = blockIdx.x, tt = threadIdx.x;
    if (m < 4) {
        const float* w = (m == 0) ? w0 : (m == 1) ? w1 : (m == 2) ? w2 : w3;
        int cols = (m < 2) ? INP : FF;
        if (c < cols) wT[m*FF*GG + c*GG + tt] = w[tt*cols + c];
    } else {
        if (c < 128) {
            int p = tt >> 7, h = tt & 127;
            if (p < 3) {
                u64 v = 0ull;
                if (h < HID) v = f2u(ws1[h*768 + p*256 + 2*c], ws1[h*768 + p*256 + 2*c + 1]);
                g_wsP[p][c*128 + h] = v;
                if (p == 0) g_wsPc[h*128 + c] = v;
            }
        }
    }
}

// ---------------- pre = x @ Wih^T + b, 8 timesteps per block, F+B merged ----------------
__global__ void k_pre8m(const float* __restrict__ xin, const float* __restrict__ wTbase,
                        const float* __restrict__ bF, const float* __restrict__ bB,
                        float* __restrict__ preFo, float* __restrict__ preBo, int Din) {
    __shared__ float xs[8][FF];
    int z = blockIdx.z;
    const float* wT   = wTbase + z*FF*GG;
    const float* bias = z ? bB : bF;
    float* pre        = z ? preBo : preFo;
    int sb = blockIdx.x * 8, b = blockIdx.y, g = threadIdx.x;
    for (int idx = g; idx < 8*Din; idx += GG) {
        int j = idx / Din, k = idx - j*Din;
        xs[j][k] = xin[(b*SS + sb + j)*Din + k];
    }
    __syncthreads();
    float bi = bias[g];
    float acc[8];
    #pragma unroll
    for (int j = 0; j < 8; j++) acc[j] = bi;
    for (int i = 0; i < Din; i += 4) {
        float w0 = wT[(i    )*GG + g];
        float w1 = wT[(i + 1)*GG + g];
        float w2 = wT[(i + 2)*GG + g];
        float w3 = wT[(i + 3)*GG + g];
        #pragma unroll
        for (int j = 0; j < 8; j++)
            acc[j] += xs[j][i]*w0 + xs[j][i+1]*w1 + xs[j][i+2]*w2 + xs[j][i+3]*w3;
    }
    #pragma unroll
    for (int j = 0; j < 8; j++) pre[((sb + j)*BB + b)*GG + g] = acc[j];
}

// ---------------- LSTM scan: 8-CTA cluster per dir, one-hop bulk exchange ----------------
// Cluster rank r: q = r&3 (h-quarter), bt = r>>2 (batch). 128 threads/CTA.
// Epilogue warp stores h to local smem, then lanes 0-2 issue cp.async.bulk
// (128B) to the 3 same-batch peers; the copy's complete_tx lands on the
// peer's double-buffered mbarrier -> single fabric hop carries data + signal.
__global__ void __launch_bounds__(128, 1) __cluster_dims__(8, 1, 1)
k_scan8(const float* __restrict__ preFp, const float* __restrict__ preBp,
        const float* __restrict__ whFp, const float* __restrict__ whBp,
        float* __restrict__ hout) {
    int dir  = blockIdx.x >> 3;
    int r    = blockIdx.x & 7;
    int q    = r & 3;
    int bt   = r >> 2;
    const float* pre = dir ? preBp : preFp;
    const u64*   W   = (const u64*)(dir ? whBp : whFp);   // [512 rows][64 u64]
    int t  = threadIdx.x;          // 128
    int g  = t >> 5;
    int hl = t & 31;
    int row = g*HH + q*32 + hl;

    __shared__ __align__(16) float hsf[2][HH];     // [buf][k] for this batch
    __shared__ float gs[4][32];                    // [gate][local unit]
    __shared__ __align__(8) u64 mbar[2];           // one barrier per buffer

    u64 w[64];
    #pragma unroll
    for (int c = 0; c < 4; c++) {
        int qb = 16 * ((q + c) & 3);
        #pragma unroll
        for (int j = 0; j < 16; j++) w[c*16 + j] = W[row*64 + qb + j];
    }

    for (int i = t; i < 2*HH; i += 128) ((float*)hsf)[i] = 0.f;
    unsigned mb = smem_u32(&mbar[0]);
    if (t == 0) { mbar_init(mb, 1); mbar_init(mb + 8, 1); }
    __syncthreads();
    if (t == 0) { mbar_expect(mb, 384); mbar_expect(mb + 8, 384); }
    asm volatile("barrier.cluster.arrive.aligned;" ::: "memory");
    asm volatile("barrier.cluster.wait.aligned;"   ::: "memory");

    unsigned lbase = smem_u32(&hsf[0][0]);
    unsigned rbp[3], rmb[3];
    #pragma unroll
    for (int pi = 0; pi < 3; pi++) {
        int pr = (bt << 2) | ((q + 1 + pi) & 3);   // same-batch peer
        asm("mapa.shared::cluster.u32 %0, %1, %2;" : "=r"(rmb[pi]) : "r"(mb),    "r"(pr));
        asm("mapa.shared::cluster.u32 %0, %1, %2;" : "=r"(rbp[pi]) : "r"(lbase), "r"(pr));
    }

    int eh = t & 31;               // epilogue lane (t < 32)
    float cst = 0.f;
    int s0 = dir ? (SS - 1) : 0;
    float pcur = __ldg(&pre[(s0*BB + bt)*GG + row]);
    unsigned ph0 = 0, ph1 = 0;

    for (int s_ = 0; s_ < SS; s_++) {
        int s  = dir ? (SS - 1 - s_) : s_;
        int sn = dir ? (s - 1 < 0 ? 0 : s - 1) : (s + 1 > SS - 1 ? SS - 1 : s + 1);
        float pnext = __ldg(&pre[(sn*BB + bt)*GG + row]);
        int rb = (s_ + 1) & 1;
        int wb = s_ & 1;
        const u64* h2 = (const u64*)hsf[rb];
        u64 a0 = 0ull, a1 = 0ull, a2 = 0ull, a3 = 0ull;
        {   // local quarter — ordered by __syncthreads
            const u64* hq = h2 + 16*q;
            #pragma unroll
            for (int j = 0; j < 16; j += 2) {
                ulonglong2 x = *(const ulonglong2*)(hq + j);
                fma2(a0, w[j], x.x);  fma2(a1, w[j + 1], x.y);
            }
        }
        if (s_ > 0) {                              // wait peers' h(s_-1) in buffer rb
            unsigned bmb = mb + 8u*(unsigned)rb;
            mbar_wait_par(bmb, rb ? ph1 : ph0);
            if (t == 0) mbar_expect(bmb, 384);     // re-arm for next use (s_+2)
            if (rb) ph1 ^= 1; else ph0 ^= 1;
        }
        #pragma unroll
        for (int c = 1; c < 4; c++) {
            const u64* hq = h2 + 16*((q + c) & 3);
            #pragma unroll
            for (int j = 0; j < 16; j += 4) {
                ulonglong2 x0 = *(const ulonglong2*)(hq + j);
                ulonglong2 x1 = *(const ulonglong2*)(hq + j + 2);
                fma2(a0, w[c*16 + j],     x0.x);  fma2(a1, w[c*16 + j + 1], x0.y);
                fma2(a2, w[c*16 + j + 2], x1.x);  fma2(a3, w[c*16 + j + 3], x1.y);
            }
        }
        float2 fa = u2f(a0), fb = u2f(a1), fc = u2f(a2), fd = u2f(a3);
        gs[g][hl] = ((fa.x + fa.y) + (fb.x + fb.y)) + ((fc.x + fc.y) + (fd.x + fd.y)) + pcur;
        pcur = pnext;
        __syncthreads();                           // gates ready; reads of rb done
        if (t < 32) {
            float ig = 0.5f*tanha(0.5f*gs[0][eh]) + 0.5f;
            float fg = 0.5f*tanha(0.5f*gs[1][eh]) + 0.5f;
            float gg = tanha(gs[2][eh]);
            float og = 0.5f*tanha(0.5f*gs[3][eh]) + 0.5f;
            cst = fg*cst + ig*gg;
            float hv = og * tanha(cst);
            hsf[wb][q*32 + eh] = hv;
            __syncwarp();
            if (eh < 3) {                          // ship quarter to 3 peers, one hop each
                fence_async();
                unsigned off = (unsigned)((wb*HH + q*32) * 4);
                bulk_copy_peer(rbp[eh] + off, lbase + off, rmb[eh] + 8u*(unsigned)wb);
            }
            hout[(bt*SS + s)*FF + dir*HH + q*32 + eh] = hv;
        }
        __syncthreads();                           // local quarter of wb visible to CTA
    }
    asm volatile("barrier.cluster.arrive.aligned;" ::: "memory");
    asm volatile("barrier.cluster.wait.aligned;"   ::: "memory");
}

// ---------------- cls / bin MLPs ----------------
__global__ void k_clsbin(const float* __restrict__ rnn,
    const float* ac0, const float* __restrict__ wc1, const float* __restrict__ bc1,
    const float* ac1, const float* __restrict__ wc2, const float* __restrict__ bc2,
    const float* ab0, const float* __restrict__ wb1, const float* __restrict__ bb1,
    const float* ab1, const float* __restrict__ wb2, const float* __restrict__ bb2,
    float* __restrict__ out) {
    int s = blockIdx.x, b = blockIdx.y, t = threadIdx.x; // blockDim = 192
    __shared__ float xc[FF], xb[FF], hc[80], hb[80];
    float a0c = *ac0, a0b = *ab0;
    for (int k = t; k < FF; k += 192) {
        float v = rnn[(b*SS + s)*FF + k];
        xc[k] = v >= 0.f ? v : a0c*v;
        xb[k] = v >= 0.f ? v : a0b*v;
    }
    __syncthreads();
    if (t < 80) {
        float acc = bc1[t];
        const float* w = wc1 + t*FF;
        #pragma unroll 4
        for (int k = 0; k < FF; k++) acc += xc[k]*w[k];
        float a1 = *ac1;
        hc[t] = acc >= 0.f ? acc : a1*acc;
    } else if (t < 160) {
        int g = t - 80;
        float acc = bb1[g];
        const float* w = wb1 + g*FF;
        #pragma unroll 4
        for (int k = 0; k < FF; k++) acc += xb[k]*w[k];
        float a1 = *ab1;
        hb[g] = acc >= 0.f ? acc : a1*acc;
    }
    __syncthreads();
    if (t < NCC) {
        float acc = bc2[t];
        const float* w = wc2 + t*80;
        #pragma unroll 4
        for (int k = 0; k < 80; k++) acc += hc[k]*w[k];
        out[(b*SS + s)*NCC + t] = acc;
    } else if (t < NCC + 2) {
        int o = t - NCC;
        float acc = bb2[o];
        const float* w = wb2 + o*80;
        #pragma unroll 4
        for (int k = 0; k < 80; k++) acc += hb[k]*w[k];
        out[20480 + (b*SS + s)*2 + o] = acc;
    }
}

// ---------------- cumsum (software-pipelined loads) ----------------
__global__ void k_cum(const float* __restrict__ rnn) {
    int b = blockIdx.x, k = threadIdx.x;
    float run = 0.f;
    float v[8], vn[8];
    #pragma unroll
    for (int j = 0; j < 8; j++) v[j] = rnn[(b*SS + j)*FF + k];
    for (int t0 = 0; t0 < SS; t0 += 8) {
        if (t0 + 8 < SS) {
            #pragma unroll
            for (int j = 0; j < 8; j++) vn[j] = rnn[(b*SS + t0 + 8 + j)*FF + k];
        }
        #pragma unroll
        for (int j = 0; j < 8; j++) { run += v[j]; g_cum[(b*SS + t0 + j)*FF + k] = run; }
        #pragma unroll
        for (int j = 0; j < 8; j++) v[j] = vn[j];
    }
}

// ---------------- Pd / Pe, 2 timesteps per block ----------------
__global__ void k_pdpe2(const float* __restrict__ rnn, const float* as0, const float* __restrict__ bs1) {
    int sp = blockIdx.x * 2, b = blockIdx.y, t = threadIdx.x; // blockDim = 128
    __shared__ __align__(16) float xr[2][FF];
    float a0 = *as0;
    #pragma unroll
    for (int ss = 0; ss < 2; ss++) {
        float v0 = rnn[(b*SS + sp + ss)*FF + 2*t];
        float v1 = rnn[(b*SS + sp + ss)*FF + 2*t + 1];
        xr[ss][2*t]     = v0 >= 0.f ? v0 : a0*v0;
        xr[ss][2*t + 1] = v1 >= 0.f ? v1 : a0*v1;
    }
    __syncthreads();
    if (t < HID) {
        u64 d0 = 0ull, e0 = 0ull, d1 = 0ull, e1 = 0ull;
        const u64* xp0 = (const u64*)xr[0];
        const u64* xp1 = (const u64*)xr[1];
        #pragma unroll 4
        for (int k2 = 0; k2 < 128; k2++) {
            u64 wd = g_wsP[1][k2*128 + t];
            u64 we = g_wsP[2][k2*128 + t];
            u64 x0 = xp0[k2], x1 = xp1[k2];
            fma2(d0, wd, x0);  fma2(e0, we, x0);
            fma2(d1, wd, x1);  fma2(e1, we, x1);
        }
        float bsv = bs1[t];
        float2 f;
        f = u2f(d0); g_Pd[(b*SS + sp    )*HID + t] = f.x + f.y;
        f = u2f(e0); g_Pe[(b*SS + sp    )*HID + t] = f.x + f.y + bsv;
        f = u2f(d1); g_Pd[(b*SS + sp + 1)*HID + t] = f.x + f.y;
        f = u2f(e1); g_Pe[(b*SS + sp + 1)*HID + t] = f.x + f.y + bsv;
    }
}

// ---------------- banded score MLP, register-blocked 16 windows, vectorized ----------------
__global__ void k_scores(const float* as0, const float* as1,
                         const float* __restrict__ ws2, const float* bs2) {
    int i = blockIdx.x, b = blockIdx.y, t = threadIdx.x; // blockDim = 128
    if (i == 0) return;
    __shared__ __align__(16) float cdf[16][FF];
    __shared__ float sv[16][104];
    const ulonglong2 (*cd2)[64] = (const ulonglong2 (*)[64])cdf;
    float a0 = *as0, a1 = *as1, b2 = *bs2;
    u64 civ = ((const u64*)(g_cum + (b*SS + i)*FF))[t];
    float2 ci = u2f(civ);
    float pei = (t < HID) ? g_Pe[(b*SS + i)*HID + t] : 0.f;
    float w2  = (t < HID) ? ws2[t] : 0.f;
    int wid = t >> 5, lane = t & 31;

    for (int gq = 0; gq < 4; gq++) {
        #pragma unroll 4
        for (int p = 0; p < 16; p++) {
            int j = i - WW + gq*16 + p;
            float c0 = 0.f, c1 = 0.f;
            if (j >= 0) {
                float2 cj = u2f(((const u64*)(g_cum + (b*SS + j)*FF))[t]);
                c0 = ci.x - cj.x;  c1 = ci.y - cj.y;
                c0 = c0 >= 0.f ? c0 : a0*c0;
                c1 = c1 >= 0.f ? c1 : a0*c1;
            }
            ((u64*)cdf[p])[t] = f2u(c0, c1);
        }
        __syncthreads();
        if (t < HID) {
            u64 acc[16];
            #pragma unroll
            for (int p = 0; p < 16; p++) acc[p] = 0ull;
            const ulonglong2* wr = (const ulonglong2*)(g_wsPc + (size_t)t*128);
            #pragma unroll 2
            for (int k4 = 0; k4 < 64; k4++) {
                ulonglong2 wv = __ldg(&wr[k4]);
                #pragma unroll
                for (int p = 0; p < 16; p++) {
                    ulonglong2 x = cd2[p][k4];
                    fma2(acc[p], wv.x, x.x);
                    fma2(acc[p], wv.y, x.y);
                }
            }
            #pragma unroll
            for (int p = 0; p < 16; p++) {
                int j = i - WW + gq*16 + p;
                float2 f = u2f(acc[p]);
                float pd = (j >= 0) ? g_Pd[(b*SS + j)*HID + t] : 0.f;
                float hid = f.x + f.y + pd + pei;
                float ph  = hid >= 0.f ? hid : a1*hid;
                sv[p][t] = ph * w2;
            }
        }
        __syncthreads();
        #pragma unroll
        for (int qq = 0; qq < 4; qq++) {
            int p = wid + qq*4;
            float v = sv[p][lane] + sv[p][lane + 32] + sv[p][lane + 64]
                    + (lane < 4 ? sv[p][lane + 96] : 0.f);
            for (int off = 16; off; off >>= 1) v += __shfl_down_sync(0xffffffffu, v, off);
            if (lane == 0) {
                int w = gq*16 + p;
                int j = i - WW + w;
                g_sband[(b*SS + i)*WW + w] = (j >= 0) ? v + b2 : -1000000000.0f;
            }
        }
        __syncthreads();
    }
}

// ---------------- DP + backtrack (sband preloaded to smem, redux argmax) ----------------
__global__ void k_dp(const int* __restrict__ lengths, float* __restrict__ out) {
    extern __shared__ __align__(16) float sbf[];   // 2*256*64 floats = 128 KB
    __shared__ float best[BB][SS];
    __shared__ int   bp[BB][SS];
    int t = threadIdx.x;          // blockDim = 256
    {
        float4* dst = (float4*)sbf;
        const float4* src = (const float4*)g_sband;
        #pragma unroll 4
        for (int idx = t; idx < BB*SS*WW/4; idx += 256) dst[idx] = __ldg(src + idx);
    }
    for (int idx = t; idx < BB*SS; idx += 256) { out[21504 + idx] = 0.f; best[idx >> 8][idx & 255] = 0.f; }
    if (t < BB) bp[t][0] = 0;
    __syncthreads();
    if (t < 64) {
        int b = t >> 5, lane = t & 31;
        for (int i = 1; i < SS; i++) {
            int w1 = lane, w2 = lane + 32;
            int j1 = i - WW + w1, j2 = i - WW + w2;
            const float* sr = sbf + (b*SS + i)*WW;
            float c1 = (j1 >= 0) ? best[b][j1] + sr[w1] : -1000000000.0f;
            float c2 = (j2 >= 0) ? best[b][j2] + sr[w2] : -1000000000.0f;
            float v; int jj;
            if (c2 > c1) { v = c2; jj = j2; } else { v = c1; jj = j1; }   // tie -> smaller j
            unsigned key = orderable(v), kmax;
            asm("redux.sync.max.u32 %0, %1, 0xffffffff;" : "=r"(kmax) : "r"(key));
            unsigned jc = (key == kmax) ? (unsigned)jj : 0xFFFFFFFFu;
            unsigned jmin;
            asm("redux.sync.min.u32 %0, %1, 0xffffffff;" : "=r"(jmin) : "r"(jc));
            if (lane == 0) { best[b][i] = unorder(kmax); bp[b][i] = (int)jmin; }
            __syncwarp();
        }
    }
    __syncthreads();
    if (t < BB) {
        int cur = lengths[t] - 1;
        if (cur < 0) cur = 0;
        float acc = 0.f;
        while (true) {
            out[21504 + t*SS + cur] = 1.f;
            if (cur == 0) break;
            int prev = bp[t][cur];
            acc += sbf[(t*SS + cur)*WW + (prev - (cur - WW))];
            cur = prev;
        }
        out[22016 + t] = acc;
    }
}

// ---------------- launch ----------------
extern "C" void kernel_launch(void* const* d_in, const int* in_sizes, int n_in,
                              void* d_out, int out_size) {
    (void)in_sizes; (void)n_in; (void)out_size;
    const float* x        = (const float*)d_in[0];
    const int*   lengths  = (const int*)  d_in[1];
    const float* wih[4]   = {(const float*)d_in[2], (const float*)d_in[5],
                             (const float*)d_in[8], (const float*)d_in[11]};
    const float* whh[4]   = {(const float*)d_in[3], (const float*)d_in[6],
                             (const float*)d_in[9], (const float*)d_in[12]};
    const float* bl[4]    = {(const float*)d_in[4], (const float*)d_in[7],
                             (const float*)d_in[10], (const float*)d_in[13]};
    const float* a_s0 = (const float*)d_in[14];
    const float* w_s1 = (const float*)d_in[15];
    const float* b_s1 = (const float*)d_in[16];
    const float* a_s1 = (const float*)d_in[17];
    const float* w_s2 = (const float*)d_in[18];
    const float* b_s2 = (const float*)d_in[19];
    const float* a_c0 = (const float*)d_in[20];
    const float* w_c1 = (const float*)d_in[21];
    const float* b_c1 = (const float*)d_in[22];
    const float* a_c1 = (const float*)d_in[23];
    const float* w_c2 = (const float*)d_in[24];
    const float* b_c2 = (const float*)d_in[25];
    const float* a_b0 = (const float*)d_in[26];
    const float* w_b1 = (const float*)d_in[27];
    const float* b_b1 = (const float*)d_in[28];
    const float* a_b1 = (const float*)d_in[29];
    const float* w_b2 = (const float*)d_in[30];
    const float* b_b2 = (const float*)d_in[31];
    float* out = (float*)d_out;

    float *wihT, *preF, *preB, *h0, *rnn;
    cudaGetSymbolAddress((void**)&wihT, g_wihT);
    cudaGetSymbolAddress((void**)&preF, g_preF);
    cudaGetSymbolAddress((void**)&preB, g_preB);
    cudaGetSymbolAddress((void**)&h0,   g_h0);
    cudaGetSymbolAddress((void**)&rnn,  g_rnn);

    static int dp_attr_set = 0;
    if (!dp_attr_set) {
        cudaFuncSetAttribute(k_dp, cudaFuncAttributeMaxDynamicSharedMemorySize, BB*SS*WW*4);
        dp_attr_set = 1;
    }

    k_prep<<<dim3(FF, 5), GG>>>(wih[0], wih[1], wih[2], wih[3], w_s1, wihT);

    dim3 gpre8(SS/8, BB, 2);
    // layer 0
    k_pre8m<<<gpre8, GG>>>(x, wihT, bl[0], bl[1], preF, preB, INP);
    k_scan8<<<16, 128>>>(preF, preB, whh[0], whh[1], h0);
    // layer 1
    k_pre8m<<<gpre8, GG>>>(h0, wihT + 2*FF*GG, bl[2], bl[3], preF, preB, FF);
    k_scan8<<<16, 128>>>(preF, preB, whh[2], whh[3], rnn);

    k_clsbin<<<dim3(SS, BB), 192>>>(rnn, a_c0, w_c1, b_c1, a_c1, w_c2, b_c2,
                                         a_b0, w_b1, b_b1, a_b1, w_b2, b_b2, out);
    k_cum<<<BB, FF>>>(rnn);
    k_pdpe2<<<dim3(SS/2, BB), 128>>>(rnn, a_s0, b_s1);
    k_scores<<<dim3(SS, BB), 128>>>(a_s0, a_s1, w_s2, b_s2);
    k_dp<<<1, 256, BB*SS*WW*4>>>(lengths, out);
}

// round 15
// speedup vs baseline: 5.0540x; 1.0603x over previous
#include <cuda_runtime.h>
#include <cuda_bf16.h>

#define BB   2
#define SS   256
#define INP  80
#define HH   128
#define GG   512
#define FF   256
#define NCC  40
#define WW   64
#define HID  100

typedef unsigned long long u64;

__device__ float g_wihT [4][FF*GG];
__device__ u64   g_wsP  [3][128*128];
__device__ __align__(16) u64 g_wsPc[128*128];   // w_s1 c-part, [h][k2] contiguous
__device__ float g_preF [SS*BB*GG];
__device__ float g_preB [SS*BB*GG];
__device__ float g_h0   [BB*SS*FF];
__device__ float g_rnn  [BB*SS*FF];
__device__ float g_cum  [BB*SS*FF];
__device__ float g_Pd   [BB*SS*HID];
__device__ float g_Pe   [BB*SS*HID];
__device__ float g_sband[BB*SS*WW];

__device__ __forceinline__ void fma2(u64 &d, u64 a, u64 b) {
    asm("fma.rn.f32x2 %0, %1, %2, %0;" : "+l"(d) : "l"(a), "l"(b));
}
__device__ __forceinline__ float2 u2f(u64 v) {
    float2 f; asm("mov.b64 {%0,%1}, %2;" : "=f"(f.x), "=f"(f.y) : "l"(v)); return f;
}
__device__ __forceinline__ u64 f2u(float x, float y) {
    u64 v; asm("mov.b64 %0, {%1,%2};" : "=l"(v) : "f"(x), "f"(y)); return v;
}
__device__ __forceinline__ unsigned smem_u32(const void* p) {
    unsigned a;
    asm("{ .reg .u64 t; cvta.to.shared.u64 t, %1; cvt.u32.u64 %0, t; }" : "=r"(a) : "l"(p));
    return a;
}
__device__ __forceinline__ float tanha(float x) {
    float r; asm("tanh.approx.f32 %0, %1;" : "=f"(r) : "f"(x)); return r;
}
__device__ __forceinline__ unsigned orderable(float v) {
    unsigned u = __float_as_uint(v);
    return (u & 0x80000000u) ? ~u : (u | 0x80000000u);
}
__device__ __forceinline__ float unorder(unsigned u) {
    return (u & 0x80000000u) ? __uint_as_float(u & 0x7FFFFFFFu)
                             : __uint_as_float(~u);
}
__device__ __forceinline__ void mbar_init(unsigned mb, unsigned cnt) {
    asm volatile("mbarrier.init.shared.b64 [%0], %1;" :: "r"(mb), "r"(cnt) : "memory");
}
__device__ __forceinline__ void mbar_expect(unsigned mb, unsigned bytes) {
    asm volatile("mbarrier.arrive.expect_tx.shared.b64 _, [%0], %1;"
                 :: "r"(mb), "r"(bytes) : "memory");
}
__device__ __forceinline__ void mbar_wait_par(unsigned mb, unsigned par) {
    unsigned done = 0;
    do {
        asm volatile("{\n\t.reg .pred p;\n\t"
            "mbarrier.try_wait.parity.acquire.cta.shared::cta.b64 p, [%1], %2, 0x989680;\n\t"
            "selp.b32 %0,1,0,p;\n\t}" : "=r"(done) : "r"(mb), "r"(par) : "memory");
    } while (!done);
}
__device__ __forceinline__ void bulk_copy_peer(unsigned dst, unsigned src, unsigned mbar_remote) {
    asm volatile("cp.async.bulk.shared::cluster.shared::cta.mbarrier::complete_tx::bytes "
                 "[%0], [%1], 128, [%2];"
                 :: "r"(dst), "r"(src), "r"(mbar_remote) : "memory");
}
__device__ __forceinline__ void fence_async() {
    asm volatile("fence.proxy.async.shared::cta;" ::: "memory");
}

// ---------------- prep: transpose + ws1 pack, one kernel ----------------
__global__ void k_prep(const float* __restrict__ w0, const float* __restrict__ w1,
                       const float* __restrict__ w2, const float* __restrict__ w3,
                       const float* __restrict__ ws1, float* __restrict__ wT) {
    int m = blockIdx.y, c = blockIdx.x, tt = threadIdx.x;
    if (m < 4) {
        const float* w = (m == 0) ? w0 : (m == 1) ? w1 : (m == 2) ? w2 : w3;
        int cols = (m < 2) ? INP : FF;
        if (c < cols) wT[m*FF*GG + c*GG + tt] = w[tt*cols + c];
    } else {
        if (c < 128) {
            int p = tt >> 7, h = tt & 127;
            if (p < 3) {
                u64 v = 0ull;
                if (h < HID) v = f2u(ws1[h*768 + p*256 + 2*c], ws1[h*768 + p*256 + 2*c + 1]);
                g_wsP[p][c*128 + h] = v;
                if (p == 0) g_wsPc[h*128 + c] = v;
            }
        }
    }
}

// ---------------- pre = x @ Wih^T + b, 16 timesteps per block, F+B merged ----------------
__global__ void k_pre16m(const float* __restrict__ xin, const float* __restrict__ wTbase,
                         const float* __restrict__ bF, const float* __restrict__ bB,
                         float* __restrict__ preFo, float* __restrict__ preBo, int Din) {
    __shared__ float xs[16][FF];
    int z = blockIdx.z;
    const float* wT   = wTbase + z*FF*GG;
    const float* bias = z ? bB : bF;
    float* pre        = z ? preBo : preFo;
    int sb = blockIdx.x * 16, b = blockIdx.y, g = threadIdx.x;
    for (int idx = g; idx < 16*Din; idx += GG) {
        int j = idx / Din, k = idx - j*Din;
        xs[j][k] = xin[(b*SS + sb + j)*Din + k];
    }
    __syncthreads();
    float bi = bias[g];
    float acc[16];
    #pragma unroll
    for (int j = 0; j < 16; j++) acc[j] = bi;
    for (int i = 0; i < Din; i += 2) {
        float w0 = wT[(i    )*GG + g];
        float w1 = wT[(i + 1)*GG + g];
        #pragma unroll
        for (int j = 0; j < 16; j++)
            acc[j] += xs[j][i]*w0 + xs[j][i+1]*w1;
    }
    #pragma unroll
    for (int j = 0; j < 16; j++) pre[((sb + j)*BB + b)*GG + g] = acc[j];
}

// ---------------- LSTM scan: 8-CTA cluster per dir, one-hop bulk exchange ----------------
__global__ void __launch_bounds__(128, 1) __cluster_dims__(8, 1, 1)
k_scan8(const float* __restrict__ preFp, const float* __restrict__ preBp,
        const float* __restrict__ whFp, const float* __restrict__ whBp,
        float* __restrict__ hout) {
    int dir  = blockIdx.x >> 3;
    int r    = blockIdx.x & 7;
    int q    = r & 3;
    int bt   = r >> 2;
    const float* pre = dir ? preBp : preFp;
    const u64*   W   = (const u64*)(dir ? whBp : whFp);   // [512 rows][64 u64]
    int t  = threadIdx.x;          // 128
    int g  = t >> 5;
    int hl = t & 31;
    int row = g*HH + q*32 + hl;

    __shared__ __align__(16) float hsf[2][HH];     // [buf][k] for this batch
    __shared__ float gs[4][32];                    // [gate][local unit]
    __shared__ __align__(8) u64 mbar[2];           // one barrier per buffer

    u64 w[64];
    #pragma unroll
    for (int c = 0; c < 4; c++) {
        int qb = 16 * ((q + c) & 3);
        #pragma unroll
        for (int j = 0; j < 16; j++) w[c*16 + j] = W[row*64 + qb + j];
    }

    for (int i = t; i < 2*HH; i += 128) ((float*)hsf)[i] = 0.f;
    unsigned mb = smem_u32(&mbar[0]);
    if (t == 0) { mbar_init(mb, 1); mbar_init(mb + 8, 1); }
    __syncthreads();
    if (t == 0) { mbar_expect(mb, 384); mbar_expect(mb + 8, 384); }
    asm volatile("barrier.cluster.arrive.aligned;" ::: "memory");
    asm volatile("barrier.cluster.wait.aligned;"   ::: "memory");

    unsigned lbase = smem_u32(&hsf[0][0]);
    unsigned rbp[3], rmb[3];
    #pragma unroll
    for (int pi = 0; pi < 3; pi++) {
        int pr = (bt << 2) | ((q + 1 + pi) & 3);   // same-batch peer
        asm("mapa.shared::cluster.u32 %0, %1, %2;" : "=r"(rmb[pi]) : "r"(mb),    "r"(pr));
        asm("mapa.shared::cluster.u32 %0, %1, %2;" : "=r"(rbp[pi]) : "r"(lbase), "r"(pr));
    }

    int eh = t & 31;               // epilogue lane (t < 32)
    float cst = 0.f;
    int s0 = dir ? (SS - 1) : 0;
    float pcur = __ldg(&pre[(s0*BB + bt)*GG + row]);
    unsigned ph0 = 0, ph1 = 0;

    for (int s_ = 0; s_ < SS; s_++) {
        int s  = dir ? (SS - 1 - s_) : s_;
        int sn = dir ? (s - 1 < 0 ? 0 : s - 1) : (s + 1 > SS - 1 ? SS - 1 : s + 1);
        float pnext = __ldg(&pre[(sn*BB + bt)*GG + row]);
        int rb = (s_ + 1) & 1;
        int wb = s_ & 1;
        const u64* h2 = (const u64*)hsf[rb];
        u64 a0 = 0ull, a1 = 0ull, a2 = 0ull, a3 = 0ull;
        {   // local quarter — ordered by __syncthreads
            const u64* hq = h2 + 16*q;
            #pragma unroll
            for (int j = 0; j < 16; j += 2) {
                ulonglong2 x = *(const ulonglong2*)(hq + j);
                fma2(a0, w[j], x.x);  fma2(a1, w[j + 1], x.y);
            }
        }
        if (s_ > 0) {                              // wait peers' h(s_-1) in buffer rb
            unsigned bmb = mb + 8u*(unsigned)rb;
            mbar_wait_par(bmb, rb ? ph1 : ph0);
            if (t == 0) mbar_expect(bmb, 384);     // re-arm for next use (s_+2)
            if (rb) ph1 ^= 1; else ph0 ^= 1;
        }
        #pragma unroll
        for (int c = 1; c < 4; c++) {
            const u64* hq = h2 + 16*((q + c) & 3);
            #pragma unroll
            for (int j = 0; j < 16; j += 4) {
                ulonglong2 x0 = *(const ulonglong2*)(hq + j);
                ulonglong2 x1 = *(const ulonglong2*)(hq + j + 2);
                fma2(a0, w[c*16 + j],     x0.x);  fma2(a1, w[c*16 + j + 1], x0.y);
                fma2(a2, w[c*16 + j + 2], x1.x);  fma2(a3, w[c*16 + j + 3], x1.y);
            }
        }
        float2 fa = u2f(a0), fb = u2f(a1), fc = u2f(a2), fd = u2f(a3);
        gs[g][hl] = ((fa.x + fa.y) + (fb.x + fb.y)) + ((fc.x + fc.y) + (fd.x + fd.y)) + pcur;
        pcur = pnext;
        __syncthreads();                           // gates ready; reads of rb done
        if (t < 32) {
            float ig = 0.5f*tanha(0.5f*gs[0][eh]) + 0.5f;
            float fg = 0.5f*tanha(0.5f*gs[1][eh]) + 0.5f;
            float gg = tanha(gs[2][eh]);
            float og = 0.5f*tanha(0.5f*gs[3][eh]) + 0.5f;
            cst = fg*cst + ig*gg;
            float hv = og * tanha(cst);
            hsf[wb][q*32 + eh] = hv;
            __syncwarp();
            if (eh < 3) {                          // ship quarter to 3 peers, one hop each
                fence_async();
                unsigned off = (unsigned)((wb*HH + q*32) * 4);
                bulk_copy_peer(rbp[eh] + off, lbase + off, rmb[eh] + 8u*(unsigned)wb);
            }
            hout[(bt*SS + s)*FF + dir*HH + q*32 + eh] = hv;
        }
        __syncthreads();                           // local quarter of wb visible to CTA
    }
    asm volatile("barrier.cluster.arrive.aligned;" ::: "memory");
    asm volatile("barrier.cluster.wait.aligned;"   ::: "memory");
}

// ---------------- cls / bin MLPs, 4 timesteps per block ----------------
__global__ void k_clsbin4(const float* __restrict__ rnn,
    const float* ac0, const float* __restrict__ wc1, const float* __restrict__ bc1,
    const float* ac1, const float* __restrict__ wc2, const float* __restrict__ bc2,
    const float* ab0, const float* __restrict__ wb1, const float* __restrict__ bb1,
    const float* ab1, const float* __restrict__ wb2, const float* __restrict__ bb2,
    float* __restrict__ out) {
    int sb = blockIdx.x * 4, b = blockIdx.y, t = threadIdx.x; // blockDim = 192
    __shared__ float xc[4][FF], xb[4][FF], hc[4][80], hb[4][80];
    float a0c = *ac0, a0b = *ab0;
    for (int k = t; k < 4*FF; k += 192) {
        int j = k >> 8, kk = k & 255;
        float v = rnn[(b*SS + sb + j)*FF + kk];
        xc[j][kk] = v >= 0.f ? v : a0c*v;
        xb[j][kk] = v >= 0.f ? v : a0b*v;
    }
    __syncthreads();
    if (t < 80) {
        float acc[4];
        float bv = bc1[t];
        #pragma unroll
        for (int j = 0; j < 4; j++) acc[j] = bv;
        const float* w = wc1 + t*FF;
        #pragma unroll 4
        for (int k = 0; k < FF; k++) {
            float wv = w[k];
            #pragma unroll
            for (int j = 0; j < 4; j++) acc[j] += xc[j][k]*wv;
        }
        float a1 = *ac1;
        #pragma unroll
        for (int j = 0; j < 4; j++) hc[j][t] = acc[j] >= 0.f ? acc[j] : a1*acc[j];
    } else if (t < 160) {
        int g = t - 80;
        float acc[4];
        float bv = bb1[g];
        #pragma unroll
        for (int j = 0; j < 4; j++) acc[j] = bv;
        const float* w = wb1 + g*FF;
        #pragma unroll 4
        for (int k = 0; k < FF; k++) {
            float wv = w[k];
            #pragma unroll
            for (int j = 0; j < 4; j++) acc[j] += xb[j][k]*wv;
        }
        float a1 = *ab1;
        #pragma unroll
        for (int j = 0; j < 4; j++) hb[j][g] = acc[j] >= 0.f ? acc[j] : a1*acc[j];
    }
    __syncthreads();
    if (t < NCC) {
        float acc[4];
        float bv = bc2[t];
        #pragma unroll
        for (int j = 0; j < 4; j++) acc[j] = bv;
        const float* w = wc2 + t*80;
        #pragma unroll 4
        for (int k = 0; k < 80; k++) {
            float wv = w[k];
            #pragma unroll
            for (int j = 0; j < 4; j++) acc[j] += hc[j][k]*wv;
        }
        #pragma unroll
        for (int j = 0; j < 4; j++) out[(b*SS + sb + j)*NCC + t] = acc[j];
    } else if (t < NCC + 2) {
        int o = t - NCC;
        float acc[4];
        float bv = bb2[o];
        #pragma unroll
        for (int j = 0; j < 4; j++) acc[j] = bv;
        const float* w = wb2 + o*80;
        #pragma unroll 4
        for (int k = 0; k < 80; k++) {
            float wv = w[k];
            #pragma unroll
            for (int j = 0; j < 4; j++) acc[j] += hb[j][k]*wv;
        }
        #pragma unroll
        for (int j = 0; j < 4; j++) out[20480 + (b*SS + sb + j)*2 + o] = acc[j];
    }
}

// ---------------- cumsum (software-pipelined loads) ----------------
__global__ void k_cum(const float* __restrict__ rnn) {
    int b = blockIdx.x, k = threadIdx.x;
    float run = 0.f;
    float v[8], vn[8];
    #pragma unroll
    for (int j = 0; j < 8; j++) v[j] = rnn[(b*SS + j)*FF + k];
    for (int t0 = 0; t0 < SS; t0 += 8) {
        if (t0 + 8 < SS) {
            #pragma unroll
            for (int j = 0; j < 8; j++) vn[j] = rnn[(b*SS + t0 + 8 + j)*FF + k];
        }
        #pragma unroll
        for (int j = 0; j < 8; j++) { run += v[j]; g_cum[(b*SS + t0 + j)*FF + k] = run; }
        #pragma unroll
        for (int j = 0; j < 8; j++) v[j] = vn[j];
    }
}

// ---------------- Pd / Pe, 2 timesteps per block ----------------
__global__ void k_pdpe2(const float* __restrict__ rnn, const float* as0, const float* __restrict__ bs1) {
    int sp = blockIdx.x * 2, b = blockIdx.y, t = threadIdx.x; // blockDim = 128
    __shared__ __align__(16) float xr[2][FF];
    float a0 = *as0;
    #pragma unroll
    for (int ss = 0; ss < 2; ss++) {
        float v0 = rnn[(b*SS + sp + ss)*FF + 2*t];
        float v1 = rnn[(b*SS + sp + ss)*FF + 2*t + 1];
        xr[ss][2*t]     = v0 >= 0.f ? v0 : a0*v0;
        xr[ss][2*t + 1] = v1 >= 0.f ? v1 : a0*v1;
    }
    __syncthreads();
    if (t < HID) {
        u64 d0 = 0ull, e0 = 0ull, d1 = 0ull, e1 = 0ull;
        const u64* xp0 = (const u64*)xr[0];
        const u64* xp1 = (const u64*)xr[1];
        #pragma unroll 4
        for (int k2 = 0; k2 < 128; k2++) {
            u64 wd = g_wsP[1][k2*128 + t];
            u64 we = g_wsP[2][k2*128 + t];
            u64 x0 = xp0[k2], x1 = xp1[k2];
            fma2(d0, wd, x0);  fma2(e0, we, x0);
            fma2(d1, wd, x1);  fma2(e1, we, x1);
        }
        float bsv = bs1[t];
        float2 f;
        f = u2f(d0); g_Pd[(b*SS + sp    )*HID + t] = f.x + f.y;
        f = u2f(e0); g_Pe[(b*SS + sp    )*HID + t] = f.x + f.y + bsv;
        f = u2f(d1); g_Pd[(b*SS + sp + 1)*HID + t] = f.x + f.y;
        f = u2f(e1); g_Pe[(b*SS + sp + 1)*HID + t] = f.x + f.y + bsv;
    }
}

// ---------------- banded score MLP, register-blocked 16 windows, vectorized ----------------
__global__ void k_scores(const float* as0, const float* as1,
                         const float* __restrict__ ws2, const float* bs2) {
    int i = blockIdx.x, b = blockIdx.y, t = threadIdx.x; // blockDim = 128
    if (i == 0) return;
    __shared__ __align__(16) float cdf[16][FF];
    __shared__ float sv[16][104];
    const ulonglong2 (*cd2)[64] = (const ulonglong2 (*)[64])cdf;
    float a0 = *as0, a1 = *as1, b2 = *bs2;
    u64 civ = ((const u64*)(g_cum + (b*SS + i)*FF))[t];
    float2 ci = u2f(civ);
    float pei = (t < HID) ? g_Pe[(b*SS + i)*HID + t] : 0.f;
    float w2  = (t < HID) ? ws2[t] : 0.f;
    int wid = t >> 5, lane = t & 31;

    for (int gq = 0; gq < 4; gq++) {
        #pragma unroll 4
        for (int p = 0; p < 16; p++) {
            int j = i - WW + gq*16 + p;
            float c0 = 0.f, c1 = 0.f;
            if (j >= 0) {
                float2 cj = u2f(((const u64*)(g_cum + (b*SS + j)*FF))[t]);
                c0 = ci.x - cj.x;  c1 = ci.y - cj.y;
                c0 = c0 >= 0.f ? c0 : a0*c0;
                c1 = c1 >= 0.f ? c1 : a0*c1;
            }
            ((u64*)cdf[p])[t] = f2u(c0, c1);
        }
        __syncthreads();
        if (t < HID) {
            u64 acc[16];
            #pragma unroll
            for (int p = 0; p < 16; p++) acc[p] = 0ull;
            const ulonglong2* wr = (const ulonglong2*)(g_wsPc + (size_t)t*128);
            #pragma unroll 2
            for (int k4 = 0; k4 < 64; k4++) {
                ulonglong2 wv = __ldg(&wr[k4]);
                #pragma unroll
                for (int p = 0; p < 16; p++) {
                    ulonglong2 x = cd2[p][k4];
                    fma2(acc[p], wv.x, x.x);
                    fma2(acc[p], wv.y, x.y);
                }
            }
            #pragma unroll
            for (int p = 0; p < 16; p++) {
                int j = i - WW + gq*16 + p;
                float2 f = u2f(acc[p]);
                float pd = (j >= 0) ? g_Pd[(b*SS + j)*HID + t] : 0.f;
                float hid = f.x + f.y + pd + pei;
                float ph  = hid >= 0.f ? hid : a1*hid;
                sv[p][t] = ph * w2;
            }
        }
        __syncthreads();
        #pragma unroll
        for (int qq = 0; qq < 4; qq++) {
            int p = wid + qq*4;
            float v = sv[p][lane] + sv[p][lane + 32] + sv[p][lane + 64]
                    + (lane < 4 ? sv[p][lane + 96] : 0.f);
            for (int off = 16; off; off >>= 1) v += __shfl_down_sync(0xffffffffu, v, off);
            if (lane == 0) {
                int w = gq*16 + p;
                int j = i - WW + w;
                g_sband[(b*SS + i)*WW + w] = (j >= 0) ? v + b2 : -1000000000.0f;
            }
        }
        __syncthreads();
    }
}

// ---------------- DP + backtrack (sband preloaded to smem, redux argmax) ----------------
__global__ void k_dp(const int* __restrict__ lengths, float* __restrict__ out) {
    extern __shared__ __align__(16) float sbf[];   // 2*256*64 floats = 128 KB
    __shared__ float best[BB][SS];
    __shared__ int   bp[BB][SS];
    int t = threadIdx.x;          // blockDim = 256
    {
        float4* dst = (float4*)sbf;
        const float4* src = (const float4*)g_sband;
        #pragma unroll 4
        for (int idx = t; idx < BB*SS*WW/4; idx += 256) dst[idx] = __ldg(src + idx);
    }
    for (int idx = t; idx < BB*SS; idx += 256) { out[21504 + idx] = 0.f; best[idx >> 8][idx & 255] = 0.f; }
    if (t < BB) bp[t][0] = 0;
    __syncthreads();
    if (t < 64) {
        int b = t >> 5, lane = t & 31;
        for (int i = 1; i < SS; i++) {
            int w1 = lane, w2 = lane + 32;
            int j1 = i - WW + w1, j2 = i - WW + w2;
            const float* sr = sbf + (b*SS + i)*WW;
            float c1 = (j1 >= 0) ? best[b][j1] + sr[w1] : -1000000000.0f;
            float c2 = (j2 >= 0) ? best[b][j2] + sr[w2] : -1000000000.0f;
            float v; int jj;
            if (c2 > c1) { v = c2; jj = j2; } else { v = c1; jj = j1; }   // tie -> smaller j
            unsigned key = orderable(v), kmax;
            asm("redux.sync.max.u32 %0, %1, 0xffffffff;" : "=r"(kmax) : "r"(key));
            unsigned jc = (key == kmax) ? (unsigned)jj : 0xFFFFFFFFu;
            unsigned jmin;
            asm("redux.sync.min.u32 %0, %1, 0xffffffff;" : "=r"(jmin) : "r"(jc));
            if (lane == 0) { best[b][i] = unorder(kmax); bp[b][i] = (int)jmin; }
            __syncwarp();
        }
    }
    __syncthreads();
    if (t < BB) {
        int cur = lengths[t] - 1;
        if (cur < 0) cur = 0;
        float acc = 0.f;
        while (true) {
            out[21504 + t*SS + cur] = 1.f;
            if (cur == 0) break;
            int prev = bp[t][cur];
            acc += sbf[(t*SS + cur)*WW + (prev - (cur - WW))];
            cur = prev;
        }
        out[22016 + t] = acc;
    }
}

// ---------------- launch ----------------
extern "C" void kernel_launch(void* const* d_in, const int* in_sizes, int n_in,
                              void* d_out, int out_size) {
    (void)in_sizes; (void)n_in; (void)out_size;
    const float* x        = (const float*)d_in[0];
    const int*   lengths  = (const int*)  d_in[1];
    const float* wih[4]   = {(const float*)d_in[2], (const float*)d_in[5],
                             (const float*)d_in[8], (const float*)d_in[11]};
    const float* whh[4]   = {(const float*)d_in[3], (const float*)d_in[6],
                             (const float*)d_in[9], (const float*)d_in[12]};
    const float* bl[4]    = {(const float*)d_in[4], (const float*)d_in[7],
                             (const float*)d_in[10], (const float*)d_in[13]};
    const float* a_s0 = (const float*)d_in[14];
    const float* w_s1 = (const float*)d_in[15];
    const float* b_s1 = (const float*)d_in[16];
    const float* a_s1 = (const float*)d_in[17];
    const float* w_s2 = (const float*)d_in[18];
    const float* b_s2 = (const float*)d_in[19];
    const float* a_c0 = (const float*)d_in[20];
    const float* w_c1 = (const float*)d_in[21];
    const float* b_c1 = (const float*)d_in[22];
    const float* a_c1 = (const float*)d_in[23];
    const float* w_c2 = (const float*)d_in[24];
    const float* b_c2 = (const float*)d_in[25];
    const float* a_b0 = (const float*)d_in[26];
    const float* w_b1 = (const float*)d_in[27];
    const float* b_b1 = (const float*)d_in[28];
    const float* a_b1 = (const float*)d_in[29];
    const float* w_b2 = (const float*)d_in[30];
    const float* b_b2 = (const float*)d_in[31];
    float* out = (float*)d_out;

    float *wihT, *preF, *preB, *h0, *rnn;
    cudaGetSymbolAddress((void**)&wihT, g_wihT);
    cudaGetSymbolAddress((void**)&preF, g_preF);
    cudaGetSymbolAddress((void**)&preB, g_preB);
    cudaGetSymbolAddress((void**)&h0,   g_h0);
    cudaGetSymbolAddress((void**)&rnn,  g_rnn);

    static int dp_attr_set = 0;
    if (!dp_attr_set) {
        cudaFuncSetAttribute(k_dp, cudaFuncAttributeMaxDynamicSharedMemorySize, BB*SS*WW*4);
        dp_attr_set = 1;
    }

    k_prep<<<dim3(FF, 5), GG>>>(wih[0], wih[1], wih[2], wih[3], w_s1, wihT);

    dim3 gpre16(SS/16, BB, 2);
    // layer 0
    k_pre16m<<<gpre16, GG>>>(x, wihT, bl[0], bl[1], preF, preB, INP);
    k_scan8<<<16, 128>>>(preF, preB, whh[0], whh[1], h0);
    // layer 1
    k_pre16m<<<gpre16, GG>>>(h0, wihT + 2*FF*GG, bl[2], bl[3], preF, preB, FF);
    k_scan8<<<16, 128>>>(preF, preB, whh[2], whh[3], rnn);

    k_clsbin4<<<dim3(SS/4, BB), 192>>>(rnn, a_c0, w_c1, b_c1, a_c1, w_c2, b_c2,
                                            a_b0, w_b1, b_b1, a_b1, w_b2, b_b2, out);
    k_cum<<<BB, FF>>>(rnn);
    k_pdpe2<<<dim3(SS/2, BB), 128>>>(rnn, a_s0, b_s1);
    k_scores<<<dim3(SS, BB), 128>>>(a_s0, a_s1, w_s2, b_s2);
    k_dp<<<1, 256, BB*SS*WW*4>>>(lengths, out);
}